// round 2
// baseline (speedup 1.0000x reference)
#include <cuda_runtime.h>
#include <math.h>
#include <stdint.h>

#define NPTS 16384
#define DIM  192
#define NS   16
#define NH   6
#define HD   32
#define KSP  16
#define DQ   48

// ---------------- scratch (device globals; no allocs allowed) ----------------
__device__ float g_xpw[NPTS * DIM];        // x @ prop_W[:192]
__device__ float g_prefus[NPTS * DIM];     // pre-fusion features (without vol term)
__device__ float g_xfused[NPTS * DIM];
__device__ float g_qkv[NPTS * 576];
__device__ float g_A[3L * NPTS * DIM];     // per-mat per-node A (includes pos_b1)
__device__ float g_knnxyz[NPTS * 48];
__device__ float g_m3[NPTS * 3];
__device__ float g_attnout[NPTS * DIM];
__device__ float g_distsum[NPTS];
__device__ float g_distmax[NPTS];
__device__ double g_ch[3 * DIM * 5];       // per (mat,c): SA, SA2, SAMx, SAMy, SAMz
__device__ double g_Sm3[3];
__device__ double g_SM33[6];               // xx, xy, xz, yy, yz, zz
__device__ double g_sumdist;
__device__ int    g_maxbits;
__device__ float g_S[9 * DIM];             // S[mat][k][c]
__device__ float g_bnscale[3 * DIM];
__device__ float g_bnshift[3 * DIM];
__device__ float g_volvec[DIM];
__device__ float g_kpwproj[DQ];
__device__ float g_kpconst;

__device__ __forceinline__ float warpsum(float v) {
#pragma unroll
    for (int o = 16; o > 0; o >>= 1) v += __shfl_xor_sync(0xffffffffu, v, o);
    return v;
}

// ---------------- zero accumulators (graph replay determinism) ----------------
__global__ void zero_kernel() {
    int t = blockIdx.x * blockDim.x + threadIdx.x;
    if (t < 3 * DIM * 5) g_ch[t] = 0.0;
    if (t < 3) g_Sm3[t] = 0.0;
    if (t < 6) g_SM33[t] = 0.0;
    if (t == 0) { g_sumdist = 0.0; g_maxbits = 0; }
}

// ---------------- tiny precompute: de_W2 @ kp_W ----------------
__global__ void pre_kernel(const float* __restrict__ de_W2, const float* __restrict__ de_b2,
                           const float* __restrict__ kp_W, const float* __restrict__ kp_b) {
    int t = threadIdx.x;
    if (t < DQ) {
        float s = 0.f;
        for (int c = 0; c < DIM; c++) s += de_W2[t * DIM + c] * kp_W[c];
        g_kpwproj[t] = s;
    }
    if (t == 63) {
        float s = 0.f;
        for (int c = 0; c < DIM; c++) s += de_b2[c] * kp_W[c];
        g_kpconst = s + kp_b[0];
    }
}

// ---------------- generic fp32 tiled GEMM: C = (A + addvec?) @ B (+ bias?) ----------------
// A [M,K] row-major, B [K,Ncol] row-major. M%64==0, Ncol%64==0, K%16==0.
__global__ void __launch_bounds__(256) gemm_kernel(
    const float* __restrict__ A, const float* __restrict__ B,
    const float* __restrict__ bias, const float* __restrict__ addvec,
    float* __restrict__ C, int M, int K, int Ncol)
{
    __shared__ float As[16][65];
    __shared__ float Bs[16][65];
    int t = threadIdx.x;
    int row0 = blockIdx.y * 64;
    int col0 = blockIdx.x * 64;
    int mb = (t / 16) * 4;
    int nb = (t % 16) * 4;
    int a_k = t % 16, a_m = t / 16;   // a_m: 0..15
    int b_n = t % 64, b_k = t / 64;   // b_k: 0..3
    float acc[4][4] = {};
    for (int k0 = 0; k0 < K; k0 += 16) {
#pragma unroll
        for (int p = 0; p < 4; p++) {
            int m = a_m + p * 16;
            float v = A[(long)(row0 + m) * K + k0 + a_k];
            if (addvec) v += addvec[k0 + a_k];
            As[a_k][m] = v;
        }
#pragma unroll
        for (int p = 0; p < 4; p++) {
            int kk = b_k + p * 4;
            Bs[kk][b_n] = B[(long)(k0 + kk) * Ncol + col0 + b_n];
        }
        __syncthreads();
#pragma unroll
        for (int kk = 0; kk < 16; kk++) {
            float a[4], b[4];
#pragma unroll
            for (int i = 0; i < 4; i++) a[i] = As[kk][mb + i];
#pragma unroll
            for (int j = 0; j < 4; j++) b[j] = Bs[kk][nb + j];
#pragma unroll
            for (int i = 0; i < 4; i++)
#pragma unroll
                for (int j = 0; j < 4; j++)
                    acc[i][j] += a[i] * b[j];
        }
        __syncthreads();
    }
#pragma unroll
    for (int i = 0; i < 4; i++)
#pragma unroll
        for (int j = 0; j < 4; j++) {
            float v = acc[i][j];
            if (bias) v += bias[col0 + nb + j];
            C[(long)(row0 + mb + i) * Ncol + col0 + nb + j] = v;
        }
}

// ---------------- per-node stage 1 ----------------
__global__ void __launch_bounds__(192) node1_kernel(
    const float* __restrict__ p, const float* __restrict__ x, const int* __restrict__ knn,
    const float* __restrict__ prop_W, const float* __restrict__ prop_b,
    const float* __restrict__ gA_W, const float* __restrict__ gA_b,
    const float* __restrict__ gB_W, const float* __restrict__ gB_b,
    const float* __restrict__ pos_W1, const float* __restrict__ pos_b1,
    const float* __restrict__ kn, const float* __restrict__ de_W1,
    const float* __restrict__ de_b1, const float* __restrict__ de_W2,
    const float* __restrict__ de_b2)
{
    int n = blockIdx.x;
    int c = threadIdx.x;
    __shared__ float s_p[3];
    __shared__ int   s_idx[NS];
    __shared__ float s_xyz[NS * 3];
    __shared__ float s_pr[NS * 3];
    __shared__ float s_dist[NS];
    __shared__ float s_rep[9];
    __shared__ float s_maxd;
    __shared__ float s_kd[KSP];
    __shared__ float s_g[KSP * DQ];
    __shared__ float s_sc[KSP];
    __shared__ float s_w[DQ];

    if (c < 3) s_p[c] = p[n * 3 + c];
    if (c < NS) s_idx[c] = knn[n * NS + c];
    __syncthreads();

    if (c < NS) {
        int id = s_idx[c];
        float ax = p[id * 3 + 0], ay = p[id * 3 + 1], az = p[id * 3 + 2];
        s_xyz[c * 3 + 0] = ax; s_xyz[c * 3 + 1] = ay; s_xyz[c * 3 + 2] = az;
        float rx = ax - s_p[0], ry = ay - s_p[1], rz = az - s_p[2];
        s_pr[c * 3 + 0] = rx; s_pr[c * 3 + 1] = ry; s_pr[c * 3 + 2] = rz;
        s_dist[c] = sqrtf(rx * rx + ry * ry + rz * rz + 1e-12f);
    }
    if (c >= 32 && c < 32 + KSP) {
        int s = c - 32;
        float dx = s_p[0] - kn[s * 3 + 0];
        float dy = s_p[1] - kn[s * 3 + 1];
        float dz = s_p[2] - kn[s * 3 + 2];
        s_kd[s] = sqrtf(dx * dx + dy * dy + dz * dz + 1e-12f);
    }
    __syncthreads();

    if (c == 0) {
        float mx = 0, my = 0, mz = 0, qx = 0, qy = 0, qz = 0, md = 0, sd = 0;
        for (int j = 0; j < NS; j++) {
            mx += s_pr[j * 3]; my += s_pr[j * 3 + 1]; mz += s_pr[j * 3 + 2];
            qx += s_xyz[j * 3]; qy += s_xyz[j * 3 + 1]; qz += s_xyz[j * 3 + 2];
            md = fmaxf(md, s_dist[j]); sd += s_dist[j];
        }
        const float inv = 1.f / NS;
        s_rep[0] = mx * inv; s_rep[1] = my * inv; s_rep[2] = mz * inv;
        s_rep[3] = qx * inv; s_rep[4] = qy * inv; s_rep[5] = qz * inv;
        s_rep[6] = s_p[0]; s_rep[7] = s_p[1]; s_rep[8] = s_p[2];
        s_maxd = md;
        g_distsum[n] = sd; g_distmax[n] = md;
        g_m3[n * 3 + 0] = qx; g_m3[n * 3 + 1] = qy; g_m3[n * 3 + 2] = qz;
    }
    if (c < NS * 3) g_knnxyz[n * 48 + c] = s_xyz[c];
    for (int idx = c; idx < KSP * DQ; idx += 192) {
        int s = idx / DQ, k = idx % DQ;
        s_g[idx] = fmaxf(s_kd[s] * de_W1[k] + de_b1[k], 0.f);
    }
    __syncthreads();

    if (c < KSP) {
        float l = g_kpconst;
        for (int k = 0; k < DQ; k++) l += s_g[c * DQ + k] * g_kpwproj[k];
        s_sc[c] = l;
    }
    __syncthreads();
    if (c == 0) {
        float mx = -1e30f;
        for (int s = 0; s < KSP; s++) mx = fmaxf(mx, s_sc[s]);
        float se = 0.f;
        for (int s = 0; s < KSP; s++) { float e = expf(s_sc[s] - mx); s_sc[s] = e; se += e; }
        float inv = 1.f / se;
        for (int s = 0; s < KSP; s++) s_sc[s] *= inv;
    }
    __syncthreads();
    if (c < DQ) {
        float w = 0.f;
        for (int s = 0; s < KSP; s++) w += s_sc[s] * s_g[s * DQ + c];
        s_w[c] = w;
    }
    __syncthreads();

    // ---- per-channel main ----
    float dist_feat = de_b2[c];
#pragma unroll
    for (int k = 0; k < DQ; k++) dist_feat += s_w[k] * de_W2[k * DIM + c];

    float geo = gA_b[c] + gB_b[c] + s_maxd * gB_W[c];
#pragma unroll
    for (int i = 0; i < 9; i++) geo += s_rep[i] * gA_W[i * DIM + c];

    float w0 = prop_W[192 * DIM + c], w1 = prop_W[193 * DIM + c], w2 = prop_W[194 * DIM + c];
    float pb = prop_b[c];
    float msg = 0.f;
#pragma unroll
    for (int s = 0; s < NS; s++) {
        float v = g_xpw[(long)s_idx[s] * DIM + c]
                + s_pr[s * 3] * w0 + s_pr[s * 3 + 1] * w1 + s_pr[s * 3 + 2] * w2 + pb;
        msg += fmaxf(v, 0.f);
    }
    msg *= (1.f / NS);
    g_prefus[(long)n * DIM + c] = x[(long)n * DIM + c] + msg + geo + dist_feat;

#pragma unroll
    for (int m = 0; m < 3; m++) {
        float a = pos_b1[m * DIM + c];
        const float* W1 = pos_W1 + (long)m * 48 * DIM;
#pragma unroll
        for (int j = 0; j < NS; j++) {
            a += s_xyz[j * 3 + 0] * W1[(3 * j + 0) * DIM + c]
               + s_xyz[j * 3 + 1] * W1[(3 * j + 1) * DIM + c]
               + s_xyz[j * 3 + 2] * W1[(3 * j + 2) * DIM + c];
        }
        g_A[((long)m * NPTS + n) * DIM + c] = a;
    }
}

// ---------------- global reductions: vol scalar + Sm3/SM33 ----------------
__global__ void __launch_bounds__(256) reduce_kernel() {
    int tid = blockIdx.x * blockDim.x + threadIdx.x;
    int stride = gridDim.x * blockDim.x;
    double lsum = 0, l0 = 0, l1 = 0, l2 = 0;
    double m0 = 0, m1 = 0, m2 = 0, m3v = 0, m4 = 0, m5 = 0;
    float lmax = 0.f;
    for (int n = tid; n < NPTS; n += stride) {
        lsum += (double)g_distsum[n];
        lmax = fmaxf(lmax, g_distmax[n]);
        l0 += (double)g_m3[n * 3 + 0];
        l1 += (double)g_m3[n * 3 + 1];
        l2 += (double)g_m3[n * 3 + 2];
        for (int i = 0; i < NS; i++) {
            float xx = g_knnxyz[n * 48 + i * 3 + 0];
            float yy = g_knnxyz[n * 48 + i * 3 + 1];
            float zz = g_knnxyz[n * 48 + i * 3 + 2];
            m0 += (double)xx * xx; m1 += (double)xx * yy; m2 += (double)xx * zz;
            m3v += (double)yy * yy; m4 += (double)yy * zz; m5 += (double)zz * zz;
        }
    }
    __shared__ double sd[256];
    double vals[10] = {lsum, l0, l1, l2, m0, m1, m2, m3v, m4, m5};
    double* outs[10] = {&g_sumdist, &g_Sm3[0], &g_Sm3[1], &g_Sm3[2],
                        &g_SM33[0], &g_SM33[1], &g_SM33[2], &g_SM33[3], &g_SM33[4], &g_SM33[5]};
    for (int q = 0; q < 10; q++) {
        sd[threadIdx.x] = vals[q];
        __syncthreads();
        for (int s = 128; s > 0; s >>= 1) {
            if (threadIdx.x < s) sd[threadIdx.x] += sd[threadIdx.x + s];
            __syncthreads();
        }
        if (threadIdx.x == 0) atomicAdd(outs[q], sd[0]);
        __syncthreads();
    }
    sd[threadIdx.x] = (double)lmax;
    __syncthreads();
    for (int s = 128; s > 0; s >>= 1) {
        if (threadIdx.x < s) sd[threadIdx.x] = fmax(sd[threadIdx.x], sd[threadIdx.x + s]);
        __syncthreads();
    }
    if (threadIdx.x == 0) atomicMax(&g_maxbits, __float_as_int((float)sd[0]));
}

// ---------------- BN per-channel statistics ----------------
#define BNCHUNK 512
__global__ void __launch_bounds__(192) bnstats_kernel() {
    int m = blockIdx.y;
    int n0 = blockIdx.x * BNCHUNK;
    int c = threadIdx.x;
    double sa = 0, sa2 = 0, sx = 0, sy = 0, sz = 0;
    const float* Abase = g_A + (long)m * NPTS * DIM;
    for (int n = n0; n < n0 + BNCHUNK; n++) {
        float a = Abase[(long)n * DIM + c];
        float mx = g_m3[n * 3 + 0], my = g_m3[n * 3 + 1], mz = g_m3[n * 3 + 2];
        sa += (double)a;
        sa2 += (double)a * a;
        sx += (double)a * mx; sy += (double)a * my; sz += (double)a * mz;
    }
    double* d = g_ch + ((long)m * DIM + c) * 5;
    atomicAdd(d + 0, sa); atomicAdd(d + 1, sa2);
    atomicAdd(d + 2, sx); atomicAdd(d + 3, sy); atomicAdd(d + 4, sz);
}

// ---------------- finalize: S, BN scale/shift, vol vector ----------------
__global__ void __launch_bounds__(192) finalize_kernel(
    const float* __restrict__ pos_W1, const float* __restrict__ pos_gamma,
    const float* __restrict__ pos_beta, const float* __restrict__ gC_W,
    const float* __restrict__ gC_b)
{
    int c = threadIdx.x;
    float Sv[3][3];
#pragma unroll
    for (int m = 0; m < 3; m++)
#pragma unroll
        for (int k = 0; k < 3; k++) {
            float s = 0.f;
            for (int j = 0; j < NS; j++) s += pos_W1[(long)m * 48 * DIM + (3 * j + k) * DIM + c];
            Sv[m][k] = s;
            g_S[(m * 3 + k) * DIM + c] = s;
        }
    const double T = (double)NPTS * NS;
    double Q0 = g_SM33[0], Q1 = g_SM33[1], Q2 = g_SM33[2], Q3 = g_SM33[3], Q4 = g_SM33[4], Q5 = g_SM33[5];
    double P0 = g_Sm3[0], P1 = g_Sm3[1], P2 = g_Sm3[2];
#pragma unroll
    for (int m = 0; m < 3; m++) {
        const double* d = g_ch + ((long)m * DIM + c) * 5;
        double SA = d[0], SA2 = d[1], SMx = d[2], SMy = d[3], SMz = d[4];
        double Sx = Sv[m][0], Sy = Sv[m][1], Sz = Sv[m][2];
        double mean = (16.0 * SA - (Sx * P0 + Sy * P1 + Sz * P2)) / T;
        double sq = 16.0 * SA2 - 2.0 * (Sx * SMx + Sy * SMy + Sz * SMz)
                  + Sx * Sx * Q0 + Sy * Sy * Q3 + Sz * Sz * Q5
                  + 2.0 * (Sx * Sy * Q1 + Sx * Sz * Q2 + Sy * Sz * Q4);
        double var = sq / T - mean * mean;
        float sc = pos_gamma[m * DIM + c] * rsqrtf((float)(var + 1e-5));
        g_bnscale[m * DIM + c] = sc;
        g_bnshift[m * DIM + c] = pos_beta[m * DIM + c] - (float)mean * sc;
    }
    float maxd = __int_as_float(g_maxbits);
    float vol = (float)(g_sumdist / T) / (maxd + 1e-8f);
    g_volvec[c] = vol * gC_W[c] + gC_b[c];
}

// ---------------- attention (per node): pos MLP + fused biased attention ----------------
__global__ void __launch_bounds__(192) attn_kernel(
    const int* __restrict__ knn, const float* __restrict__ pos_W2,
    const float* __restrict__ pos_b2)
{
    int n = blockIdx.x;
    int c = threadIdx.x;
    int w = c >> 5, lane = c & 31;
    __shared__ int   s_idx[NS];
    __shared__ __align__(16) float s_h[NS * DIM];
    __shared__ float s_xyz[NS * 3];
    __shared__ float s_dots[NH][NS];

    if (c < NS) s_idx[c] = knn[n * NS + c];
    if (c < 48) s_xyz[c] = g_knnxyz[n * 48 + c];
    __syncthreads();

    int i0 = s_idx[0];
    float q0 = g_qkv[(long)i0 * 576 + c];
    float k0 = g_qkv[(long)i0 * 576 + 192 + c];

    // q0 . k_j
#pragma unroll
    for (int j = 0; j < NS; j++) {
        float kj = g_qkv[(long)s_idx[j] * 576 + 192 + c];
        float r = warpsum(q0 * kj);
        if (lane == 0) s_dots[w][j] = r;
    }

    float pm[NS];
    for (int m = 0; m < 3; m++) {
        __syncthreads();
        {
            float a = g_A[((long)m * NPTS + n) * DIM + c];
            float S0 = g_S[(m * 3 + 0) * DIM + c];
            float S1 = g_S[(m * 3 + 1) * DIM + c];
            float S2 = g_S[(m * 3 + 2) * DIM + c];
            float sc = g_bnscale[m * DIM + c], sh = g_bnshift[m * DIM + c];
#pragma unroll
            for (int j = 0; j < NS; j++) {
                float h = a - (s_xyz[j * 3] * S0 + s_xyz[j * 3 + 1] * S1 + s_xyz[j * 3 + 2] * S2);
                s_h[j * DIM + c] = fmaxf(h * sc + sh, 0.f);
            }
        }
        __syncthreads();
#pragma unroll
        for (int j = 0; j < NS; j++) pm[j] = 0.f;
        const float* W2 = pos_W2 + (long)m * DIM * DIM;
        for (int k = 0; k < DIM; k += 4) {
            float w0 = W2[(k + 0) * DIM + c];
            float w1 = W2[(k + 1) * DIM + c];
            float w2 = W2[(k + 2) * DIM + c];
            float w3 = W2[(k + 3) * DIM + c];
#pragma unroll
            for (int j = 0; j < NS; j++) {
                float4 h4 = *reinterpret_cast<const float4*>(&s_h[j * DIM + k]);
                pm[j] += h4.x * w0 + h4.y * w1 + h4.z * w2 + h4.w * w3;
            }
        }
        float b2 = pos_b2[m * DIM + c];
#pragma unroll
        for (int j = 0; j < NS; j++) pm[j] += b2;
        if (m == 0) {
#pragma unroll
            for (int j = 0; j < NS; j++) {
                float r = warpsum(q0 * pm[j]);
                if (lane == 0) s_dots[w][j] += r;
            }
        } else if (m == 1) {
#pragma unroll
            for (int j = 0; j < NS; j++) {
                float r = warpsum(k0 * pm[j]);
                if (lane == 0) s_dots[w][j] += r;
            }
        }
    }
    __syncthreads();

    // softmax over j (per head, computed redundantly by all lanes of the warp)
    const float scale = 0.17677669529663687f;  // 32^-0.5
    float mx = -1e30f;
#pragma unroll
    for (int j = 0; j < NS; j++) mx = fmaxf(mx, s_dots[w][j]);
    float e[NS]; float se = 0.f;
#pragma unroll
    for (int j = 0; j < NS; j++) { e[j] = expf((s_dots[w][j] - mx) * scale); se += e[j]; }
    float inv = 1.f / se;

    float o = 0.f;
#pragma unroll
    for (int j = 0; j < NS; j++) {
        float vj = g_qkv[(long)s_idx[j] * 576 + 384 + c];
        o += e[j] * (vj + pm[j]);    // pm holds pv after the m==2 pass
    }
    g_attnout[(long)n * DIM + c] = o * inv;
}

// ---------------- host launcher ----------------
extern "C" void kernel_launch(void* const* d_in, const int* in_sizes, int n_in,
                              void* d_out, int out_size)
{
    const float* p      = (const float*)d_in[0];
    const float* x      = (const float*)d_in[1];
    const int*   knn    = (const int*)d_in[2];
    const float* W_qkv  = (const float*)d_in[3];
    const float* W_proj = (const float*)d_in[4];
    const float* b_proj = (const float*)d_in[5];
    const float* prop_W = (const float*)d_in[6];
    const float* prop_b = (const float*)d_in[7];
    const float* gA_W   = (const float*)d_in[8];
    const float* gA_b   = (const float*)d_in[9];
    const float* gB_W   = (const float*)d_in[10];
    const float* gB_b   = (const float*)d_in[11];
    const float* gC_W   = (const float*)d_in[12];
    const float* gC_b   = (const float*)d_in[13];
    const float* pos_W1 = (const float*)d_in[14];
    const float* pos_b1 = (const float*)d_in[15];
    const float* pos_gamma = (const float*)d_in[16];
    const float* pos_beta  = (const float*)d_in[17];
    const float* pos_W2 = (const float*)d_in[18];
    const float* pos_b2 = (const float*)d_in[19];
    const float* kn     = (const float*)d_in[20];
    const float* de_W1  = (const float*)d_in[21];
    const float* de_b1  = (const float*)d_in[22];
    const float* de_W2  = (const float*)d_in[23];
    const float* de_b2  = (const float*)d_in[24];
    const float* kp_W   = (const float*)d_in[25];
    const float* kp_b   = (const float*)d_in[26];
    const float* fus_W  = (const float*)d_in[27];
    const float* fus_b  = (const float*)d_in[28];
    float* out = (float*)d_out;

    float *xpw, *prefus, *xfused, *qkv, *attnout, *volvec;
    cudaGetSymbolAddress((void**)&xpw, g_xpw);
    cudaGetSymbolAddress((void**)&prefus, g_prefus);
    cudaGetSymbolAddress((void**)&xfused, g_xfused);
    cudaGetSymbolAddress((void**)&qkv, g_qkv);
    cudaGetSymbolAddress((void**)&attnout, g_attnout);
    cudaGetSymbolAddress((void**)&volvec, g_volvec);

    zero_kernel<<<12, 256>>>();
    pre_kernel<<<1, 64>>>(de_W2, de_b2, kp_W, kp_b);
    // x @ prop_W[:192]
    gemm_kernel<<<dim3(DIM / 64, NPTS / 64), 256>>>(x, prop_W, nullptr, nullptr, xpw, NPTS, DIM, DIM);
    node1_kernel<<<NPTS, 192>>>(p, x, knn, prop_W, prop_b, gA_W, gA_b, gB_W, gB_b,
                                pos_W1, pos_b1, kn, de_W1, de_b1, de_W2, de_b2);
    reduce_kernel<<<64, 256>>>();
    bnstats_kernel<<<dim3(NPTS / BNCHUNK, 3), 192>>>();
    finalize_kernel<<<1, 192>>>(pos_W1, pos_gamma, pos_beta, gC_W, gC_b);
    // x_fused = (prefus + volvec) @ fus_W + fus_b
    gemm_kernel<<<dim3(DIM / 64, NPTS / 64), 256>>>(prefus, fus_W, fus_b, volvec, xfused, NPTS, DIM, DIM);
    // qkv = x_fused @ W_qkv
    gemm_kernel<<<dim3(576 / 64, NPTS / 64), 256>>>(xfused, W_qkv, nullptr, nullptr, qkv, NPTS, DIM, 576);
    attn_kernel<<<NPTS, 192>>>(knn, pos_W2, pos_b2);
    // out = attnout @ W_proj + b_proj
    gemm_kernel<<<dim3(DIM / 64, NPTS / 64), 256>>>(attnout, W_proj, b_proj, nullptr, out, NPTS, DIM, DIM);
}

// round 4
// speedup vs baseline: 1.7796x; 1.7796x over previous
#include <cuda_runtime.h>
#include <math.h>
#include <stdint.h>

#define NPTS 16384
#define DIM  192
#define NS   16
#define NH   6
#define HD   32
#define KSP  16
#define DQ   48

// ---------------- scratch (device globals; no allocs allowed) ----------------
__device__ float g_xpw[NPTS * DIM];        // x @ prop_W[:192]
__device__ float g_prefus[NPTS * DIM];     // pre-fusion features (without vol term)
__device__ float g_xfused[NPTS * DIM];
__device__ float g_qkv[NPTS * 576];
__device__ float g_A[3L * NPTS * DIM];     // per-mat per-node A (includes pos_b1)
__device__ float g_knnxyz[NPTS * 48];
__device__ float g_m3[NPTS * 3];
__device__ float g_attnout[NPTS * DIM];
__device__ float g_distsum[NPTS];
__device__ float g_distmax[NPTS];
__device__ double g_ch[3 * DIM * 5];       // per (mat,c): SA, SA2, SAMx, SAMy, SAMz
__device__ double g_Sm3[3];
__device__ double g_SM33[6];               // xx, xy, xz, yy, yz, zz
__device__ double g_sumdist;
__device__ int    g_maxbits;
__device__ float g_S[9 * DIM];             // S[mat][k][c]
__device__ float g_bnscale[3 * DIM];
__device__ float g_bnshift[3 * DIM];
__device__ float g_volvec[DIM];
__device__ float g_kpwproj[DQ];
__device__ float g_kpconst;
__device__ uint32_t g_W2t[3 * DIM * DIM];  // pos_W2 converted to tf32 bits, [m][k][n]

__device__ __forceinline__ uint32_t f2tf32(float f) {
    uint32_t r;
    asm("cvt.rna.tf32.f32 %0, %1;" : "=r"(r) : "f"(f));
    return r;
}

// mma.sync m16n8k8 tf32 (baseline PTX, works on target sm_103)
__device__ __forceinline__ void mma_tf32(float* c, const uint32_t* a, uint32_t b0, uint32_t b1) {
    asm volatile("mma.sync.aligned.m16n8k8.row.col.f32.tf32.tf32.f32 "
        "{%0,%1,%2,%3}, {%4,%5,%6,%7}, {%8,%9}, {%0,%1,%2,%3};"
        : "+f"(c[0]), "+f"(c[1]), "+f"(c[2]), "+f"(c[3])
        : "r"(a[0]), "r"(a[1]), "r"(a[2]), "r"(a[3]), "r"(b0), "r"(b1));
}

__device__ __forceinline__ float warpsum(float v) {
#pragma unroll
    for (int o = 16; o > 0; o >>= 1) v += __shfl_xor_sync(0xffffffffu, v, o);
    return v;
}

// ---------------- zero accumulators ----------------
__global__ void zero_kernel() {
    int t = blockIdx.x * blockDim.x + threadIdx.x;
    if (t < 3 * DIM * 5) g_ch[t] = 0.0;
    if (t < 3) g_Sm3[t] = 0.0;
    if (t < 6) g_SM33[t] = 0.0;
    if (t == 0) { g_sumdist = 0.0; g_maxbits = 0; }
}

// ---------------- tiny precompute: de_W2 @ kp_W ----------------
__global__ void pre_kernel(const float* __restrict__ de_W2, const float* __restrict__ de_b2,
                           const float* __restrict__ kp_W, const float* __restrict__ kp_b) {
    int t = threadIdx.x;
    if (t < DQ) {
        float s = 0.f;
        for (int c = 0; c < DIM; c++) s += de_W2[t * DIM + c] * kp_W[c];
        g_kpwproj[t] = s;
    }
    if (t == 63) {
        float s = 0.f;
        for (int c = 0; c < DIM; c++) s += de_b2[c] * kp_W[c];
        g_kpconst = s + kp_b[0];
    }
}

// ---------------- convert pos_W2 to tf32 bits ----------------
__global__ void __launch_bounds__(256) w2t_kernel(const float* __restrict__ pos_W2) {
    int gid = blockIdx.x * 256 + threadIdx.x;
    if (gid < 3 * DIM * DIM) g_W2t[gid] = f2tf32(pos_W2[gid]);
}

// ---------------- generic fp32 tiled GEMM: C = (A + addvec?) @ B (+ bias?) ----------------
__global__ void __launch_bounds__(256) gemm_kernel(
    const float* __restrict__ A, const float* __restrict__ B,
    const float* __restrict__ bias, const float* __restrict__ addvec,
    float* __restrict__ C, int M, int K, int Ncol)
{
    __shared__ float As[16][65];
    __shared__ float Bs[16][65];
    int t = threadIdx.x;
    int row0 = blockIdx.y * 64;
    int col0 = blockIdx.x * 64;
    int mb = (t / 16) * 4;
    int nb = (t % 16) * 4;
    int a_k = t % 16, a_m = t / 16;
    int b_n = t % 64, b_k = t / 64;
    float acc[4][4] = {};
    for (int k0 = 0; k0 < K; k0 += 16) {
#pragma unroll
        for (int p = 0; p < 4; p++) {
            int m = a_m + p * 16;
            float v = A[(long)(row0 + m) * K + k0 + a_k];
            if (addvec) v += addvec[k0 + a_k];
            As[a_k][m] = v;
        }
#pragma unroll
        for (int p = 0; p < 4; p++) {
            int kk = b_k + p * 4;
            Bs[kk][b_n] = B[(long)(k0 + kk) * Ncol + col0 + b_n];
        }
        __syncthreads();
#pragma unroll
        for (int kk = 0; kk < 16; kk++) {
            float a[4], b[4];
#pragma unroll
            for (int i = 0; i < 4; i++) a[i] = As[kk][mb + i];
#pragma unroll
            for (int j = 0; j < 4; j++) b[j] = Bs[kk][nb + j];
#pragma unroll
            for (int i = 0; i < 4; i++)
#pragma unroll
                for (int j = 0; j < 4; j++)
                    acc[i][j] += a[i] * b[j];
        }
        __syncthreads();
    }
#pragma unroll
    for (int i = 0; i < 4; i++)
#pragma unroll
        for (int j = 0; j < 4; j++) {
            float v = acc[i][j];
            if (bias) v += bias[col0 + nb + j];
            C[(long)(row0 + mb + i) * Ncol + col0 + nb + j] = v;
        }
}

// ---------------- per-node stage 1 ----------------
__global__ void __launch_bounds__(192) node1_kernel(
    const float* __restrict__ p, const float* __restrict__ x, const int* __restrict__ knn,
    const float* __restrict__ prop_W, const float* __restrict__ prop_b,
    const float* __restrict__ gA_W, const float* __restrict__ gA_b,
    const float* __restrict__ gB_W, const float* __restrict__ gB_b,
    const float* __restrict__ pos_W1, const float* __restrict__ pos_b1,
    const float* __restrict__ kn, const float* __restrict__ de_W1,
    const float* __restrict__ de_b1, const float* __restrict__ de_W2,
    const float* __restrict__ de_b2)
{
    int n = blockIdx.x;
    int c = threadIdx.x;
    __shared__ float s_p[3];
    __shared__ int   s_idx[NS];
    __shared__ float s_xyz[NS * 3];
    __shared__ float s_pr[NS * 3];
    __shared__ float s_dist[NS];
    __shared__ float s_rep[9];
    __shared__ float s_maxd;
    __shared__ float s_kd[KSP];
    __shared__ float s_g[KSP * DQ];
    __shared__ float s_sc[KSP];
    __shared__ float s_w[DQ];

    if (c < 3) s_p[c] = p[n * 3 + c];
    if (c < NS) s_idx[c] = knn[n * NS + c];
    __syncthreads();

    if (c < NS) {
        int id = s_idx[c];
        float ax = p[id * 3 + 0], ay = p[id * 3 + 1], az = p[id * 3 + 2];
        s_xyz[c * 3 + 0] = ax; s_xyz[c * 3 + 1] = ay; s_xyz[c * 3 + 2] = az;
        float rx = ax - s_p[0], ry = ay - s_p[1], rz = az - s_p[2];
        s_pr[c * 3 + 0] = rx; s_pr[c * 3 + 1] = ry; s_pr[c * 3 + 2] = rz;
        s_dist[c] = sqrtf(rx * rx + ry * ry + rz * rz + 1e-12f);
    }
    if (c >= 32 && c < 32 + KSP) {
        int s = c - 32;
        float dx = s_p[0] - kn[s * 3 + 0];
        float dy = s_p[1] - kn[s * 3 + 1];
        float dz = s_p[2] - kn[s * 3 + 2];
        s_kd[s] = sqrtf(dx * dx + dy * dy + dz * dz + 1e-12f);
    }
    __syncthreads();

    if (c == 0) {
        float mx = 0, my = 0, mz = 0, qx = 0, qy = 0, qz = 0, md = 0, sd = 0;
        for (int j = 0; j < NS; j++) {
            mx += s_pr[j * 3]; my += s_pr[j * 3 + 1]; mz += s_pr[j * 3 + 2];
            qx += s_xyz[j * 3]; qy += s_xyz[j * 3 + 1]; qz += s_xyz[j * 3 + 2];
            md = fmaxf(md, s_dist[j]); sd += s_dist[j];
        }
        const float inv = 1.f / NS;
        s_rep[0] = mx * inv; s_rep[1] = my * inv; s_rep[2] = mz * inv;
        s_rep[3] = qx * inv; s_rep[4] = qy * inv; s_rep[5] = qz * inv;
        s_rep[6] = s_p[0]; s_rep[7] = s_p[1]; s_rep[8] = s_p[2];
        s_maxd = md;
        g_distsum[n] = sd; g_distmax[n] = md;
        g_m3[n * 3 + 0] = qx; g_m3[n * 3 + 1] = qy; g_m3[n * 3 + 2] = qz;
    }
    if (c < NS * 3) g_knnxyz[n * 48 + c] = s_xyz[c];
    for (int idx = c; idx < KSP * DQ; idx += 192) {
        int s = idx / DQ, k = idx % DQ;
        s_g[idx] = fmaxf(s_kd[s] * de_W1[k] + de_b1[k], 0.f);
    }
    __syncthreads();

    if (c < KSP) {
        float l = g_kpconst;
        for (int k = 0; k < DQ; k++) l += s_g[c * DQ + k] * g_kpwproj[k];
        s_sc[c] = l;
    }
    __syncthreads();
    if (c == 0) {
        float mx = -1e30f;
        for (int s = 0; s < KSP; s++) mx = fmaxf(mx, s_sc[s]);
        float se = 0.f;
        for (int s = 0; s < KSP; s++) { float e = expf(s_sc[s] - mx); s_sc[s] = e; se += e; }
        float inv = 1.f / se;
        for (int s = 0; s < KSP; s++) s_sc[s] *= inv;
    }
    __syncthreads();
    if (c < DQ) {
        float w = 0.f;
        for (int s = 0; s < KSP; s++) w += s_sc[s] * s_g[s * DQ + c];
        s_w[c] = w;
    }
    __syncthreads();

    float dist_feat = de_b2[c];
#pragma unroll
    for (int k = 0; k < DQ; k++) dist_feat += s_w[k] * de_W2[k * DIM + c];

    float geo = gA_b[c] + gB_b[c] + s_maxd * gB_W[c];
#pragma unroll
    for (int i = 0; i < 9; i++) geo += s_rep[i] * gA_W[i * DIM + c];

    float w0 = prop_W[192 * DIM + c], w1 = prop_W[193 * DIM + c], w2 = prop_W[194 * DIM + c];
    float pb = prop_b[c];
    float msg = 0.f;
#pragma unroll
    for (int s = 0; s < NS; s++) {
        float v = g_xpw[(long)s_idx[s] * DIM + c]
                + s_pr[s * 3] * w0 + s_pr[s * 3 + 1] * w1 + s_pr[s * 3 + 2] * w2 + pb;
        msg += fmaxf(v, 0.f);
    }
    msg *= (1.f / NS);
    g_prefus[(long)n * DIM + c] = x[(long)n * DIM + c] + msg + geo + dist_feat;

#pragma unroll
    for (int m = 0; m < 3; m++) {
        float a = pos_b1[m * DIM + c];
        const float* W1 = pos_W1 + (long)m * 48 * DIM;
#pragma unroll
        for (int j = 0; j < NS; j++) {
            a += s_xyz[j * 3 + 0] * W1[(3 * j + 0) * DIM + c]
               + s_xyz[j * 3 + 1] * W1[(3 * j + 1) * DIM + c]
               + s_xyz[j * 3 + 2] * W1[(3 * j + 2) * DIM + c];
        }
        g_A[((long)m * NPTS + n) * DIM + c] = a;
    }
}

// ---------------- global reductions ----------------
__global__ void __launch_bounds__(256) reduce_kernel() {
    int tid = blockIdx.x * blockDim.x + threadIdx.x;
    int stride = gridDim.x * blockDim.x;
    double lsum = 0, l0 = 0, l1 = 0, l2 = 0;
    double m0 = 0, m1 = 0, m2 = 0, m3v = 0, m4 = 0, m5 = 0;
    float lmax = 0.f;
    for (int n = tid; n < NPTS; n += stride) {
        lsum += (double)g_distsum[n];
        lmax = fmaxf(lmax, g_distmax[n]);
        l0 += (double)g_m3[n * 3 + 0];
        l1 += (double)g_m3[n * 3 + 1];
        l2 += (double)g_m3[n * 3 + 2];
        for (int i = 0; i < NS; i++) {
            float xx = g_knnxyz[n * 48 + i * 3 + 0];
            float yy = g_knnxyz[n * 48 + i * 3 + 1];
            float zz = g_knnxyz[n * 48 + i * 3 + 2];
            m0 += (double)xx * xx; m1 += (double)xx * yy; m2 += (double)xx * zz;
            m3v += (double)yy * yy; m4 += (double)yy * zz; m5 += (double)zz * zz;
        }
    }
    __shared__ double sd[256];
    double vals[10] = {lsum, l0, l1, l2, m0, m1, m2, m3v, m4, m5};
    double* outs[10] = {&g_sumdist, &g_Sm3[0], &g_Sm3[1], &g_Sm3[2],
                        &g_SM33[0], &g_SM33[1], &g_SM33[2], &g_SM33[3], &g_SM33[4], &g_SM33[5]};
    for (int q = 0; q < 10; q++) {
        sd[threadIdx.x] = vals[q];
        __syncthreads();
        for (int s = 128; s > 0; s >>= 1) {
            if (threadIdx.x < s) sd[threadIdx.x] += sd[threadIdx.x + s];
            __syncthreads();
        }
        if (threadIdx.x == 0) atomicAdd(outs[q], sd[0]);
        __syncthreads();
    }
    sd[threadIdx.x] = (double)lmax;
    __syncthreads();
    for (int s = 128; s > 0; s >>= 1) {
        if (threadIdx.x < s) sd[threadIdx.x] = fmax(sd[threadIdx.x], sd[threadIdx.x + s]);
        __syncthreads();
    }
    if (threadIdx.x == 0) atomicMax(&g_maxbits, __float_as_int((float)sd[0]));
}

// ---------------- BN per-channel statistics ----------------
#define BNCHUNK 512
__global__ void __launch_bounds__(192) bnstats_kernel() {
    int m = blockIdx.y;
    int n0 = blockIdx.x * BNCHUNK;
    int c = threadIdx.x;
    double sa = 0, sa2 = 0, sx = 0, sy = 0, sz = 0;
    const float* Abase = g_A + (long)m * NPTS * DIM;
    for (int n = n0; n < n0 + BNCHUNK; n++) {
        float a = Abase[(long)n * DIM + c];
        float mx = g_m3[n * 3 + 0], my = g_m3[n * 3 + 1], mz = g_m3[n * 3 + 2];
        sa += (double)a;
        sa2 += (double)a * a;
        sx += (double)a * mx; sy += (double)a * my; sz += (double)a * mz;
    }
    double* d = g_ch + ((long)m * DIM + c) * 5;
    atomicAdd(d + 0, sa); atomicAdd(d + 1, sa2);
    atomicAdd(d + 2, sx); atomicAdd(d + 3, sy); atomicAdd(d + 4, sz);
}

// ---------------- finalize: S, BN scale/shift, vol vector ----------------
__global__ void __launch_bounds__(192) finalize_kernel(
    const float* __restrict__ pos_W1, const float* __restrict__ pos_gamma,
    const float* __restrict__ pos_beta, const float* __restrict__ gC_W,
    const float* __restrict__ gC_b)
{
    int c = threadIdx.x;
    float Sv[3][3];
#pragma unroll
    for (int m = 0; m < 3; m++)
#pragma unroll
        for (int k = 0; k < 3; k++) {
            float s = 0.f;
            for (int j = 0; j < NS; j++) s += pos_W1[(long)m * 48 * DIM + (3 * j + k) * DIM + c];
            Sv[m][k] = s;
            g_S[(m * 3 + k) * DIM + c] = s;
        }
    const double T = (double)NPTS * NS;
    double Q0 = g_SM33[0], Q1 = g_SM33[1], Q2 = g_SM33[2], Q3 = g_SM33[3], Q4 = g_SM33[4], Q5 = g_SM33[5];
    double P0 = g_Sm3[0], P1 = g_Sm3[1], P2 = g_Sm3[2];
#pragma unroll
    for (int m = 0; m < 3; m++) {
        const double* d = g_ch + ((long)m * DIM + c) * 5;
        double SA = d[0], SA2 = d[1], SMx = d[2], SMy = d[3], SMz = d[4];
        double Sx = Sv[m][0], Sy = Sv[m][1], Sz = Sv[m][2];
        double mean = (16.0 * SA - (Sx * P0 + Sy * P1 + Sz * P2)) / T;
        double sq = 16.0 * SA2 - 2.0 * (Sx * SMx + Sy * SMy + Sz * SMz)
                  + Sx * Sx * Q0 + Sy * Sy * Q3 + Sz * Sz * Q5
                  + 2.0 * (Sx * Sy * Q1 + Sx * Sz * Q2 + Sy * Sz * Q4);
        double var = sq / T - mean * mean;
        float sc = pos_gamma[m * DIM + c] * rsqrtf((float)(var + 1e-5));
        g_bnscale[m * DIM + c] = sc;
        g_bnshift[m * DIM + c] = pos_beta[m * DIM + c] - (float)mean * sc;
    }
    float maxd = __int_as_float(g_maxbits);
    float vol = (float)(g_sumdist / T) / (maxd + 1e-8f);
    g_volvec[c] = vol * gC_W[c] + gC_b[c];
}

// ---------------- fused attention via mma.sync tf32 ----------------
// Block = 8 nodes (M=128 rows = node*16 + j), 512 threads = 16 warps.
// Warp tile: 32 rows (warp_m=wid&3) x 48 cols (warp_n=wid>>2). K in 3 panels of 64.
// SMEM byte offsets:
#define SH_OFF    0          // 128 x 68 u32 (tf32 bits of h)   = 34816 B
#define SB_OFF    34816      // 64 x 200 u32 (tf32 bits of W2)  = 51200 B
#define SQ_OFF    86016      // 8 x 192 f32 = 6144
#define SK_OFF    92160      // 8 x 192 f32 = 6144
#define SB2_OFF   98304      // 3 x 192 f32 = 2304
#define SSC_OFF   100608     // 48 x 16 f32 = 3072
#define SWT_OFF   103680     // 48 x 16 f32 = 3072
#define SXYZ_OFF  106752     // 8 x 48 f32  = 1536
#define SIDX_OFF  108288     // 128 i32     = 512
#define ATT_SMEM  108800

__global__ void __launch_bounds__(512, 1) attn_mma_kernel(
    const int* __restrict__ knn, const float* __restrict__ pos_b2)
{
    extern __shared__ char smem[];
    const int t = threadIdx.x;
    const int wid = t >> 5, lane = t & 31;
    const int wm = wid & 3, wn = wid >> 2;
    const int nb = blockIdx.x * 8;

    uint32_t* s_h  = (uint32_t*)(smem + SH_OFF);
    uint32_t* s_b  = (uint32_t*)(smem + SB_OFF);
    float* s_q   = (float*)(smem + SQ_OFF);
    float* s_k0  = (float*)(smem + SK_OFF);
    float* s_b2  = (float*)(smem + SB2_OFF);
    float* s_sc  = (float*)(smem + SSC_OFF);
    float* s_w   = (float*)(smem + SWT_OFF);
    float* s_xyz = (float*)(smem + SXYZ_OFF);
    int*   s_idx = (int*)(smem + SIDX_OFF);

    // ---- stage shared inputs ----
    for (int u = t; u < 128; u += 512) s_idx[u] = knn[(nb + (u >> 4)) * NS + (u & 15)];
    for (int u = t; u < 8 * 48; u += 512) s_xyz[u] = g_knnxyz[(long)nb * 48 + u];
    for (int u = t; u < 3 * DIM; u += 512) s_b2[u] = pos_b2[u];
    for (int u = t; u < 8 * DIM; u += 512) {
        int n = u / DIM, c = u % DIM;
        long r0 = (long)knn[(nb + n) * NS] * 576;
        s_q[u]  = g_qkv[r0 + c];
        s_k0[u] = g_qkv[r0 + 192 + c];
    }
    __syncthreads();

    // ---- base scores: q0.k_j + q0.b2[0] + k0.b2[1], per (n,h,j) ----
    for (int task = t; task < 768; task += 512) {
        int n = task / 96, h = (task / 16) % 6, j = task & 15;
        const float4* qv = (const float4*)(s_q + n * DIM + 32 * h);
        const float4* kv0 = (const float4*)(s_k0 + n * DIM + 32 * h);
        const float4* b0 = (const float4*)(s_b2 + 32 * h);
        const float4* b1 = (const float4*)(s_b2 + DIM + 32 * h);
        const float4* kj = (const float4*)(g_qkv + (long)s_idx[n * 16 + j] * 576 + 192 + 32 * h);
        float dot = 0.f;
#pragma unroll
        for (int u = 0; u < 8; u++) {
            float4 q4 = qv[u], k4 = kj[u], b04 = b0[u], b14 = b1[u], kk0 = kv0[u];
            dot += q4.x * (k4.x + b04.x) + q4.y * (k4.y + b04.y)
                 + q4.z * (k4.z + b04.z) + q4.w * (k4.w + b04.w);
            dot += kk0.x * b14.x + kk0.y * b14.y + kk0.z * b14.z + kk0.w * b14.w;
        }
        s_sc[(n * 6 + h) * 16 + j] = dot;
    }

    const int hb0 = (48 * wn) >> 5;   // first head covered by this warp's N range

    for (int m = 0; m < 3; m++) {
        float acc[2][6][4];
#pragma unroll
        for (int a1 = 0; a1 < 2; a1++)
#pragma unroll
            for (int a2 = 0; a2 < 6; a2++)
#pragma unroll
                for (int a3 = 0; a3 < 4; a3++) acc[a1][a2][a3] = 0.f;

        for (int pan = 0; pan < 3; pan++) {
            __syncthreads();
            // ---- generate A panel (h values, tf32 bits) ----
            {
                int cl = t & 63;
                int rq = t >> 6;   // 0..7
                int cg = pan * 64 + cl;
                float S0 = g_S[(m * 3 + 0) * DIM + cg];
                float S1 = g_S[(m * 3 + 1) * DIM + cg];
                float S2 = g_S[(m * 3 + 2) * DIM + cg];
                float sc = g_bnscale[m * DIM + cg], sh = g_bnshift[m * DIM + cg];
#pragma unroll
                for (int i = 0; i < 16; i++) {
                    int row = rq + 8 * i;
                    int n2 = row >> 4, j2 = row & 15;
                    float a = g_A[((long)m * NPTS + nb + n2) * DIM + cg];
                    float xx = s_xyz[n2 * 48 + j2 * 3 + 0];
                    float yy = s_xyz[n2 * 48 + j2 * 3 + 1];
                    float zz = s_xyz[n2 * 48 + j2 * 3 + 2];
                    float h = a - (xx * S0 + yy * S1 + zz * S2);
                    h = fmaxf(h * sc + sh, 0.f);
                    s_h[row * 68 + cl] = f2tf32(h);
                }
            }
            // ---- copy B panel (pre-converted tf32) ----
            {
                const float4* src = (const float4*)(g_W2t + ((long)m * DIM + pan * 64) * DIM);
                for (int u = t; u < 3072; u += 512) {
                    int k = u / 48, n4 = u % 48;
                    ((float4*)(s_b + k * 200))[n4] = src[u];
                }
            }
            __syncthreads();
            // ---- mma over this panel (8 k-steps of 8) ----
            const int rbase = 32 * wm + (lane >> 2);
            const int la3 = lane & 3;
            const int cb0 = 48 * wn + (lane >> 2);
#pragma unroll
            for (int ks = 0; ks < 8; ks++) {
                uint32_t afr[2][4];
                int ca = ks * 8 + la3;
#pragma unroll
                for (int mt = 0; mt < 2; mt++) {
                    int r = rbase + 16 * mt;
                    afr[mt][0] = s_h[r * 68 + ca];
                    afr[mt][1] = s_h[(r + 8) * 68 + ca];
                    afr[mt][2] = s_h[r * 68 + ca + 4];
                    afr[mt][3] = s_h[(r + 8) * 68 + ca + 4];
                }
                int kr = ks * 8 + la3;
#pragma unroll
                for (int nt = 0; nt < 6; nt++) {
                    uint32_t b0 = s_b[kr * 200 + cb0 + 8 * nt];
                    uint32_t b1 = s_b[(kr + 4) * 200 + cb0 + 8 * nt];
                    mma_tf32(acc[0][nt], afr[0], b0, b1);
                    mma_tf32(acc[1][nt], afr[1], b0, b1);
                }
            }
        }

        // ---- epilogue for mat m ----
        if (m < 2) {
            const float* base = (m == 0) ? s_q : s_k0;
            float part[8];   // [mt][rowhalf][bucket]
#pragma unroll
            for (int u = 0; u < 8; u++) part[u] = 0.f;
#pragma unroll
            for (int mt = 0; mt < 2; mt++) {
                const float* bp = base + (2 * wm + mt) * DIM;
#pragma unroll
                for (int nt = 0; nt < 6; nt++) {
                    int c0 = 48 * wn + 8 * nt + 2 * (lane & 3);
                    int bkt = ((48 * wn + 8 * nt) >> 5) - hb0;
                    float q0v = bp[c0], q1v = bp[c0 + 1];
                    part[mt * 4 + 0 * 2 + bkt] += acc[mt][nt][0] * q0v + acc[mt][nt][1] * q1v;
                    part[mt * 4 + 1 * 2 + bkt] += acc[mt][nt][2] * q0v + acc[mt][nt][3] * q1v;
                }
            }
#pragma unroll
            for (int u = 0; u < 8; u++) {
                part[u] += __shfl_xor_sync(0xffffffffu, part[u], 1);
                part[u] += __shfl_xor_sync(0xffffffffu, part[u], 2);
            }
            if ((lane & 3) == 0) {
                int j0 = lane >> 2;
#pragma unroll
                for (int mt = 0; mt < 2; mt++)
#pragma unroll
                    for (int rb = 0; rb < 2; rb++)
#pragma unroll
                        for (int bkt = 0; bkt < 2; bkt++) {
                            int h = hb0 + bkt;
                            atomicAdd(&s_sc[((2 * wm + mt) * 6 + h) * 16 + j0 + 8 * rb],
                                      part[mt * 4 + rb * 2 + bkt]);
                        }
            }
            if (m == 1) {
                __syncthreads();
                if (t < 48) {
                    const float scale = 0.17677669529663687f;  // 32^-0.5
                    float* sc = s_sc + t * 16;
                    float mx = -1e30f;
#pragma unroll
                    for (int j = 0; j < 16; j++) mx = fmaxf(mx, sc[j]);
                    float se = 0.f;
                    float ev[16];
#pragma unroll
                    for (int j = 0; j < 16; j++) { ev[j] = expf((sc[j] - mx) * scale); se += ev[j]; }
                    float inv = 1.f / se;
#pragma unroll
                    for (int j = 0; j < 16; j++) s_w[t * 16 + j] = ev[j] * inv;
                }
                __syncthreads();
            }
        } else {
            // output epilogue: out[node][c] = sum_j w * (v_j[c] + b2[c] + pv[j][c])
#pragma unroll
            for (int mt = 0; mt < 2; mt++) {
                int node = 2 * wm + mt;
                int j0 = lane >> 2;
                long v0b = (long)s_idx[node * 16 + j0] * 576 + 384;
                long v1b = (long)s_idx[node * 16 + j0 + 8] * 576 + 384;
#pragma unroll
                for (int nt = 0; nt < 6; nt++) {
                    int c0 = 48 * wn + 8 * nt + 2 * (lane & 3);
                    int h = c0 >> 5;
                    float w0 = s_w[(node * 6 + h) * 16 + j0];
                    float w1 = s_w[(node * 6 + h) * 16 + j0 + 8];
                    float b20 = s_b2[2 * DIM + c0], b21 = s_b2[2 * DIM + c0 + 1];
                    float o0 = w0 * (acc[mt][nt][0] + g_qkv[v0b + c0] + b20)
                             + w1 * (acc[mt][nt][2] + g_qkv[v1b + c0] + b20);
                    float o1 = w0 * (acc[mt][nt][1] + g_qkv[v0b + c0 + 1] + b21)
                             + w1 * (acc[mt][nt][3] + g_qkv[v1b + c0 + 1] + b21);
#pragma unroll
                    for (int o = 4; o < 32; o <<= 1) {
                        o0 += __shfl_xor_sync(0xffffffffu, o0, o);
                        o1 += __shfl_xor_sync(0xffffffffu, o1, o);
                    }
                    if ((lane >> 2) == 0) {
                        *(float2*)(g_attnout + (long)(nb + node) * DIM + c0) = make_float2(o0, o1);
                    }
                }
            }
        }
    }
}

// ---------------- host launcher ----------------
extern "C" void kernel_launch(void* const* d_in, const int* in_sizes, int n_in,
                              void* d_out, int out_size)
{
    const float* p      = (const float*)d_in[0];
    const float* x      = (const float*)d_in[1];
    const int*   knn    = (const int*)d_in[2];
    const float* W_qkv  = (const float*)d_in[3];
    const float* W_proj = (const float*)d_in[4];
    const float* b_proj = (const float*)d_in[5];
    const float* prop_W = (const float*)d_in[6];
    const float* prop_b = (const float*)d_in[7];
    const float* gA_W   = (const float*)d_in[8];
    const float* gA_b   = (const float*)d_in[9];
    const float* gB_W   = (const float*)d_in[10];
    const float* gB_b   = (const float*)d_in[11];
    const float* gC_W   = (const float*)d_in[12];
    const float* gC_b   = (const float*)d_in[13];
    const float* pos_W1 = (const float*)d_in[14];
    const float* pos_b1 = (const float*)d_in[15];
    const float* pos_gamma = (const float*)d_in[16];
    const float* pos_beta  = (const float*)d_in[17];
    const float* pos_W2 = (const float*)d_in[18];
    const float* pos_b2 = (const float*)d_in[19];
    const float* kn     = (const float*)d_in[20];
    const float* de_W1  = (const float*)d_in[21];
    const float* de_b1  = (const float*)d_in[22];
    const float* de_W2  = (const float*)d_in[23];
    const float* de_b2  = (const float*)d_in[24];
    const float* kp_W   = (const float*)d_in[25];
    const float* kp_b   = (const float*)d_in[26];
    const float* fus_W  = (const float*)d_in[27];
    const float* fus_b  = (const float*)d_in[28];
    float* out = (float*)d_out;

    float *xpw, *prefus, *xfused, *qkv, *attnout, *volvec;
    cudaGetSymbolAddress((void**)&xpw, g_xpw);
    cudaGetSymbolAddress((void**)&prefus, g_prefus);
    cudaGetSymbolAddress((void**)&xfused, g_xfused);
    cudaGetSymbolAddress((void**)&qkv, g_qkv);
    cudaGetSymbolAddress((void**)&attnout, g_attnout);
    cudaGetSymbolAddress((void**)&volvec, g_volvec);

    cudaFuncSetAttribute(attn_mma_kernel, cudaFuncAttributeMaxDynamicSharedMemorySize, ATT_SMEM);

    zero_kernel<<<12, 256>>>();
    pre_kernel<<<1, 64>>>(de_W2, de_b2, kp_W, kp_b);
    w2t_kernel<<<432, 256>>>(pos_W2);
    gemm_kernel<<<dim3(DIM / 64, NPTS / 64), 256>>>(x, prop_W, nullptr, nullptr, xpw, NPTS, DIM, DIM);
    node1_kernel<<<NPTS, 192>>>(p, x, knn, prop_W, prop_b, gA_W, gA_b, gB_W, gB_b,
                                pos_W1, pos_b1, kn, de_W1, de_b1, de_W2, de_b2);
    reduce_kernel<<<64, 256>>>();
    bnstats_kernel<<<dim3(NPTS / BNCHUNK, 3), 192>>>();
    finalize_kernel<<<1, 192>>>(pos_W1, pos_gamma, pos_beta, gC_W, gC_b);
    gemm_kernel<<<dim3(DIM / 64, NPTS / 64), 256>>>(prefus, fus_W, fus_b, volvec, xfused, NPTS, DIM, DIM);
    gemm_kernel<<<dim3(576 / 64, NPTS / 64), 256>>>(xfused, W_qkv, nullptr, nullptr, qkv, NPTS, DIM, 576);
    attn_mma_kernel<<<NPTS / 8, 512, ATT_SMEM>>>(knn, pos_b2);
    gemm_kernel<<<dim3(DIM / 64, NPTS / 64), 256>>>(attnout, W_proj, b_proj, nullptr, out, NPTS, DIM, DIM);
}

// round 5
// speedup vs baseline: 2.4282x; 1.3645x over previous
#include <cuda_runtime.h>
#include <cuda_fp16.h>
#include <math.h>
#include <stdint.h>

#define NPTS 16384
#define DIM  192
#define NS   16
#define NH   6
#define HD   32
#define KSP  16
#define DQ   48

// ---------------- scratch (device globals; no allocs allowed) ----------------
__device__ float g_xpw[NPTS * DIM];
__device__ float g_prefus[NPTS * DIM];
__device__ float g_xfused[NPTS * DIM];
__device__ float g_qkv[NPTS * 576];
__device__ float g_A[3L * NPTS * DIM];
__device__ float g_knnxyz[NPTS * 48];
__device__ float g_m3[NPTS * 3];
__device__ float g_attnout[NPTS * DIM];
__device__ float g_distsum[NPTS];
__device__ float g_distmax[NPTS];
__device__ double g_ch[3 * DIM * 5];
__device__ double g_Sm3[3];
__device__ double g_SM33[6];
__device__ double g_sumdist;
__device__ int    g_maxbits;
__device__ float g_S[9 * DIM];
__device__ float g_bnscale[3 * DIM];
__device__ float g_bnshift[3 * DIM];
__device__ float g_volvec[DIM];
__device__ float g_kpwproj[DQ];
__device__ float g_kpconst;
__device__ __half g_W2h[3 * DIM * DIM];    // pos_W2 as half, [m][n][k]
__device__ __half g_Wh[221184];            // dense weights as half, [n][k] per matrix

#define OFF_PROP 0
#define OFF_FUS  36864
#define OFF_QKV  73728
#define OFF_PROJ 184320

// mma.sync m16n8k16 f16 with f32 accum (baseline PTX)
__device__ __forceinline__ void mma_f16(float* c, const uint32_t* a, uint32_t b0, uint32_t b1) {
    asm volatile("mma.sync.aligned.m16n8k16.row.col.f32.f16.f16.f32 "
        "{%0,%1,%2,%3}, {%4,%5,%6,%7}, {%8,%9}, {%0,%1,%2,%3};"
        : "+f"(c[0]), "+f"(c[1]), "+f"(c[2]), "+f"(c[3])
        : "r"(a[0]), "r"(a[1]), "r"(a[2]), "r"(a[3]), "r"(b0), "r"(b1));
}

__device__ __forceinline__ uint32_t pack_h2(float a, float b) {
    __half2 h = __floats2half2_rn(a, b);
    return *(uint32_t*)&h;
}

// ---------------- zero accumulators ----------------
__global__ void zero_kernel() {
    int t = blockIdx.x * blockDim.x + threadIdx.x;
    if (t < 3 * DIM * 5) g_ch[t] = 0.0;
    if (t < 3) g_Sm3[t] = 0.0;
    if (t < 6) g_SM33[t] = 0.0;
    if (t == 0) { g_sumdist = 0.0; g_maxbits = 0; }
}

// ---------------- tiny precompute: de_W2 @ kp_W ----------------
__global__ void pre_kernel(const float* __restrict__ de_W2, const float* __restrict__ de_b2,
                           const float* __restrict__ kp_W, const float* __restrict__ kp_b) {
    int t = threadIdx.x;
    if (t < DQ) {
        float s = 0.f;
        for (int c = 0; c < DIM; c++) s += de_W2[t * DIM + c] * kp_W[c];
        g_kpwproj[t] = s;
    }
    if (t == 63) {
        float s = 0.f;
        for (int c = 0; c < DIM; c++) s += de_b2[c] * kp_W[c];
        g_kpconst = s + kp_b[0];
    }
}

// ---------------- weight conversions ----------------
__global__ void __launch_bounds__(256) w2h_kernel(const float* __restrict__ pos_W2) {
    int gid = blockIdx.x * 256 + threadIdx.x;
    if (gid >= 3 * DIM * DIM) return;
    int m = gid / (DIM * DIM);
    int n = (gid / DIM) % DIM;
    int k = gid % DIM;
    g_W2h[gid] = __float2half(pos_W2[((long)m * DIM + k) * DIM + n]);
}

__global__ void __launch_bounds__(256) wconv_kernel(const float* __restrict__ W, int Ncol, int dstoff) {
    int gid = blockIdx.x * 256 + threadIdx.x;
    if (gid >= 192 * Ncol) return;
    int k = gid / Ncol, n = gid % Ncol;
    g_Wh[dstoff + n * 192 + k] = __float2half(W[gid]);
}

// ---------------- fp16 tensor-core GEMM: C = (A fp32 + addvec?) @ Wh^T (+ bias?) ----------------
// A [M,192] fp32 row-major; Wh [Ncol,192] half (n-major); tile 128x64, K panels of 64.
__global__ void __launch_bounds__(256) hgemm_kernel(
    const float* __restrict__ A, int woff, const float* __restrict__ bias,
    const float* __restrict__ addvec, float* __restrict__ C, int Ncol)
{
    __shared__ uint32_t sA[128][36];
    __shared__ uint32_t sB[64][36];
    int t = threadIdx.x;
    int wid = t >> 5, lane = t & 31;
    int wm = wid & 3, wn = wid >> 2;
    int g = lane >> 2, la3 = lane & 3;
    int row0 = blockIdx.y * 128, col0 = blockIdx.x * 64;
    const uint32_t* Wh = (const uint32_t*)(g_Wh + woff);
    float acc[2][4][4] = {};
    for (int kp = 0; kp < 3; kp++) {
        int k0 = kp * 64;
        for (int u = t; u < 4096; u += 256) {
            int r = u >> 5, cu = u & 31;
            const float* ap = A + (long)(row0 + r) * 192 + k0 + 2 * cu;
            float f0 = ap[0], f1 = ap[1];
            if (addvec) { f0 += addvec[k0 + 2 * cu]; f1 += addvec[k0 + 2 * cu + 1]; }
            sA[r][cu] = pack_h2(f0, f1);
        }
        for (int u = t; u < 2048; u += 256) {
            int r = u >> 5, cu = u & 31;
            sB[r][cu] = Wh[(col0 + r) * 96 + (k0 >> 1) + cu];
        }
        __syncthreads();
#pragma unroll
        for (int ks = 0; ks < 4; ks++) {
            int o = ks * 8 + la3;
            uint32_t afr[2][4];
#pragma unroll
            for (int mt = 0; mt < 2; mt++) {
                int r = 32 * wm + 16 * mt + g;
                afr[mt][0] = sA[r][o];
                afr[mt][1] = sA[r + 8][o];
                afr[mt][2] = sA[r][o + 4];
                afr[mt][3] = sA[r + 8][o + 4];
            }
#pragma unroll
            for (int nt = 0; nt < 4; nt++) {
                int nr = 32 * wn + 8 * nt + g;
                uint32_t b0 = sB[nr][o], b1 = sB[nr][o + 4];
                mma_f16(acc[0][nt], afr[0], b0, b1);
                mma_f16(acc[1][nt], afr[1], b0, b1);
            }
        }
        __syncthreads();
    }
#pragma unroll
    for (int mt = 0; mt < 2; mt++) {
#pragma unroll
        for (int nt = 0; nt < 4; nt++) {
            int col = col0 + 32 * wn + 8 * nt + 2 * la3;
            float b0v = bias ? bias[col] : 0.f;
            float b1v = bias ? bias[col + 1] : 0.f;
            int r = row0 + 32 * wm + 16 * mt + g;
            *(float2*)&C[(long)r * Ncol + col] =
                make_float2(acc[mt][nt][0] + b0v, acc[mt][nt][1] + b1v);
            *(float2*)&C[(long)(r + 8) * Ncol + col] =
                make_float2(acc[mt][nt][2] + b0v, acc[mt][nt][3] + b1v);
        }
    }
}

// ---------------- per-node stage 1 ----------------
__global__ void __launch_bounds__(192) node1_kernel(
    const float* __restrict__ p, const float* __restrict__ x, const int* __restrict__ knn,
    const float* __restrict__ prop_W, const float* __restrict__ prop_b,
    const float* __restrict__ gA_W, const float* __restrict__ gA_b,
    const float* __restrict__ gB_W, const float* __restrict__ gB_b,
    const float* __restrict__ pos_W1, const float* __restrict__ pos_b1,
    const float* __restrict__ kn, const float* __restrict__ de_W1,
    const float* __restrict__ de_b1, const float* __restrict__ de_W2,
    const float* __restrict__ de_b2)
{
    int n = blockIdx.x;
    int c = threadIdx.x;
    __shared__ float s_p[3];
    __shared__ int   s_idx[NS];
    __shared__ float s_xyz[NS * 3];
    __shared__ float s_pr[NS * 3];
    __shared__ float s_dist[NS];
    __shared__ float s_rep[9];
    __shared__ float s_maxd;
    __shared__ float s_kd[KSP];
    __shared__ float s_g[KSP * DQ];
    __shared__ float s_sc[KSP];
    __shared__ float s_w[DQ];

    if (c < 3) s_p[c] = p[n * 3 + c];
    if (c < NS) s_idx[c] = knn[n * NS + c];
    __syncthreads();

    if (c < NS) {
        int id = s_idx[c];
        float ax = p[id * 3 + 0], ay = p[id * 3 + 1], az = p[id * 3 + 2];
        s_xyz[c * 3 + 0] = ax; s_xyz[c * 3 + 1] = ay; s_xyz[c * 3 + 2] = az;
        float rx = ax - s_p[0], ry = ay - s_p[1], rz = az - s_p[2];
        s_pr[c * 3 + 0] = rx; s_pr[c * 3 + 1] = ry; s_pr[c * 3 + 2] = rz;
        s_dist[c] = sqrtf(rx * rx + ry * ry + rz * rz + 1e-12f);
    }
    if (c >= 32 && c < 32 + KSP) {
        int s = c - 32;
        float dx = s_p[0] - kn[s * 3 + 0];
        float dy = s_p[1] - kn[s * 3 + 1];
        float dz = s_p[2] - kn[s * 3 + 2];
        s_kd[s] = sqrtf(dx * dx + dy * dy + dz * dz + 1e-12f);
    }
    __syncthreads();

    if (c == 0) {
        float mx = 0, my = 0, mz = 0, qx = 0, qy = 0, qz = 0, md = 0, sd = 0;
        for (int j = 0; j < NS; j++) {
            mx += s_pr[j * 3]; my += s_pr[j * 3 + 1]; mz += s_pr[j * 3 + 2];
            qx += s_xyz[j * 3]; qy += s_xyz[j * 3 + 1]; qz += s_xyz[j * 3 + 2];
            md = fmaxf(md, s_dist[j]); sd += s_dist[j];
        }
        const float inv = 1.f / NS;
        s_rep[0] = mx * inv; s_rep[1] = my * inv; s_rep[2] = mz * inv;
        s_rep[3] = qx * inv; s_rep[4] = qy * inv; s_rep[5] = qz * inv;
        s_rep[6] = s_p[0]; s_rep[7] = s_p[1]; s_rep[8] = s_p[2];
        s_maxd = md;
        g_distsum[n] = sd; g_distmax[n] = md;
        g_m3[n * 3 + 0] = qx; g_m3[n * 3 + 1] = qy; g_m3[n * 3 + 2] = qz;
    }
    if (c < NS * 3) g_knnxyz[n * 48 + c] = s_xyz[c];
    for (int idx = c; idx < KSP * DQ; idx += 192) {
        int s = idx / DQ, k = idx % DQ;
        s_g[idx] = fmaxf(s_kd[s] * de_W1[k] + de_b1[k], 0.f);
    }
    __syncthreads();

    if (c < KSP) {
        float l = g_kpconst;
        for (int k = 0; k < DQ; k++) l += s_g[c * DQ + k] * g_kpwproj[k];
        s_sc[c] = l;
    }
    __syncthreads();
    if (c == 0) {
        float mx = -1e30f;
        for (int s = 0; s < KSP; s++) mx = fmaxf(mx, s_sc[s]);
        float se = 0.f;
        for (int s = 0; s < KSP; s++) { float e = expf(s_sc[s] - mx); s_sc[s] = e; se += e; }
        float inv = 1.f / se;
        for (int s = 0; s < KSP; s++) s_sc[s] *= inv;
    }
    __syncthreads();
    if (c < DQ) {
        float w = 0.f;
        for (int s = 0; s < KSP; s++) w += s_sc[s] * s_g[s * DQ + c];
        s_w[c] = w;
    }
    __syncthreads();

    float dist_feat = de_b2[c];
#pragma unroll
    for (int k = 0; k < DQ; k++) dist_feat += s_w[k] * de_W2[k * DIM + c];

    float geo = gA_b[c] + gB_b[c] + s_maxd * gB_W[c];
#pragma unroll
    for (int i = 0; i < 9; i++) geo += s_rep[i] * gA_W[i * DIM + c];

    float w0 = prop_W[192 * DIM + c], w1 = prop_W[193 * DIM + c], w2 = prop_W[194 * DIM + c];
    float pb = prop_b[c];
    float msg = 0.f;
#pragma unroll
    for (int s = 0; s < NS; s++) {
        float v = g_xpw[(long)s_idx[s] * DIM + c]
                + s_pr[s * 3] * w0 + s_pr[s * 3 + 1] * w1 + s_pr[s * 3 + 2] * w2 + pb;
        msg += fmaxf(v, 0.f);
    }
    msg *= (1.f / NS);
    g_prefus[(long)n * DIM + c] = x[(long)n * DIM + c] + msg + geo + dist_feat;

#pragma unroll
    for (int m = 0; m < 3; m++) {
        float a = pos_b1[m * DIM + c];
        const float* W1 = pos_W1 + (long)m * 48 * DIM;
#pragma unroll
        for (int j = 0; j < NS; j++) {
            a += s_xyz[j * 3 + 0] * W1[(3 * j + 0) * DIM + c]
               + s_xyz[j * 3 + 1] * W1[(3 * j + 1) * DIM + c]
               + s_xyz[j * 3 + 2] * W1[(3 * j + 2) * DIM + c];
        }
        g_A[((long)m * NPTS + n) * DIM + c] = a;
    }
}

// ---------------- global reductions ----------------
__global__ void __launch_bounds__(256) reduce_kernel() {
    int tid = blockIdx.x * blockDim.x + threadIdx.x;
    int stride = gridDim.x * blockDim.x;
    double lsum = 0, l0 = 0, l1 = 0, l2 = 0;
    double m0 = 0, m1 = 0, m2 = 0, m3v = 0, m4 = 0, m5 = 0;
    float lmax = 0.f;
    for (int n = tid; n < NPTS; n += stride) {
        lsum += (double)g_distsum[n];
        lmax = fmaxf(lmax, g_distmax[n]);
        l0 += (double)g_m3[n * 3 + 0];
        l1 += (double)g_m3[n * 3 + 1];
        l2 += (double)g_m3[n * 3 + 2];
        for (int i = 0; i < NS; i++) {
            float xx = g_knnxyz[n * 48 + i * 3 + 0];
            float yy = g_knnxyz[n * 48 + i * 3 + 1];
            float zz = g_knnxyz[n * 48 + i * 3 + 2];
            m0 += (double)xx * xx; m1 += (double)xx * yy; m2 += (double)xx * zz;
            m3v += (double)yy * yy; m4 += (double)yy * zz; m5 += (double)zz * zz;
        }
    }
    __shared__ double sd[256];
    double vals[10] = {lsum, l0, l1, l2, m0, m1, m2, m3v, m4, m5};
    double* outs[10] = {&g_sumdist, &g_Sm3[0], &g_Sm3[1], &g_Sm3[2],
                        &g_SM33[0], &g_SM33[1], &g_SM33[2], &g_SM33[3], &g_SM33[4], &g_SM33[5]};
    for (int q = 0; q < 10; q++) {
        sd[threadIdx.x] = vals[q];
        __syncthreads();
        for (int s = 128; s > 0; s >>= 1) {
            if (threadIdx.x < s) sd[threadIdx.x] += sd[threadIdx.x + s];
            __syncthreads();
        }
        if (threadIdx.x == 0) atomicAdd(outs[q], sd[0]);
        __syncthreads();
    }
    sd[threadIdx.x] = (double)lmax;
    __syncthreads();
    for (int s = 128; s > 0; s >>= 1) {
        if (threadIdx.x < s) sd[threadIdx.x] = fmax(sd[threadIdx.x], sd[threadIdx.x + s]);
        __syncthreads();
    }
    if (threadIdx.x == 0) atomicMax(&g_maxbits, __float_as_int((float)sd[0]));
}

// ---------------- BN per-channel statistics ----------------
#define BNCHUNK 512
__global__ void __launch_bounds__(192) bnstats_kernel() {
    int m = blockIdx.y;
    int n0 = blockIdx.x * BNCHUNK;
    int c = threadIdx.x;
    double sa = 0, sa2 = 0, sx = 0, sy = 0, sz = 0;
    const float* Abase = g_A + (long)m * NPTS * DIM;
    for (int n = n0; n < n0 + BNCHUNK; n++) {
        float a = Abase[(long)n * DIM + c];
        float mx = g_m3[n * 3 + 0], my = g_m3[n * 3 + 1], mz = g_m3[n * 3 + 2];
        sa += (double)a;
        sa2 += (double)a * a;
        sx += (double)a * mx; sy += (double)a * my; sz += (double)a * mz;
    }
    double* d = g_ch + ((long)m * DIM + c) * 5;
    atomicAdd(d + 0, sa); atomicAdd(d + 1, sa2);
    atomicAdd(d + 2, sx); atomicAdd(d + 3, sy); atomicAdd(d + 4, sz);
}

// ---------------- finalize: S, BN scale/shift, vol vector ----------------
__global__ void __launch_bounds__(192) finalize_kernel(
    const float* __restrict__ pos_W1, const float* __restrict__ pos_gamma,
    const float* __restrict__ pos_beta, const float* __restrict__ gC_W,
    const float* __restrict__ gC_b)
{
    int c = threadIdx.x;
    float Sv[3][3];
#pragma unroll
    for (int m = 0; m < 3; m++)
#pragma unroll
        for (int k = 0; k < 3; k++) {
            float s = 0.f;
            for (int j = 0; j < NS; j++) s += pos_W1[(long)m * 48 * DIM + (3 * j + k) * DIM + c];
            Sv[m][k] = s;
            g_S[(m * 3 + k) * DIM + c] = s;
        }
    const double T = (double)NPTS * NS;
    double Q0 = g_SM33[0], Q1 = g_SM33[1], Q2 = g_SM33[2], Q3 = g_SM33[3], Q4 = g_SM33[4], Q5 = g_SM33[5];
    double P0 = g_Sm3[0], P1 = g_Sm3[1], P2 = g_Sm3[2];
#pragma unroll
    for (int m = 0; m < 3; m++) {
        const double* d = g_ch + ((long)m * DIM + c) * 5;
        double SA = d[0], SA2 = d[1], SMx = d[2], SMy = d[3], SMz = d[4];
        double Sx = Sv[m][0], Sy = Sv[m][1], Sz = Sv[m][2];
        double mean = (16.0 * SA - (Sx * P0 + Sy * P1 + Sz * P2)) / T;
        double sq = 16.0 * SA2 - 2.0 * (Sx * SMx + Sy * SMy + Sz * SMz)
                  + Sx * Sx * Q0 + Sy * Sy * Q3 + Sz * Sz * Q5
                  + 2.0 * (Sx * Sy * Q1 + Sx * Sz * Q2 + Sy * Sz * Q4);
        double var = sq / T - mean * mean;
        float sc = pos_gamma[m * DIM + c] * rsqrtf((float)(var + 1e-5));
        g_bnscale[m * DIM + c] = sc;
        g_bnshift[m * DIM + c] = pos_beta[m * DIM + c] - (float)mean * sc;
    }
    float maxd = __int_as_float(g_maxbits);
    float vol = (float)(g_sumdist / T) / (maxd + 1e-8f);
    g_volvec[c] = vol * gC_W[c] + gC_b[c];
}

// ---------------- fused attention via mma.sync fp16 ----------------
// Block = 8 nodes (M=128 rows = node*16 + j), 512 threads = 16 warps.
// Warp tile: 32 rows x 48 cols. Full K=192 halves resident (96 u32, stride 100).
#define SH_OFF    0          // 128 x 100 u32 = 51200
#define SB_OFF    51200      // 192 x 100 u32 = 76800
#define SQ_OFF    128000     // 6144
#define SK_OFF    134144     // 6144
#define SB2_OFF   140288     // 2304
#define SSC_OFF   142592     // 3072
#define SWT_OFF   145664     // 3072
#define SXYZ_OFF  148736     // 1536
#define SIDX_OFF  150272     // 512
#define ATT_SMEM  150784

__global__ void __launch_bounds__(512, 1) attn_mma_kernel(
    const int* __restrict__ knn, const float* __restrict__ pos_b2)
{
    extern __shared__ char smem[];
    const int t = threadIdx.x;
    const int wid = t >> 5, lane = t & 31;
    const int wm = wid & 3, wn = wid >> 2;
    const int g = lane >> 2, la3 = lane & 3;
    const int nb = blockIdx.x * 8;

    uint32_t* s_h  = (uint32_t*)(smem + SH_OFF);
    uint32_t* s_b  = (uint32_t*)(smem + SB_OFF);
    float* s_q   = (float*)(smem + SQ_OFF);
    float* s_k0  = (float*)(smem + SK_OFF);
    float* s_b2  = (float*)(smem + SB2_OFF);
    float* s_sc  = (float*)(smem + SSC_OFF);
    float* s_w   = (float*)(smem + SWT_OFF);
    float* s_xyz = (float*)(smem + SXYZ_OFF);
    int*   s_idx = (int*)(smem + SIDX_OFF);

    // ---- stage shared inputs ----
    for (int u = t; u < 128; u += 512) s_idx[u] = knn[(nb + (u >> 4)) * NS + (u & 15)];
    for (int u = t; u < 8 * 48; u += 512) s_xyz[u] = g_knnxyz[(long)nb * 48 + u];
    for (int u = t; u < 3 * DIM; u += 512) s_b2[u] = pos_b2[u];
    for (int u = t; u < 8 * DIM; u += 512) {
        int n = u / DIM, c = u % DIM;
        long r0 = (long)knn[(nb + n) * NS] * 576;
        s_q[u]  = g_qkv[r0 + c];
        s_k0[u] = g_qkv[r0 + 192 + c];
    }
    __syncthreads();

    // ---- base scores: q0.k_j + q0.b2[0] + k0.b2[1], per (n,h,j) ----
    for (int task = t; task < 768; task += 512) {
        int n = task / 96, h = (task / 16) % 6, j = task & 15;
        const float4* qv = (const float4*)(s_q + n * DIM + 32 * h);
        const float4* kv0 = (const float4*)(s_k0 + n * DIM + 32 * h);
        const float4* b0 = (const float4*)(s_b2 + 32 * h);
        const float4* b1 = (const float4*)(s_b2 + DIM + 32 * h);
        const float4* kj = (const float4*)(g_qkv + (long)s_idx[n * 16 + j] * 576 + 192 + 32 * h);
        float dot = 0.f;
#pragma unroll
        for (int u = 0; u < 8; u++) {
            float4 q4 = qv[u], k4 = kj[u], b04 = b0[u], b14 = b1[u], kk0 = kv0[u];
            dot += q4.x * (k4.x + b04.x) + q4.y * (k4.y + b04.y)
                 + q4.z * (k4.z + b04.z) + q4.w * (k4.w + b04.w);
            dot += kk0.x * b14.x + kk0.y * b14.y + kk0.z * b14.z + kk0.w * b14.w;
        }
        s_sc[(n * 6 + h) * 16 + j] = dot;
    }

    const int hb0 = (48 * wn) >> 5;

    for (int m = 0; m < 3; m++) {
        float acc[2][6][4];
#pragma unroll
        for (int a1 = 0; a1 < 2; a1++)
#pragma unroll
            for (int a2 = 0; a2 < 6; a2++)
#pragma unroll
                for (int a3 = 0; a3 < 4; a3++) acc[a1][a2][a3] = 0.f;

        __syncthreads();   // previous iteration's mma reads done before overwriting s_h/s_b
        // ---- generate A (h values) as fp16 pairs, full K=192 ----
        for (int u = t; u < 128 * 96; u += 512) {
            int row = u / 96, cu = u % 96;
            int cg = 2 * cu;
            int n2 = row >> 4, j2 = row & 15;
            float2 a2v = *(const float2*)&g_A[((long)m * NPTS + nb + n2) * DIM + cg];
            float2 S0 = *(const float2*)&g_S[(m * 3 + 0) * DIM + cg];
            float2 S1 = *(const float2*)&g_S[(m * 3 + 1) * DIM + cg];
            float2 S2 = *(const float2*)&g_S[(m * 3 + 2) * DIM + cg];
            float2 sc2 = *(const float2*)&g_bnscale[m * DIM + cg];
            float2 sh2 = *(const float2*)&g_bnshift[m * DIM + cg];
            float xx = s_xyz[n2 * 48 + j2 * 3 + 0];
            float yy = s_xyz[n2 * 48 + j2 * 3 + 1];
            float zz = s_xyz[n2 * 48 + j2 * 3 + 2];
            float h0 = a2v.x - (xx * S0.x + yy * S1.x + zz * S2.x);
            float h1 = a2v.y - (xx * S0.y + yy * S1.y + zz * S2.y);
            h0 = fmaxf(h0 * sc2.x + sh2.x, 0.f);
            h1 = fmaxf(h1 * sc2.y + sh2.y, 0.f);
            s_h[row * 100 + cu] = pack_h2(h0, h1);
        }
        // ---- copy B (pre-converted half, [n][k]) ----
        {
            const float4* src = (const float4*)((const uint32_t*)g_W2h + (long)m * DIM * 96);
            for (int u = t; u < 192 * 24; u += 512) {
                int row = u / 24, c4 = u % 24;
                ((float4*)(s_b + row * 100))[c4] = src[u];
            }
        }
        __syncthreads();

        // ---- mma: K=192 in 12 k16-steps ----
        const int rbase = 32 * wm + g;
#pragma unroll
        for (int ks = 0; ks < 12; ks++) {
            int o = ks * 8 + la3;
            uint32_t afr[2][4];
#pragma unroll
            for (int mt = 0; mt < 2; mt++) {
                int r = rbase + 16 * mt;
                afr[mt][0] = s_h[r * 100 + o];
                afr[mt][1] = s_h[(r + 8) * 100 + o];
                afr[mt][2] = s_h[r * 100 + o + 4];
                afr[mt][3] = s_h[(r + 8) * 100 + o + 4];
            }
#pragma unroll
            for (int nt = 0; nt < 6; nt++) {
                int nr = 48 * wn + 8 * nt + g;
                uint32_t b0 = s_b[nr * 100 + o];
                uint32_t b1 = s_b[nr * 100 + o + 4];
                mma_f16(acc[0][nt], afr[0], b0, b1);
                mma_f16(acc[1][nt], afr[1], b0, b1);
            }
        }

        // ---- epilogue for mat m ----
        if (m < 2) {
            const float* base = (m == 0) ? s_q : s_k0;
            float part[8];
#pragma unroll
            for (int u = 0; u < 8; u++) part[u] = 0.f;
#pragma unroll
            for (int mt = 0; mt < 2; mt++) {
                const float* bp = base + (2 * wm + mt) * DIM;
#pragma unroll
                for (int nt = 0; nt < 6; nt++) {
                    int c0 = 48 * wn + 8 * nt + 2 * la3;
                    int bkt = ((48 * wn + 8 * nt) >> 5) - hb0;
                    float q0v = bp[c0], q1v = bp[c0 + 1];
                    part[mt * 4 + 0 * 2 + bkt] += acc[mt][nt][0] * q0v + acc[mt][nt][1] * q1v;
                    part[mt * 4 + 1 * 2 + bkt] += acc[mt][nt][2] * q0v + acc[mt][nt][3] * q1v;
                }
            }
#pragma unroll
            for (int u = 0; u < 8; u++) {
                part[u] += __shfl_xor_sync(0xffffffffu, part[u], 1);
                part[u] += __shfl_xor_sync(0xffffffffu, part[u], 2);
            }
            if (la3 == 0) {
                int j0 = g;
#pragma unroll
                for (int mt = 0; mt < 2; mt++)
#pragma unroll
                    for (int rb = 0; rb < 2; rb++)
#pragma unroll
                        for (int bkt = 0; bkt < 2; bkt++) {
                            int h = hb0 + bkt;
                            atomicAdd(&s_sc[((2 * wm + mt) * 6 + h) * 16 + j0 + 8 * rb],
                                      part[mt * 4 + rb * 2 + bkt]);
                        }
            }
            if (m == 1) {
                __syncthreads();
                if (t < 48) {
                    const float scale = 0.17677669529663687f;  // 32^-0.5
                    float* sc = s_sc + t * 16;
                    float mx = -1e30f;
#pragma unroll
                    for (int j = 0; j < 16; j++) mx = fmaxf(mx, sc[j]);
                    float se = 0.f;
                    float ev[16];
#pragma unroll
                    for (int j = 0; j < 16; j++) { ev[j] = expf((sc[j] - mx) * scale); se += ev[j]; }
                    float inv = 1.f / se;
#pragma unroll
                    for (int j = 0; j < 16; j++) s_w[t * 16 + j] = ev[j] * inv;
                }
                __syncthreads();
            }
        } else {
#pragma unroll
            for (int mt = 0; mt < 2; mt++) {
                int node = 2 * wm + mt;
                int j0 = g;
                long v0b = (long)s_idx[node * 16 + j0] * 576 + 384;
                long v1b = (long)s_idx[node * 16 + j0 + 8] * 576 + 384;
#pragma unroll
                for (int nt = 0; nt < 6; nt++) {
                    int c0 = 48 * wn + 8 * nt + 2 * la3;
                    int h = c0 >> 5;
                    float w0 = s_w[(node * 6 + h) * 16 + j0];
                    float w1 = s_w[(node * 6 + h) * 16 + j0 + 8];
                    float b20 = s_b2[2 * DIM + c0], b21 = s_b2[2 * DIM + c0 + 1];
                    float o0 = w0 * (acc[mt][nt][0] + g_qkv[v0b + c0] + b20)
                             + w1 * (acc[mt][nt][2] + g_qkv[v1b + c0] + b20);
                    float o1 = w0 * (acc[mt][nt][1] + g_qkv[v0b + c0 + 1] + b21)
                             + w1 * (acc[mt][nt][3] + g_qkv[v1b + c0 + 1] + b21);
#pragma unroll
                    for (int o = 4; o < 32; o <<= 1) {
                        o0 += __shfl_xor_sync(0xffffffffu, o0, o);
                        o1 += __shfl_xor_sync(0xffffffffu, o1, o);
                    }
                    if (g == 0 && la3 == (lane & 3)) {
                        if ((lane >> 2) == 0) {
                            *(float2*)(g_attnout + (long)(nb + node) * DIM + c0) = make_float2(o0, o1);
                        }
                    }
                }
            }
        }
    }
}

// ---------------- host launcher ----------------
extern "C" void kernel_launch(void* const* d_in, const int* in_sizes, int n_in,
                              void* d_out, int out_size)
{
    const float* p      = (const float*)d_in[0];
    const float* x      = (const float*)d_in[1];
    const int*   knn    = (const int*)d_in[2];
    const float* W_qkv  = (const float*)d_in[3];
    const float* W_proj = (const float*)d_in[4];
    const float* b_proj = (const float*)d_in[5];
    const float* prop_W = (const float*)d_in[6];
    const float* prop_b = (const float*)d_in[7];
    const float* gA_W   = (const float*)d_in[8];
    const float* gA_b   = (const float*)d_in[9];
    const float* gB_W   = (const float*)d_in[10];
    const float* gB_b   = (const float*)d_in[11];
    const float* gC_W   = (const float*)d_in[12];
    const float* gC_b   = (const float*)d_in[13];
    const float* pos_W1 = (const float*)d_in[14];
    const float* pos_b1 = (const float*)d_in[15];
    const float* pos_gamma = (const float*)d_in[16];
    const float* pos_beta  = (const float*)d_in[17];
    const float* pos_W2 = (const float*)d_in[18];
    const float* pos_b2 = (const float*)d_in[19];
    const float* kn     = (const float*)d_in[20];
    const float* de_W1  = (const float*)d_in[21];
    const float* de_b1  = (const float*)d_in[22];
    const float* de_W2  = (const float*)d_in[23];
    const float* de_b2  = (const float*)d_in[24];
    const float* kp_W   = (const float*)d_in[25];
    const float* kp_b   = (const float*)d_in[26];
    const float* fus_W  = (const float*)d_in[27];
    const float* fus_b  = (const float*)d_in[28];
    float* out = (float*)d_out;

    float *xpw, *prefus, *xfused, *qkv, *attnout, *volvec;
    cudaGetSymbolAddress((void**)&xpw, g_xpw);
    cudaGetSymbolAddress((void**)&prefus, g_prefus);
    cudaGetSymbolAddress((void**)&xfused, g_xfused);
    cudaGetSymbolAddress((void**)&qkv, g_qkv);
    cudaGetSymbolAddress((void**)&attnout, g_attnout);
    cudaGetSymbolAddress((void**)&volvec, g_volvec);

    cudaFuncSetAttribute(attn_mma_kernel, cudaFuncAttributeMaxDynamicSharedMemorySize, ATT_SMEM);

    zero_kernel<<<12, 256>>>();
    pre_kernel<<<1, 64>>>(de_W2, de_b2, kp_W, kp_b);
    w2h_kernel<<<432, 256>>>(pos_W2);
    wconv_kernel<<<144, 256>>>(prop_W, 192, OFF_PROP);
    wconv_kernel<<<144, 256>>>(fus_W, 192, OFF_FUS);
    wconv_kernel<<<432, 256>>>(W_qkv, 576, OFF_QKV);
    wconv_kernel<<<144, 256>>>(W_proj, 192, OFF_PROJ);
    hgemm_kernel<<<dim3(3, 128), 256>>>(x, OFF_PROP, nullptr, nullptr, xpw, 192);
    node1_kernel<<<NPTS, 192>>>(p, x, knn, prop_W, prop_b, gA_W, gA_b, gB_W, gB_b,
                                pos_W1, pos_b1, kn, de_W1, de_b1, de_W2, de_b2);
    reduce_kernel<<<64, 256>>>();
    bnstats_kernel<<<dim3(NPTS / BNCHUNK, 3), 192>>>();
    finalize_kernel<<<1, 192>>>(pos_W1, pos_gamma, pos_beta, gC_W, gC_b);
    hgemm_kernel<<<dim3(3, 128), 256>>>(prefus, OFF_FUS, fus_b, volvec, xfused, 192);
    hgemm_kernel<<<dim3(9, 128), 256>>>(xfused, OFF_QKV, nullptr, nullptr, qkv, 576);
    attn_mma_kernel<<<NPTS / 8, 512, ATT_SMEM>>>(knn, pos_b2);
    hgemm_kernel<<<dim3(3, 128), 256>>>(attnout, OFF_PROJ, b_proj, nullptr, out, 192);
}

// round 6
// speedup vs baseline: 2.7016x; 1.1126x over previous
#include <cuda_runtime.h>
#include <cuda_fp16.h>
#include <math.h>
#include <stdint.h>

#define NPTS 16384
#define DIM  192
#define NS   16
#define NH   6
#define HD   32
#define KSP  16
#define DQ   48

// ---------------- scratch (device globals; no allocs allowed) ----------------
__device__ float g_xpw[NPTS * DIM];
__device__ float g_prefus[NPTS * DIM];
__device__ float g_qkv[NPTS * 576];
__device__ float g_A[3L * NPTS * DIM];
__device__ float g_knnxyz[NPTS * 48];
__device__ float g_m3[NPTS * 3];
__device__ float g_attnout[NPTS * DIM];
__device__ float g_distsum[NPTS];
__device__ float g_distmax[NPTS];
__device__ double g_ch[3 * DIM * 5];
__device__ double g_Sm3[3];
__device__ double g_SM33[6];
__device__ double g_sumdist;
__device__ int    g_maxbits;
__device__ float g_S[9 * DIM];
__device__ float g_bnscale[3 * DIM];
__device__ float g_bnshift[3 * DIM];
__device__ float g_volvec[DIM];
__device__ float g_kpwproj[DQ];
__device__ float g_kpconst;
__device__ __half g_W2h[3 * DIM * DIM];    // pos_W2 as half, [m][n][k]
__device__ __half g_Wh[184320];            // dense weights as half, [n][k=192]
__device__ uint32_t g_W1t[48 * 576];       // pos_W1 as tf32 bits, [k][m*192+c]
__device__ float g_bfq[576];               // fus_b @ W_qkv

#define OFF_PROP 0
#define OFF_QKV  36864
#define OFF_PROJ 147456

// mma.sync m16n8k16 f16 with f32 accum (baseline PTX)
__device__ __forceinline__ void mma_f16(float* c, const uint32_t* a, uint32_t b0, uint32_t b1) {
    asm volatile("mma.sync.aligned.m16n8k16.row.col.f32.f16.f16.f32 "
        "{%0,%1,%2,%3}, {%4,%5,%6,%7}, {%8,%9}, {%0,%1,%2,%3};"
        : "+f"(c[0]), "+f"(c[1]), "+f"(c[2]), "+f"(c[3])
        : "r"(a[0]), "r"(a[1]), "r"(a[2]), "r"(a[3]), "r"(b0), "r"(b1));
}
// mma.sync m16n8k8 tf32
__device__ __forceinline__ void mma_tf32(float* c, const uint32_t* a, uint32_t b0, uint32_t b1) {
    asm volatile("mma.sync.aligned.m16n8k8.row.col.f32.tf32.tf32.f32 "
        "{%0,%1,%2,%3}, {%4,%5,%6,%7}, {%8,%9}, {%0,%1,%2,%3};"
        : "+f"(c[0]), "+f"(c[1]), "+f"(c[2]), "+f"(c[3])
        : "r"(a[0]), "r"(a[1]), "r"(a[2]), "r"(a[3]), "r"(b0), "r"(b1));
}
__device__ __forceinline__ uint32_t pack_h2(float a, float b) {
    __half2 h = __floats2half2_rn(a, b);
    return *(uint32_t*)&h;
}
__device__ __forceinline__ uint32_t f2tf32(float f) {
    uint32_t r;
    asm("cvt.rna.tf32.f32 %0, %1;" : "=r"(r) : "f"(f));
    return r;
}

// ---------------- zero accumulators ----------------
__global__ void zero_kernel() {
    int t = blockIdx.x * blockDim.x + threadIdx.x;
    if (t < 3 * DIM * 5) g_ch[t] = 0.0;
    if (t < 3) g_Sm3[t] = 0.0;
    if (t < 6) g_SM33[t] = 0.0;
    if (t == 0) { g_sumdist = 0.0; g_maxbits = 0; }
}

// ---------------- tiny precompute: de_W2 @ kp_W ----------------
__global__ void pre_kernel(const float* __restrict__ de_W2, const float* __restrict__ de_b2,
                           const float* __restrict__ kp_W, const float* __restrict__ kp_b) {
    int t = threadIdx.x;
    if (t < DQ) {
        float s = 0.f;
        for (int c = 0; c < DIM; c++) s += de_W2[t * DIM + c] * kp_W[c];
        g_kpwproj[t] = s;
    }
    if (t == 63) {
        float s = 0.f;
        for (int c = 0; c < DIM; c++) s += de_b2[c] * kp_W[c];
        g_kpconst = s + kp_b[0];
    }
}

// ---------------- weight conversions ----------------
__global__ void __launch_bounds__(256) w2h_kernel(const float* __restrict__ pos_W2) {
    int gid = blockIdx.x * 256 + threadIdx.x;
    if (gid >= 3 * DIM * DIM) return;
    int m = gid / (DIM * DIM);
    int n = (gid / DIM) % DIM;
    int k = gid % DIM;
    g_W2h[gid] = __float2half(pos_W2[((long)m * DIM + k) * DIM + n]);
}

__global__ void __launch_bounds__(256) wconv_kernel(const float* __restrict__ W, int Ncol, int dstoff) {
    int gid = blockIdx.x * 256 + threadIdx.x;
    if (gid >= 192 * Ncol) return;
    int k = gid / Ncol, n = gid % Ncol;
    g_Wh[dstoff + n * 192 + k] = __float2half(W[gid]);
}

// Wfq = fus_W @ W_qkv  (fp32 compute, stored as half [n][k])
__global__ void __launch_bounds__(256) wfq_kernel(const float* __restrict__ fus_W,
                                                  const float* __restrict__ W_qkv) {
    int gid = blockIdx.x * 256 + threadIdx.x;
    if (gid >= 192 * 576) return;
    int k = gid / 576, n = gid % 576;
    float s = 0.f;
    for (int j = 0; j < 192; j++) s += fus_W[k * 192 + j] * W_qkv[j * 576 + n];
    g_Wh[OFF_QKV + n * 192 + k] = __float2half(s);
}
__global__ void bfq_kernel(const float* __restrict__ fus_b, const float* __restrict__ W_qkv) {
    int n = blockIdx.x * 192 + threadIdx.x;
    if (n >= 576) return;
    float s = 0.f;
    for (int j = 0; j < 192; j++) s += fus_b[j] * W_qkv[j * 576 + n];
    g_bfq[n] = s;
}
__global__ void __launch_bounds__(256) w1t_kernel(const float* __restrict__ pos_W1) {
    int gid = blockIdx.x * 256 + threadIdx.x;
    if (gid >= 48 * 576) return;
    int k = gid / 576, n = gid % 576;
    int m = n / 192, c = n % 192;
    g_W1t[gid] = f2tf32(pos_W1[((long)m * 48 + k) * 192 + c]);
}

// ---------------- fp16 tensor-core GEMM: C = (A fp32 + addvec?) @ Wh^T (+ bias?) ----------------
__global__ void __launch_bounds__(256) hgemm_kernel(
    const float* __restrict__ A, int woff, const float* __restrict__ bias,
    const float* __restrict__ addvec, float* __restrict__ C, int Ncol)
{
    __shared__ uint32_t sA[128][36];
    __shared__ uint32_t sB[64][36];
    int t = threadIdx.x;
    int wid = t >> 5, lane = t & 31;
    int wm = wid & 3, wn = wid >> 2;
    int g = lane >> 2, la3 = lane & 3;
    int row0 = blockIdx.y * 128, col0 = blockIdx.x * 64;
    const uint32_t* Wh = (const uint32_t*)(g_Wh + woff);
    float acc[2][4][4] = {};
    for (int kp = 0; kp < 3; kp++) {
        int k0 = kp * 64;
        for (int u = t; u < 4096; u += 256) {
            int r = u >> 5, cu = u & 31;
            const float* ap = A + (long)(row0 + r) * 192 + k0 + 2 * cu;
            float f0 = ap[0], f1 = ap[1];
            if (addvec) { f0 += addvec[k0 + 2 * cu]; f1 += addvec[k0 + 2 * cu + 1]; }
            sA[r][cu] = pack_h2(f0, f1);
        }
        for (int u = t; u < 2048; u += 256) {
            int r = u >> 5, cu = u & 31;
            sB[r][cu] = Wh[(col0 + r) * 96 + (k0 >> 1) + cu];
        }
        __syncthreads();
#pragma unroll
        for (int ks = 0; ks < 4; ks++) {
            int o = ks * 8 + la3;
            uint32_t afr[2][4];
#pragma unroll
            for (int mt = 0; mt < 2; mt++) {
                int r = 32 * wm + 16 * mt + g;
                afr[mt][0] = sA[r][o];
                afr[mt][1] = sA[r + 8][o];
                afr[mt][2] = sA[r][o + 4];
                afr[mt][3] = sA[r + 8][o + 4];
            }
#pragma unroll
            for (int nt = 0; nt < 4; nt++) {
                int nr = 32 * wn + 8 * nt + g;
                uint32_t b0 = sB[nr][o], b1 = sB[nr][o + 4];
                mma_f16(acc[0][nt], afr[0], b0, b1);
                mma_f16(acc[1][nt], afr[1], b0, b1);
            }
        }
        __syncthreads();
    }
#pragma unroll
    for (int mt = 0; mt < 2; mt++) {
#pragma unroll
        for (int nt = 0; nt < 4; nt++) {
            int col = col0 + 32 * wn + 8 * nt + 2 * la3;
            float b0v = bias ? bias[col] : 0.f;
            float b1v = bias ? bias[col + 1] : 0.f;
            int r = row0 + 32 * wm + 16 * mt + g;
            *(float2*)&C[(long)r * Ncol + col] =
                make_float2(acc[mt][nt][0] + b0v, acc[mt][nt][1] + b1v);
            *(float2*)&C[(long)(r + 8) * Ncol + col] =
                make_float2(acc[mt][nt][2] + b0v, acc[mt][nt][3] + b1v);
        }
    }
}

// ---------------- A = knnxyz @ pos_W1 + pos_b1 via tf32 mma (K=48) ----------------
__global__ void __launch_bounds__(256) agemm_kernel(const float* __restrict__ pos_b1) {
    __shared__ uint32_t sA[128 * 50];
    __shared__ uint32_t sB[48 * 72];
    int t = threadIdx.x;
    int wid = t >> 5, lane = t & 31;
    int wm = wid & 3, wn = wid >> 2;
    int g = lane >> 2, la3 = lane & 3;
    int row0 = blockIdx.y * 128, col0 = blockIdx.x * 64;
    int m_blk = col0 / 192, cbase = col0 - m_blk * 192;

    for (int u = t; u < 128 * 48; u += 256) {
        int r = u / 48, k = u % 48;
        sA[r * 50 + k] = f2tf32(g_knnxyz[(long)(row0 + r) * 48 + k]);
    }
    for (int u = t; u < 48 * 64; u += 256) {
        int k = u >> 6, n = u & 63;
        sB[k * 72 + n] = g_W1t[k * 576 + col0 + n];
    }
    __syncthreads();

    float acc[2][4][4] = {};
#pragma unroll
    for (int ks = 0; ks < 6; ks++) {
        int ca = ks * 8 + la3;
        uint32_t afr[2][4];
#pragma unroll
        for (int mt = 0; mt < 2; mt++) {
            int r = 32 * wm + 16 * mt + g;
            afr[mt][0] = sA[r * 50 + ca];
            afr[mt][1] = sA[(r + 8) * 50 + ca];
            afr[mt][2] = sA[r * 50 + ca + 4];
            afr[mt][3] = sA[(r + 8) * 50 + ca + 4];
        }
#pragma unroll
        for (int nt = 0; nt < 4; nt++) {
            int nc = 32 * wn + 8 * nt + g;
            uint32_t b0 = sB[ca * 72 + nc];
            uint32_t b1 = sB[(ca + 4) * 72 + nc];
            mma_tf32(acc[0][nt], afr[0], b0, b1);
            mma_tf32(acc[1][nt], afr[1], b0, b1);
        }
    }
#pragma unroll
    for (int mt = 0; mt < 2; mt++) {
#pragma unroll
        for (int nt = 0; nt < 4; nt++) {
            int colL = 32 * wn + 8 * nt + 2 * la3;
            float b0v = pos_b1[col0 + colL], b1v = pos_b1[col0 + colL + 1];
            int r = row0 + 32 * wm + 16 * mt + g;
            *(float2*)&g_A[((long)m_blk * NPTS + r) * DIM + cbase + colL] =
                make_float2(acc[mt][nt][0] + b0v, acc[mt][nt][1] + b1v);
            *(float2*)&g_A[((long)m_blk * NPTS + r + 8) * DIM + cbase + colL] =
                make_float2(acc[mt][nt][2] + b0v, acc[mt][nt][3] + b1v);
        }
    }
}

// ---------------- per-node stage 1 (no A computation anymore) ----------------
__global__ void __launch_bounds__(192) node1_kernel(
    const float* __restrict__ p, const float* __restrict__ x, const int* __restrict__ knn,
    const float* __restrict__ prop_W, const float* __restrict__ prop_b,
    const float* __restrict__ gA_W, const float* __restrict__ gA_b,
    const float* __restrict__ gB_W, const float* __restrict__ gB_b,
    const float* __restrict__ kn, const float* __restrict__ de_W1,
    const float* __restrict__ de_b1, const float* __restrict__ de_W2,
    const float* __restrict__ de_b2)
{
    int n = blockIdx.x;
    int c = threadIdx.x;
    __shared__ float s_p[3];
    __shared__ int   s_idx[NS];
    __shared__ float s_xyz[NS * 3];
    __shared__ float s_pr[NS * 3];
    __shared__ float s_dist[NS];
    __shared__ float s_rep[9];
    __shared__ float s_maxd;
    __shared__ float s_kd[KSP];
    __shared__ float s_g[KSP * DQ];
    __shared__ float s_sc[KSP];
    __shared__ float s_w[DQ];

    if (c < 3) s_p[c] = p[n * 3 + c];
    if (c < NS) s_idx[c] = knn[n * NS + c];
    __syncthreads();

    if (c < NS) {
        int id = s_idx[c];
        float ax = p[id * 3 + 0], ay = p[id * 3 + 1], az = p[id * 3 + 2];
        s_xyz[c * 3 + 0] = ax; s_xyz[c * 3 + 1] = ay; s_xyz[c * 3 + 2] = az;
        float rx = ax - s_p[0], ry = ay - s_p[1], rz = az - s_p[2];
        s_pr[c * 3 + 0] = rx; s_pr[c * 3 + 1] = ry; s_pr[c * 3 + 2] = rz;
        s_dist[c] = sqrtf(rx * rx + ry * ry + rz * rz + 1e-12f);
    }
    if (c >= 32 && c < 32 + KSP) {
        int s = c - 32;
        float dx = s_p[0] - kn[s * 3 + 0];
        float dy = s_p[1] - kn[s * 3 + 1];
        float dz = s_p[2] - kn[s * 3 + 2];
        s_kd[s] = sqrtf(dx * dx + dy * dy + dz * dz + 1e-12f);
    }
    __syncthreads();

    if (c == 0) {
        float mx = 0, my = 0, mz = 0, qx = 0, qy = 0, qz = 0, md = 0, sd = 0;
        for (int j = 0; j < NS; j++) {
            mx += s_pr[j * 3]; my += s_pr[j * 3 + 1]; mz += s_pr[j * 3 + 2];
            qx += s_xyz[j * 3]; qy += s_xyz[j * 3 + 1]; qz += s_xyz[j * 3 + 2];
            md = fmaxf(md, s_dist[j]); sd += s_dist[j];
        }
        const float inv = 1.f / NS;
        s_rep[0] = mx * inv; s_rep[1] = my * inv; s_rep[2] = mz * inv;
        s_rep[3] = qx * inv; s_rep[4] = qy * inv; s_rep[5] = qz * inv;
        s_rep[6] = s_p[0]; s_rep[7] = s_p[1]; s_rep[8] = s_p[2];
        s_maxd = md;
        g_distsum[n] = sd; g_distmax[n] = md;
        g_m3[n * 3 + 0] = qx; g_m3[n * 3 + 1] = qy; g_m3[n * 3 + 2] = qz;
    }
    if (c < NS * 3) g_knnxyz[n * 48 + c] = s_xyz[c];
    for (int idx = c; idx < KSP * DQ; idx += 192) {
        int s = idx / DQ, k = idx % DQ;
        s_g[idx] = fmaxf(s_kd[s] * de_W1[k] + de_b1[k], 0.f);
    }
    __syncthreads();

    if (c < KSP) {
        float l = g_kpconst;
        for (int k = 0; k < DQ; k++) l += s_g[c * DQ + k] * g_kpwproj[k];
        s_sc[c] = l;
    }
    __syncthreads();
    if (c == 0) {
        float mx = -1e30f;
        for (int s = 0; s < KSP; s++) mx = fmaxf(mx, s_sc[s]);
        float se = 0.f;
        for (int s = 0; s < KSP; s++) { float e = expf(s_sc[s] - mx); s_sc[s] = e; se += e; }
        float inv = 1.f / se;
        for (int s = 0; s < KSP; s++) s_sc[s] *= inv;
    }
    __syncthreads();
    if (c < DQ) {
        float w = 0.f;
        for (int s = 0; s < KSP; s++) w += s_sc[s] * s_g[s * DQ + c];
        s_w[c] = w;
    }
    __syncthreads();

    float dist_feat = de_b2[c];
#pragma unroll
    for (int k = 0; k < DQ; k++) dist_feat += s_w[k] * de_W2[k * DIM + c];

    float geo = gA_b[c] + gB_b[c] + s_maxd * gB_W[c];
#pragma unroll
    for (int i = 0; i < 9; i++) geo += s_rep[i] * gA_W[i * DIM + c];

    float w0 = prop_W[192 * DIM + c], w1 = prop_W[193 * DIM + c], w2 = prop_W[194 * DIM + c];
    float pb = prop_b[c];
    float msg = 0.f;
#pragma unroll
    for (int s = 0; s < NS; s++) {
        float v = g_xpw[(long)s_idx[s] * DIM + c]
                + s_pr[s * 3] * w0 + s_pr[s * 3 + 1] * w1 + s_pr[s * 3 + 2] * w2 + pb;
        msg += fmaxf(v, 0.f);
    }
    msg *= (1.f / NS);
    g_prefus[(long)n * DIM + c] = x[(long)n * DIM + c] + msg + geo + dist_feat;
}

// ---------------- global reductions ----------------
__global__ void __launch_bounds__(256) reduce_kernel() {
    int tid = blockIdx.x * blockDim.x + threadIdx.x;
    int stride = gridDim.x * blockDim.x;
    double lsum = 0, l0 = 0, l1 = 0, l2 = 0;
    double m0 = 0, m1 = 0, m2 = 0, m3v = 0, m4 = 0, m5 = 0;
    float lmax = 0.f;
    for (int n = tid; n < NPTS; n += stride) {
        lsum += (double)g_distsum[n];
        lmax = fmaxf(lmax, g_distmax[n]);
        l0 += (double)g_m3[n * 3 + 0];
        l1 += (double)g_m3[n * 3 + 1];
        l2 += (double)g_m3[n * 3 + 2];
        for (int i = 0; i < NS; i++) {
            float xx = g_knnxyz[n * 48 + i * 3 + 0];
            float yy = g_knnxyz[n * 48 + i * 3 + 1];
            float zz = g_knnxyz[n * 48 + i * 3 + 2];
            m0 += (double)xx * xx; m1 += (double)xx * yy; m2 += (double)xx * zz;
            m3v += (double)yy * yy; m4 += (double)yy * zz; m5 += (double)zz * zz;
        }
    }
    __shared__ double sd[256];
    double vals[10] = {lsum, l0, l1, l2, m0, m1, m2, m3v, m4, m5};
    double* outs[10] = {&g_sumdist, &g_Sm3[0], &g_Sm3[1], &g_Sm3[2],
                        &g_SM33[0], &g_SM33[1], &g_SM33[2], &g_SM33[3], &g_SM33[4], &g_SM33[5]};
    for (int q = 0; q < 10; q++) {
        sd[threadIdx.x] = vals[q];
        __syncthreads();
        for (int s = 128; s > 0; s >>= 1) {
            if (threadIdx.x < s) sd[threadIdx.x] += sd[threadIdx.x + s];
            __syncthreads();
        }
        if (threadIdx.x == 0) atomicAdd(outs[q], sd[0]);
        __syncthreads();
    }
    sd[threadIdx.x] = (double)lmax;
    __syncthreads();
    for (int s = 128; s > 0; s >>= 1) {
        if (threadIdx.x < s) sd[threadIdx.x] = fmax(sd[threadIdx.x], sd[threadIdx.x + s]);
        __syncthreads();
    }
    if (threadIdx.x == 0) atomicMax(&g_maxbits, __float_as_int((float)sd[0]));
}

// ---------------- BN per-channel statistics ----------------
#define BNCHUNK 512
__global__ void __launch_bounds__(192) bnstats_kernel() {
    int m = blockIdx.y;
    int n0 = blockIdx.x * BNCHUNK;
    int c = threadIdx.x;
    double sa = 0, sa2 = 0, sx = 0, sy = 0, sz = 0;
    const float* Abase = g_A + (long)m * NPTS * DIM;
    for (int n = n0; n < n0 + BNCHUNK; n++) {
        float a = Abase[(long)n * DIM + c];
        float mx = g_m3[n * 3 + 0], my = g_m3[n * 3 + 1], mz = g_m3[n * 3 + 2];
        sa += (double)a;
        sa2 += (double)a * a;
        sx += (double)a * mx; sy += (double)a * my; sz += (double)a * mz;
    }
    double* d = g_ch + ((long)m * DIM + c) * 5;
    atomicAdd(d + 0, sa); atomicAdd(d + 1, sa2);
    atomicAdd(d + 2, sx); atomicAdd(d + 3, sy); atomicAdd(d + 4, sz);
}

// ---------------- finalize: S, BN scale/shift, vol vector ----------------
__global__ void __launch_bounds__(192) finalize_kernel(
    const float* __restrict__ pos_W1, const float* __restrict__ pos_gamma,
    const float* __restrict__ pos_beta, const float* __restrict__ gC_W,
    const float* __restrict__ gC_b)
{
    int c = threadIdx.x;
    float Sv[3][3];
#pragma unroll
    for (int m = 0; m < 3; m++)
#pragma unroll
        for (int k = 0; k < 3; k++) {
            float s = 0.f;
            for (int j = 0; j < NS; j++) s += pos_W1[(long)m * 48 * DIM + (3 * j + k) * DIM + c];
            Sv[m][k] = s;
            g_S[(m * 3 + k) * DIM + c] = s;
        }
    const double T = (double)NPTS * NS;
    double Q0 = g_SM33[0], Q1 = g_SM33[1], Q2 = g_SM33[2], Q3 = g_SM33[3], Q4 = g_SM33[4], Q5 = g_SM33[5];
    double P0 = g_Sm3[0], P1 = g_Sm3[1], P2 = g_Sm3[2];
#pragma unroll
    for (int m = 0; m < 3; m++) {
        const double* d = g_ch + ((long)m * DIM + c) * 5;
        double SA = d[0], SA2 = d[1], SMx = d[2], SMy = d[3], SMz = d[4];
        double Sx = Sv[m][0], Sy = Sv[m][1], Sz = Sv[m][2];
        double mean = (16.0 * SA - (Sx * P0 + Sy * P1 + Sz * P2)) / T;
        double sq = 16.0 * SA2 - 2.0 * (Sx * SMx + Sy * SMy + Sz * SMz)
                  + Sx * Sx * Q0 + Sy * Sy * Q3 + Sz * Sz * Q5
                  + 2.0 * (Sx * Sy * Q1 + Sx * Sz * Q2 + Sy * Sz * Q4);
        double var = sq / T - mean * mean;
        float sc = pos_gamma[m * DIM + c] * rsqrtf((float)(var + 1e-5));
        g_bnscale[m * DIM + c] = sc;
        g_bnshift[m * DIM + c] = pos_beta[m * DIM + c] - (float)mean * sc;
    }
    float maxd = __int_as_float(g_maxbits);
    float vol = (float)(g_sumdist / T) / (maxd + 1e-8f);
    g_volvec[c] = vol * gC_W[c] + gC_b[c];
}

// ---------------- fused attention via mma.sync fp16 ----------------
#define SH_OFF    0          // 128 x 100 u32 = 51200
#define SB_OFF    51200      // 192 x 100 u32 = 76800
#define SQ_OFF    128000     // 6144
#define SK_OFF    134144     // 6144
#define SB2_OFF   140288     // 2304
#define SSC_OFF   142592     // 3072
#define SWT_OFF   145664     // 3072
#define SXYZ_OFF  148736     // 1536
#define SIDX_OFF  150272     // 512
#define SAH_OFF   150784     // 8 x 192 f32 = 6144 (BN-folded A)
#define SSH_OFF   156928     // 3 x 192 f32 = 2304 (BN-folded S)
#define ATT_SMEM  159232

__global__ void __launch_bounds__(512, 1) attn_mma_kernel(
    const int* __restrict__ knn, const float* __restrict__ pos_b2)
{
    extern __shared__ char smem[];
    const int t = threadIdx.x;
    const int wid = t >> 5, lane = t & 31;
    const int wm = wid & 3, wn = wid >> 2;
    const int g = lane >> 2, la3 = lane & 3;
    const int nb = blockIdx.x * 8;

    uint32_t* s_h  = (uint32_t*)(smem + SH_OFF);
    uint32_t* s_b  = (uint32_t*)(smem + SB_OFF);
    float* s_q   = (float*)(smem + SQ_OFF);
    float* s_k0  = (float*)(smem + SK_OFF);
    float* s_b2  = (float*)(smem + SB2_OFF);
    float* s_sc  = (float*)(smem + SSC_OFF);
    float* s_w   = (float*)(smem + SWT_OFF);
    float* s_xyz = (float*)(smem + SXYZ_OFF);
    int*   s_idx = (int*)(smem + SIDX_OFF);
    float* s_ahat = (float*)(smem + SAH_OFF);
    float* s_Sh   = (float*)(smem + SSH_OFF);

    // ---- stage shared inputs ----
    for (int u = t; u < 128; u += 512) s_idx[u] = knn[(nb + (u >> 4)) * NS + (u & 15)];
    for (int u = t; u < 8 * 48; u += 512) s_xyz[u] = g_knnxyz[(long)nb * 48 + u];
    for (int u = t; u < 3 * DIM; u += 512) s_b2[u] = pos_b2[u];
    for (int u = t; u < 8 * DIM; u += 512) {
        int n = u / DIM, c = u % DIM;
        long r0 = (long)knn[(nb + n) * NS] * 576;
        s_q[u]  = g_qkv[r0 + c];
        s_k0[u] = g_qkv[r0 + 192 + c];
    }
    __syncthreads();

    // ---- base scores: q0.k_j + q0.b2[0] + k0.b2[1], per (n,h,j) ----
    for (int task = t; task < 768; task += 512) {
        int n = task / 96, h = (task / 16) % 6, j = task & 15;
        const float4* qv = (const float4*)(s_q + n * DIM + 32 * h);
        const float4* kv0 = (const float4*)(s_k0 + n * DIM + 32 * h);
        const float4* b0 = (const float4*)(s_b2 + 32 * h);
        const float4* b1 = (const float4*)(s_b2 + DIM + 32 * h);
        const float4* kj = (const float4*)(g_qkv + (long)s_idx[n * 16 + j] * 576 + 192 + 32 * h);
        float dot = 0.f;
#pragma unroll
        for (int u = 0; u < 8; u++) {
            float4 q4 = qv[u], k4 = kj[u], b04 = b0[u], b14 = b1[u], kk0 = kv0[u];
            dot += q4.x * (k4.x + b04.x) + q4.y * (k4.y + b04.y)
                 + q4.z * (k4.z + b04.z) + q4.w * (k4.w + b04.w);
            dot += kk0.x * b14.x + kk0.y * b14.y + kk0.z * b14.z + kk0.w * b14.w;
        }
        s_sc[(n * 6 + h) * 16 + j] = dot;
    }

    const int hb0 = (48 * wn) >> 5;
    const int grow = t >> 2;                 // generation row 0..127
    const int gn2 = grow >> 4, gj2 = grow & 15;

    for (int m = 0; m < 3; m++) {
        float acc[2][6][4];
#pragma unroll
        for (int a1 = 0; a1 < 2; a1++)
#pragma unroll
            for (int a2 = 0; a2 < 6; a2++)
#pragma unroll
                for (int a3 = 0; a3 < 4; a3++) acc[a1][a2][a3] = 0.f;

        __syncthreads();   // prior mma reads of s_h/s_b done; prior generation reads of s_ahat done
        // ---- stage BN-folded A and S for this mat ----
        for (int u = t; u < 8 * DIM; u += 512) {
            int cg = u % DIM;
            float a = g_A[((long)m * NPTS + nb + (u / DIM)) * DIM + cg];
            s_ahat[u] = a * g_bnscale[m * DIM + cg] + g_bnshift[m * DIM + cg];
        }
        for (int u = t; u < 3 * DIM; u += 512) {
            int cg = u % DIM;
            s_Sh[u] = g_S[(m * 3 + u / DIM) * DIM + cg] * g_bnscale[m * DIM + cg];
        }
        // ---- copy B (pre-converted half, [n][k]) ----
        {
            const float4* src = (const float4*)((const uint32_t*)g_W2h + (long)m * DIM * 96);
            for (int u = t; u < 192 * 24; u += 512) {
                int row = u / 24, c4 = u % 24;
                ((float4*)(s_b + row * 100))[c4] = src[u];
            }
        }
        __syncthreads();
        // ---- generate h (fp16 pairs) from SMEM-staged operands ----
        {
            float xx = s_xyz[gn2 * 48 + gj2 * 3 + 0];
            float yy = s_xyz[gn2 * 48 + gj2 * 3 + 1];
            float zz = s_xyz[gn2 * 48 + gj2 * 3 + 2];
            const float* ah = s_ahat + gn2 * DIM;
#pragma unroll
            for (int i = 0; i < 24; i++) {
                int cu = (t & 3) + 4 * i;
                int cg = 2 * cu;
                float2 a2 = *(const float2*)&ah[cg];
                float2 S0 = *(const float2*)&s_Sh[cg];
                float2 S1 = *(const float2*)&s_Sh[DIM + cg];
                float2 S2 = *(const float2*)&s_Sh[2 * DIM + cg];
                float h0 = a2.x - (xx * S0.x + yy * S1.x + zz * S2.x);
                float h1 = a2.y - (xx * S0.y + yy * S1.y + zz * S2.y);
                s_h[grow * 100 + cu] = pack_h2(fmaxf(h0, 0.f), fmaxf(h1, 0.f));
            }
        }
        __syncthreads();

        // ---- mma: K=192 in 12 k16-steps ----
        const int rbase = 32 * wm + g;
#pragma unroll
        for (int ks = 0; ks < 12; ks++) {
            int o = ks * 8 + la3;
            uint32_t afr[2][4];
#pragma unroll
            for (int mt = 0; mt < 2; mt++) {
                int r = rbase + 16 * mt;
                afr[mt][0] = s_h[r * 100 + o];
                afr[mt][1] = s_h[(r + 8) * 100 + o];
                afr[mt][2] = s_h[r * 100 + o + 4];
                afr[mt][3] = s_h[(r + 8) * 100 + o + 4];
            }
#pragma unroll
            for (int nt = 0; nt < 6; nt++) {
                int nr = 48 * wn + 8 * nt + g;
                uint32_t b0 = s_b[nr * 100 + o];
                uint32_t b1 = s_b[nr * 100 + o + 4];
                mma_f16(acc[0][nt], afr[0], b0, b1);
                mma_f16(acc[1][nt], afr[1], b0, b1);
            }
        }

        // ---- epilogue for mat m ----
        if (m < 2) {
            const float* base = (m == 0) ? s_q : s_k0;
            float part[8];
#pragma unroll
            for (int u = 0; u < 8; u++) part[u] = 0.f;
#pragma unroll
            for (int mt = 0; mt < 2; mt++) {
                const float* bp = base + (2 * wm + mt) * DIM;
#pragma unroll
                for (int nt = 0; nt < 6; nt++) {
                    int c0 = 48 * wn + 8 * nt + 2 * la3;
                    int bkt = ((48 * wn + 8 * nt) >> 5) - hb0;
                    float q0v = bp[c0], q1v = bp[c0 + 1];
                    part[mt * 4 + 0 * 2 + bkt] += acc[mt][nt][0] * q0v + acc[mt][nt][1] * q1v;
                    part[mt * 4 + 1 * 2 + bkt] += acc[mt][nt][2] * q0v + acc[mt][nt][3] * q1v;
                }
            }
#pragma unroll
            for (int u = 0; u < 8; u++) {
                part[u] += __shfl_xor_sync(0xffffffffu, part[u], 1);
                part[u] += __shfl_xor_sync(0xffffffffu, part[u], 2);
            }
            if (la3 == 0) {
                int j0 = g;
#pragma unroll
                for (int mt = 0; mt < 2; mt++)
#pragma unroll
                    for (int rb = 0; rb < 2; rb++)
#pragma unroll
                        for (int bkt = 0; bkt < 2; bkt++) {
                            int h = hb0 + bkt;
                            atomicAdd(&s_sc[((2 * wm + mt) * 6 + h) * 16 + j0 + 8 * rb],
                                      part[mt * 4 + rb * 2 + bkt]);
                        }
            }
            if (m == 1) {
                __syncthreads();
                if (t < 48) {
                    const float scale = 0.17677669529663687f;  // 32^-0.5
                    float* sc = s_sc + t * 16;
                    float mx = -1e30f;
#pragma unroll
                    for (int j = 0; j < 16; j++) mx = fmaxf(mx, sc[j]);
                    float se = 0.f;
                    float ev[16];
#pragma unroll
                    for (int j = 0; j < 16; j++) { ev[j] = expf((sc[j] - mx) * scale); se += ev[j]; }
                    float inv = 1.f / se;
#pragma unroll
                    for (int j = 0; j < 16; j++) s_w[t * 16 + j] = ev[j] * inv;
                }
                __syncthreads();
            }
        } else {
#pragma unroll
            for (int mt = 0; mt < 2; mt++) {
                int node = 2 * wm + mt;
                int j0 = g;
                long v0b = (long)s_idx[node * 16 + j0] * 576 + 384;
                long v1b = (long)s_idx[node * 16 + j0 + 8] * 576 + 384;
#pragma unroll
                for (int nt = 0; nt < 6; nt++) {
                    int c0 = 48 * wn + 8 * nt + 2 * la3;
                    int h = c0 >> 5;
                    float w0 = s_w[(node * 6 + h) * 16 + j0];
                    float w1 = s_w[(node * 6 + h) * 16 + j0 + 8];
                    float b20 = s_b2[2 * DIM + c0], b21 = s_b2[2 * DIM + c0 + 1];
                    float o0 = w0 * (acc[mt][nt][0] + g_qkv[v0b + c0] + b20)
                             + w1 * (acc[mt][nt][2] + g_qkv[v1b + c0] + b20);
                    float o1 = w0 * (acc[mt][nt][1] + g_qkv[v0b + c0 + 1] + b21)
                             + w1 * (acc[mt][nt][3] + g_qkv[v1b + c0 + 1] + b21);
#pragma unroll
                    for (int o = 4; o < 32; o <<= 1) {
                        o0 += __shfl_xor_sync(0xffffffffu, o0, o);
                        o1 += __shfl_xor_sync(0xffffffffu, o1, o);
                    }
                    if (g == 0) {
                        *(float2*)(g_attnout + (long)(nb + node) * DIM + c0) = make_float2(o0, o1);
                    }
                }
            }
        }
    }
}

// ---------------- host launcher ----------------
extern "C" void kernel_launch(void* const* d_in, const int* in_sizes, int n_in,
                              void* d_out, int out_size)
{
    const float* p      = (const float*)d_in[0];
    const float* x      = (const float*)d_in[1];
    const int*   knn    = (const int*)d_in[2];
    const float* W_qkv  = (const float*)d_in[3];
    const float* W_proj = (const float*)d_in[4];
    const float* b_proj = (const float*)d_in[5];
    const float* prop_W = (const float*)d_in[6];
    const float* prop_b = (const float*)d_in[7];
    const float* gA_W   = (const float*)d_in[8];
    const float* gA_b   = (const float*)d_in[9];
    const float* gB_W   = (const float*)d_in[10];
    const float* gB_b   = (const float*)d_in[11];
    const float* gC_W   = (const float*)d_in[12];
    const float* gC_b   = (const float*)d_in[13];
    const float* pos_W1 = (const float*)d_in[14];
    const float* pos_b1 = (const float*)d_in[15];
    const float* pos_gamma = (const float*)d_in[16];
    const float* pos_beta  = (const float*)d_in[17];
    const float* pos_W2 = (const float*)d_in[18];
    const float* pos_b2 = (const float*)d_in[19];
    const float* kn     = (const float*)d_in[20];
    const float* de_W1  = (const float*)d_in[21];
    const float* de_b1  = (const float*)d_in[22];
    const float* de_W2  = (const float*)d_in[23];
    const float* de_b2  = (const float*)d_in[24];
    const float* kp_W   = (const float*)d_in[25];
    const float* kp_b   = (const float*)d_in[26];
    const float* fus_W  = (const float*)d_in[27];
    const float* fus_b  = (const float*)d_in[28];
    float* out = (float*)d_out;

    float *xpw, *prefus, *qkv, *attnout, *volvec, *bfq;
    cudaGetSymbolAddress((void**)&xpw, g_xpw);
    cudaGetSymbolAddress((void**)&prefus, g_prefus);
    cudaGetSymbolAddress((void**)&qkv, g_qkv);
    cudaGetSymbolAddress((void**)&attnout, g_attnout);
    cudaGetSymbolAddress((void**)&volvec, g_volvec);
    cudaGetSymbolAddress((void**)&bfq, g_bfq);

    cudaFuncSetAttribute(attn_mma_kernel, cudaFuncAttributeMaxDynamicSharedMemorySize, ATT_SMEM);

    zero_kernel<<<12, 256>>>();
    pre_kernel<<<1, 64>>>(de_W2, de_b2, kp_W, kp_b);
    w2h_kernel<<<432, 256>>>(pos_W2);
    wconv_kernel<<<144, 256>>>(prop_W, 192, OFF_PROP);
    wconv_kernel<<<144, 256>>>(W_proj, 192, OFF_PROJ);
    wfq_kernel<<<432, 256>>>(fus_W, W_qkv);
    bfq_kernel<<<3, 192>>>(fus_b, W_qkv);
    w1t_kernel<<<108, 256>>>(pos_W1);
    hgemm_kernel<<<dim3(3, 128), 256>>>(x, OFF_PROP, nullptr, nullptr, xpw, 192);
    node1_kernel<<<NPTS, 192>>>(p, x, knn, prop_W, prop_b, gA_W, gA_b, gB_W, gB_b,
                                kn, de_W1, de_b1, de_W2, de_b2);
    agemm_kernel<<<dim3(9, 128), 256>>>(pos_b1);
    reduce_kernel<<<64, 256>>>();
    bnstats_kernel<<<dim3(NPTS / BNCHUNK, 3), 192>>>();
    finalize_kernel<<<1, 192>>>(pos_W1, pos_gamma, pos_beta, gC_W, gC_b);
    hgemm_kernel<<<dim3(9, 128), 256>>>(prefus, OFF_QKV, bfq, volvec, qkv, 576);
    attn_mma_kernel<<<NPTS / 8, 512, ATT_SMEM>>>(knn, pos_b2);
    hgemm_kernel<<<dim3(3, 128), 256>>>(attnout, OFF_PROJ, b_proj, nullptr, out, 192);
}

// round 7
// speedup vs baseline: 3.6849x; 1.3640x over previous
#include <cuda_runtime.h>
#include <cuda_fp16.h>
#include <math.h>
#include <stdint.h>

#define NPTS 16384
#define DIM  192
#define NS   16
#define NH   6
#define HD   32
#define KSP  16
#define DQ   48

// ---------------- scratch (device globals; no allocs allowed) ----------------
__device__ float g_xpw[NPTS * DIM];
__device__ float g_qkv[NPTS * 576];
__device__ float g_A[3L * NPTS * DIM];
__device__ float g_knnxyz[NPTS * 48];
__device__ float g_m3[NPTS * 3];
__device__ float g_distsum[NPTS];
__device__ float g_distmax[NPTS];
__device__ double g_ch[3 * DIM * 5];
__device__ double g_Sm3[3];
__device__ double g_SM33[6];
__device__ double g_sumdist;
__device__ int    g_maxbits;
__device__ float g_S[9 * DIM];
__device__ float g_bnscale[3 * DIM];
__device__ float g_bnshift[3 * DIM];
__device__ float g_volvec[DIM];
__device__ float g_kpwproj[DQ];
__device__ float g_kpconst;
__device__ __half g_Wh[184320];            // dense weights as half, [n][k=192]
__device__ uint32_t g_W1t[48 * 576];       // pos_W1 as tf32 bits, [k][m*192+c]
__device__ float g_bfq[576];               // fus_b @ W_qkv
__device__ uint32_t g_W2f[221184];         // pos_W2 fp16 mma fragments [m][wn][ks][qq][lane][e]
__device__ __half g_xh[NPTS * DIM];        // x as half
__device__ __half g_prefh[NPTS * DIM];     // prefus as half
__device__ __half g_atth[NPTS * DIM];      // attn out as half

#define OFF_PROP 0
#define OFF_QKV  36864
#define OFF_PROJ 147456

// mma.sync m16n8k16 f16 with f32 accum (baseline PTX)
__device__ __forceinline__ void mma_f16(float* c, const uint32_t* a, uint32_t b0, uint32_t b1) {
    asm volatile("mma.sync.aligned.m16n8k16.row.col.f32.f16.f16.f32 "
        "{%0,%1,%2,%3}, {%4,%5,%6,%7}, {%8,%9}, {%0,%1,%2,%3};"
        : "+f"(c[0]), "+f"(c[1]), "+f"(c[2]), "+f"(c[3])
        : "r"(a[0]), "r"(a[1]), "r"(a[2]), "r"(a[3]), "r"(b0), "r"(b1));
}
// mma.sync m16n8k8 tf32
__device__ __forceinline__ void mma_tf32(float* c, const uint32_t* a, uint32_t b0, uint32_t b1) {
    asm volatile("mma.sync.aligned.m16n8k8.row.col.f32.tf32.tf32.f32 "
        "{%0,%1,%2,%3}, {%4,%5,%6,%7}, {%8,%9}, {%0,%1,%2,%3};"
        : "+f"(c[0]), "+f"(c[1]), "+f"(c[2]), "+f"(c[3])
        : "r"(a[0]), "r"(a[1]), "r"(a[2]), "r"(a[3]), "r"(b0), "r"(b1));
}
__device__ __forceinline__ void ldm_x4(uint32_t* d, uint32_t a) {
    asm volatile("ldmatrix.sync.aligned.m8n8.x4.shared.b16 {%0,%1,%2,%3}, [%4];"
        : "=r"(d[0]), "=r"(d[1]), "=r"(d[2]), "=r"(d[3]) : "r"(a));
}
__device__ __forceinline__ uint32_t pack_h2(float a, float b) {
    __half2 h = __floats2half2_rn(a, b);
    return *(uint32_t*)&h;
}
__device__ __forceinline__ uint32_t f2tf32(float f) {
    uint32_t r;
    asm("cvt.rna.tf32.f32 %0, %1;" : "=r"(r) : "f"(f));
    return r;
}

// ---------------- merged prep: zeros + weight converts + x->half ----------------
__global__ void __launch_bounds__(256) prep_kernel(
    const float* __restrict__ prop_W, const float* __restrict__ W_proj,
    const float* __restrict__ pos_W1, const float* __restrict__ x)
{
    int gid = blockIdx.x * 256 + threadIdx.x;
    int stride = gridDim.x * 256;
    for (int i = gid; i < 3 * DIM * 5; i += stride) g_ch[i] = 0.0;
    if (gid < 3) g_Sm3[gid] = 0.0;
    if (gid < 6) g_SM33[gid] = 0.0;
    if (gid == 0) { g_sumdist = 0.0; g_maxbits = 0; }
    for (int i = gid; i < 192 * 192; i += stride) {
        int k = i / 192, n = i % 192;
        g_Wh[OFF_PROP + n * 192 + k] = __float2half(prop_W[i]);
        g_Wh[OFF_PROJ + n * 192 + k] = __float2half(W_proj[i]);
    }
    for (int i = gid; i < 48 * 576; i += stride) {
        int k = i / 576, n = i % 576;
        int m = n / 192, c = n % 192;
        g_W1t[i] = f2tf32(pos_W1[((long)m * 48 + k) * 192 + c]);
    }
    for (int i = gid; i < NPTS * DIM / 2; i += stride) {
        float2 v = ((const float2*)x)[i];
        ((uint32_t*)g_xh)[i] = pack_h2(v.x, v.y);
    }
}

// ---------------- tiny precompute: de_W2 @ kp_W ----------------
__global__ void pre_kernel(const float* __restrict__ de_W2, const float* __restrict__ de_b2,
                           const float* __restrict__ kp_W, const float* __restrict__ kp_b) {
    int t = threadIdx.x;
    if (t < DQ) {
        float s = 0.f;
        for (int c = 0; c < DIM; c++) s += de_W2[t * DIM + c] * kp_W[c];
        g_kpwproj[t] = s;
    }
    if (t == 63) {
        float s = 0.f;
        for (int c = 0; c < DIM; c++) s += de_b2[c] * kp_W[c];
        g_kpconst = s + kp_b[0];
    }
}

// ---------------- pos_W2 -> per-(mat,wn,lane) mma fragment buffer ----------------
__global__ void __launch_bounds__(256) w2f_kernel(const float* __restrict__ pos_W2) {
    int gid = blockIdx.x * 256 + threadIdx.x;
    if (gid >= 221184) return;
    int e = gid & 3;
    int r = gid >> 2;
    int lane = r & 31; r >>= 5;
    int qq = r % 3; r /= 3;
    int ks = r % 12; r /= 12;
    int wn = r & 3;
    int m = r >> 2;
    int q = qq * 4 + e;
    int nt = q >> 1, ib = q & 1;
    int g = lane >> 2, la3 = lane & 3;
    int nr = 48 * wn + 8 * nt + g;
    int o = ks * 8 + la3 + 4 * ib;
    g_W2f[gid] = pack_h2(pos_W2[((long)m * DIM + 2 * o) * DIM + nr],
                         pos_W2[((long)m * DIM + 2 * o + 1) * DIM + nr]);
}

// Wfq = fus_W @ W_qkv  (fp32 compute, stored as half [n][k])
__global__ void __launch_bounds__(256) wfq_kernel(const float* __restrict__ fus_W,
                                                  const float* __restrict__ W_qkv) {
    int gid = blockIdx.x * 256 + threadIdx.x;
    if (gid >= 192 * 576) return;
    int k = gid / 576, n = gid % 576;
    float s = 0.f;
    for (int j = 0; j < 192; j++) s += fus_W[k * 192 + j] * W_qkv[j * 576 + n];
    g_Wh[OFF_QKV + n * 192 + k] = __float2half(s);
}
__global__ void bfq_kernel(const float* __restrict__ fus_b, const float* __restrict__ W_qkv) {
    int n = blockIdx.x * 192 + threadIdx.x;
    if (n >= 576) return;
    float s = 0.f;
    for (int j = 0; j < 192; j++) s += fus_b[j] * W_qkv[j * 576 + n];
    g_bfq[n] = s;
}

// ---------------- fp16 tensor-core GEMM: C = (Ah + addvec?) @ Wh^T (+ bias?) ----------------
__global__ void __launch_bounds__(256) hgemm_kernel(
    const __half* __restrict__ Ah, int woff, const float* __restrict__ bias,
    const float* __restrict__ addvec, float* __restrict__ C, int Ncol)
{
    __shared__ uint32_t sA[128][36];
    __shared__ uint32_t sB[64][36];
    int t = threadIdx.x;
    int wid = t >> 5, lane = t & 31;
    int wm = wid & 3, wn = wid >> 2;
    int g = lane >> 2, la3 = lane & 3;
    int row0 = blockIdx.y * 128, col0 = blockIdx.x * 64;
    const uint32_t* Whu = (const uint32_t*)(g_Wh + woff);
    const uint32_t* Au = (const uint32_t*)Ah;
    uint32_t sAb = (uint32_t)__cvta_generic_to_shared(&sA[0][0]);
    uint32_t sBb = (uint32_t)__cvta_generic_to_shared(&sB[0][0]);
    float acc[2][4][4] = {};
    for (int kp = 0; kp < 3; kp++) {
        int k0 = kp * 64;
        for (int u = t; u < 4096; u += 256) {
            int r = u >> 5, cu = u & 31;
            uint32_t v = Au[(long)(row0 + r) * 96 + (k0 >> 1) + cu];
            if (addvec) {
                float2 f = __half22float2(*(__half2*)&v);
                f.x += addvec[k0 + 2 * cu];
                f.y += addvec[k0 + 2 * cu + 1];
                v = pack_h2(f.x, f.y);
            }
            sA[r][cu] = v;
        }
        for (int u = t; u < 2048; u += 256) {
            int r = u >> 5, cu = u & 31;
            sB[r][cu] = Whu[(col0 + r) * 96 + (k0 >> 1) + cu];
        }
        __syncthreads();
#pragma unroll
        for (int ks = 0; ks < 4; ks++) {
            uint32_t afr[2][4], bfr[2][4];
#pragma unroll
            for (int mt = 0; mt < 2; mt++) {
                uint32_t addr = sAb + 4 * ((32 * wm + 16 * mt + (lane & 15)) * 36
                                           + ks * 8 + (lane >> 4) * 4);
                ldm_x4(afr[mt], addr);
            }
#pragma unroll
            for (int p = 0; p < 2; p++) {
                uint32_t addr = sBb + 4 * ((32 * wn + 16 * p + (lane >> 4) * 8 + (lane & 7)) * 36
                                           + ks * 8 + ((lane >> 3) & 1) * 4);
                ldm_x4(bfr[p], addr);
            }
#pragma unroll
            for (int nt = 0; nt < 4; nt++) {
                int p = nt >> 1, i0 = (nt & 1) * 2;
                mma_f16(acc[0][nt], afr[0], bfr[p][i0], bfr[p][i0 + 1]);
                mma_f16(acc[1][nt], afr[1], bfr[p][i0], bfr[p][i0 + 1]);
            }
        }
        __syncthreads();
    }
#pragma unroll
    for (int mt = 0; mt < 2; mt++) {
#pragma unroll
        for (int nt = 0; nt < 4; nt++) {
            int col = col0 + 32 * wn + 8 * nt + 2 * la3;
            float b0v = bias ? bias[col] : 0.f;
            float b1v = bias ? bias[col + 1] : 0.f;
            int r = row0 + 32 * wm + 16 * mt + g;
            *(float2*)&C[(long)r * Ncol + col] =
                make_float2(acc[mt][nt][0] + b0v, acc[mt][nt][1] + b1v);
            *(float2*)&C[(long)(r + 8) * Ncol + col] =
                make_float2(acc[mt][nt][2] + b0v, acc[mt][nt][3] + b1v);
        }
    }
}

// ---------------- A = knnxyz @ pos_W1 + pos_b1 via tf32 mma (K=48) ----------------
__global__ void __launch_bounds__(256) agemm_kernel(const float* __restrict__ pos_b1) {
    __shared__ uint32_t sA[128 * 50];
    __shared__ uint32_t sB[48 * 72];
    int t = threadIdx.x;
    int wid = t >> 5, lane = t & 31;
    int wm = wid & 3, wn = wid >> 2;
    int g = lane >> 2, la3 = lane & 3;
    int row0 = blockIdx.y * 128, col0 = blockIdx.x * 64;
    int m_blk = col0 / 192, cbase = col0 - m_blk * 192;

    for (int u = t; u < 128 * 48; u += 256) {
        int r = u / 48, k = u % 48;
        sA[r * 50 + k] = f2tf32(g_knnxyz[(long)(row0 + r) * 48 + k]);
    }
    for (int u = t; u < 48 * 64; u += 256) {
        int k = u >> 6, n = u & 63;
        sB[k * 72 + n] = g_W1t[k * 576 + col0 + n];
    }
    __syncthreads();

    float acc[2][4][4] = {};
#pragma unroll
    for (int ks = 0; ks < 6; ks++) {
        int ca = ks * 8 + la3;
        uint32_t afr[2][4];
#pragma unroll
        for (int mt = 0; mt < 2; mt++) {
            int r = 32 * wm + 16 * mt + g;
            afr[mt][0] = sA[r * 50 + ca];
            afr[mt][1] = sA[(r + 8) * 50 + ca];
            afr[mt][2] = sA[r * 50 + ca + 4];
            afr[mt][3] = sA[(r + 8) * 50 + ca + 4];
        }
#pragma unroll
        for (int nt = 0; nt < 4; nt++) {
            int nc = 32 * wn + 8 * nt + g;
            uint32_t b0 = sB[ca * 72 + nc];
            uint32_t b1 = sB[(ca + 4) * 72 + nc];
            mma_tf32(acc[0][nt], afr[0], b0, b1);
            mma_tf32(acc[1][nt], afr[1], b0, b1);
        }
    }
#pragma unroll
    for (int mt = 0; mt < 2; mt++) {
#pragma unroll
        for (int nt = 0; nt < 4; nt++) {
            int colL = 32 * wn + 8 * nt + 2 * la3;
            float b0v = pos_b1[col0 + colL], b1v = pos_b1[col0 + colL + 1];
            int r = row0 + 32 * wm + 16 * mt + g;
            *(float2*)&g_A[((long)m_blk * NPTS + r) * DIM + cbase + colL] =
                make_float2(acc[mt][nt][0] + b0v, acc[mt][nt][1] + b1v);
            *(float2*)&g_A[((long)m_blk * NPTS + r + 8) * DIM + cbase + colL] =
                make_float2(acc[mt][nt][2] + b0v, acc[mt][nt][3] + b1v);
        }
    }
}

// ---------------- per-node stage 1 ----------------
__global__ void __launch_bounds__(192) node1_kernel(
    const float* __restrict__ p, const float* __restrict__ x, const int* __restrict__ knn,
    const float* __restrict__ prop_W, const float* __restrict__ prop_b,
    const float* __restrict__ gA_W, const float* __restrict__ gA_b,
    const float* __restrict__ gB_W, const float* __restrict__ gB_b,
    const float* __restrict__ kn, const float* __restrict__ de_W1,
    const float* __restrict__ de_b1, const float* __restrict__ de_W2,
    const float* __restrict__ de_b2)
{
    int n = blockIdx.x;
    int c = threadIdx.x;
    __shared__ float s_p[3];
    __shared__ int   s_idx[NS];
    __shared__ float s_xyz[NS * 3];
    __shared__ float s_pr[NS * 3];
    __shared__ float s_dist[NS];
    __shared__ float s_rep[9];
    __shared__ float s_maxd;
    __shared__ float s_kd[KSP];
    __shared__ float s_g[KSP * DQ];
    __shared__ float s_sc[KSP];
    __shared__ float s_w[DQ];

    if (c < 3) s_p[c] = p[n * 3 + c];
    if (c < NS) s_idx[c] = knn[n * NS + c];
    __syncthreads();

    if (c < NS) {
        int id = s_idx[c];
        float ax = p[id * 3 + 0], ay = p[id * 3 + 1], az = p[id * 3 + 2];
        s_xyz[c * 3 + 0] = ax; s_xyz[c * 3 + 1] = ay; s_xyz[c * 3 + 2] = az;
        float rx = ax - s_p[0], ry = ay - s_p[1], rz = az - s_p[2];
        s_pr[c * 3 + 0] = rx; s_pr[c * 3 + 1] = ry; s_pr[c * 3 + 2] = rz;
        s_dist[c] = sqrtf(rx * rx + ry * ry + rz * rz + 1e-12f);
    }
    if (c >= 32 && c < 32 + KSP) {
        int s = c - 32;
        float dx = s_p[0] - kn[s * 3 + 0];
        float dy = s_p[1] - kn[s * 3 + 1];
        float dz = s_p[2] - kn[s * 3 + 2];
        s_kd[s] = sqrtf(dx * dx + dy * dy + dz * dz + 1e-12f);
    }
    __syncthreads();

    if (c == 0) {
        float mx = 0, my = 0, mz = 0, qx = 0, qy = 0, qz = 0, md = 0, sd = 0;
        for (int j = 0; j < NS; j++) {
            mx += s_pr[j * 3]; my += s_pr[j * 3 + 1]; mz += s_pr[j * 3 + 2];
            qx += s_xyz[j * 3]; qy += s_xyz[j * 3 + 1]; qz += s_xyz[j * 3 + 2];
            md = fmaxf(md, s_dist[j]); sd += s_dist[j];
        }
        const float inv = 1.f / NS;
        s_rep[0] = mx * inv; s_rep[1] = my * inv; s_rep[2] = mz * inv;
        s_rep[3] = qx * inv; s_rep[4] = qy * inv; s_rep[5] = qz * inv;
        s_rep[6] = s_p[0]; s_rep[7] = s_p[1]; s_rep[8] = s_p[2];
        s_maxd = md;
        g_distsum[n] = sd; g_distmax[n] = md;
        g_m3[n * 3 + 0] = qx; g_m3[n * 3 + 1] = qy; g_m3[n * 3 + 2] = qz;
    }
    if (c < NS * 3) g_knnxyz[n * 48 + c] = s_xyz[c];
    for (int idx = c; idx < KSP * DQ; idx += 192) {
        int s = idx / DQ, k = idx % DQ;
        s_g[idx] = fmaxf(s_kd[s] * de_W1[k] + de_b1[k], 0.f);
    }
    __syncthreads();

    if (c < KSP) {
        float l = g_kpconst;
        for (int k = 0; k < DQ; k++) l += s_g[c * DQ + k] * g_kpwproj[k];
        s_sc[c] = l;
    }
    __syncthreads();
    if (c == 0) {
        float mx = -1e30f;
        for (int s = 0; s < KSP; s++) mx = fmaxf(mx, s_sc[s]);
        float se = 0.f;
        for (int s = 0; s < KSP; s++) { float e = expf(s_sc[s] - mx); s_sc[s] = e; se += e; }
        float inv = 1.f / se;
        for (int s = 0; s < KSP; s++) s_sc[s] *= inv;
    }
    __syncthreads();
    if (c < DQ) {
        float w = 0.f;
        for (int s = 0; s < KSP; s++) w += s_sc[s] * s_g[s * DQ + c];
        s_w[c] = w;
    }
    __syncthreads();

    float dist_feat = de_b2[c];
#pragma unroll
    for (int k = 0; k < DQ; k++) dist_feat += s_w[k] * de_W2[k * DIM + c];

    float geo = gA_b[c] + gB_b[c] + s_maxd * gB_W[c];
#pragma unroll
    for (int i = 0; i < 9; i++) geo += s_rep[i] * gA_W[i * DIM + c];

    float w0 = prop_W[192 * DIM + c], w1 = prop_W[193 * DIM + c], w2 = prop_W[194 * DIM + c];
    float pb = prop_b[c];
    float msg = 0.f;
#pragma unroll
    for (int s = 0; s < NS; s++) {
        float v = g_xpw[(long)s_idx[s] * DIM + c]
                + s_pr[s * 3] * w0 + s_pr[s * 3 + 1] * w1 + s_pr[s * 3 + 2] * w2 + pb;
        msg += fmaxf(v, 0.f);
    }
    msg *= (1.f / NS);
    g_prefh[(long)n * DIM + c] = __float2half(x[(long)n * DIM + c] + msg + geo + dist_feat);
}

// ---------------- global reductions ----------------
__global__ void __launch_bounds__(256) reduce_kernel() {
    int tid = blockIdx.x * blockDim.x + threadIdx.x;
    int stride = gridDim.x * blockDim.x;
    double lsum = 0, l0 = 0, l1 = 0, l2 = 0;
    double m0 = 0, m1 = 0, m2 = 0, m3v = 0, m4 = 0, m5 = 0;
    float lmax = 0.f;
    for (int n = tid; n < NPTS; n += stride) {
        lsum += (double)g_distsum[n];
        lmax = fmaxf(lmax, g_distmax[n]);
        l0 += (double)g_m3[n * 3 + 0];
        l1 += (double)g_m3[n * 3 + 1];
        l2 += (double)g_m3[n * 3 + 2];
        for (int i = 0; i < NS; i++) {
            float xx = g_knnxyz[n * 48 + i * 3 + 0];
            float yy = g_knnxyz[n * 48 + i * 3 + 1];
            float zz = g_knnxyz[n * 48 + i * 3 + 2];
            m0 += (double)xx * xx; m1 += (double)xx * yy; m2 += (double)xx * zz;
            m3v += (double)yy * yy; m4 += (double)yy * zz; m5 += (double)zz * zz;
        }
    }
    __shared__ double sd[256];
    double vals[10] = {lsum, l0, l1, l2, m0, m1, m2, m3v, m4, m5};
    double* outs[10] = {&g_sumdist, &g_Sm3[0], &g_Sm3[1], &g_Sm3[2],
                        &g_SM33[0], &g_SM33[1], &g_SM33[2], &g_SM33[3], &g_SM33[4], &g_SM33[5]};
    for (int q = 0; q < 10; q++) {
        sd[threadIdx.x] = vals[q];
        __syncthreads();
        for (int s = 128; s > 0; s >>= 1) {
            if (threadIdx.x < s) sd[threadIdx.x] += sd[threadIdx.x + s];
            __syncthreads();
        }
        if (threadIdx.x == 0) atomicAdd(outs[q], sd[0]);
        __syncthreads();
    }
    sd[threadIdx.x] = (double)lmax;
    __syncthreads();
    for (int s = 128; s > 0; s >>= 1) {
        if (threadIdx.x < s) sd[threadIdx.x] = fmax(sd[threadIdx.x], sd[threadIdx.x + s]);
        __syncthreads();
    }
    if (threadIdx.x == 0) atomicMax(&g_maxbits, __float_as_int((float)sd[0]));
}

// ---------------- BN per-channel statistics (float chunks, double atomics) ----------------
#define BNCHUNK 256
__global__ void __launch_bounds__(192) bnstats_kernel() {
    int m = blockIdx.y;
    int n0 = blockIdx.x * BNCHUNK;
    int c = threadIdx.x;
    float sa = 0, sa2 = 0, sx = 0, sy = 0, sz = 0;
    const float* Abase = g_A + (long)m * NPTS * DIM;
    for (int n = n0; n < n0 + BNCHUNK; n++) {
        float a = Abase[(long)n * DIM + c];
        float mx = g_m3[n * 3 + 0], my = g_m3[n * 3 + 1], mz = g_m3[n * 3 + 2];
        sa += a;
        sa2 += a * a;
        sx += a * mx; sy += a * my; sz += a * mz;
    }
    double* d = g_ch + ((long)m * DIM + c) * 5;
    atomicAdd(d + 0, (double)sa); atomicAdd(d + 1, (double)sa2);
    atomicAdd(d + 2, (double)sx); atomicAdd(d + 3, (double)sy); atomicAdd(d + 4, (double)sz);
}

// ---------------- finalize: S, BN scale/shift, vol vector ----------------
__global__ void __launch_bounds__(192) finalize_kernel(
    const float* __restrict__ pos_W1, const float* __restrict__ pos_gamma,
    const float* __restrict__ pos_beta, const float* __restrict__ gC_W,
    const float* __restrict__ gC_b)
{
    int c = threadIdx.x;
    float Sv[3][3];
#pragma unroll
    for (int m = 0; m < 3; m++)
#pragma unroll
        for (int k = 0; k < 3; k++) {
            float s = 0.f;
            for (int j = 0; j < NS; j++) s += pos_W1[(long)m * 48 * DIM + (3 * j + k) * DIM + c];
            Sv[m][k] = s;
            g_S[(m * 3 + k) * DIM + c] = s;
        }
    const double T = (double)NPTS * NS;
    double Q0 = g_SM33[0], Q1 = g_SM33[1], Q2 = g_SM33[2], Q3 = g_SM33[3], Q4 = g_SM33[4], Q5 = g_SM33[5];
    double P0 = g_Sm3[0], P1 = g_Sm3[1], P2 = g_Sm3[2];
#pragma unroll
    for (int m = 0; m < 3; m++) {
        const double* d = g_ch + ((long)m * DIM + c) * 5;
        double SA = d[0], SA2 = d[1], SMx = d[2], SMy = d[3], SMz = d[4];
        double Sx = Sv[m][0], Sy = Sv[m][1], Sz = Sv[m][2];
        double mean = (16.0 * SA - (Sx * P0 + Sy * P1 + Sz * P2)) / T;
        double sq = 16.0 * SA2 - 2.0 * (Sx * SMx + Sy * SMy + Sz * SMz)
                  + Sx * Sx * Q0 + Sy * Sy * Q3 + Sz * Sz * Q5
                  + 2.0 * (Sx * Sy * Q1 + Sx * Sz * Q2 + Sy * Sz * Q4);
        double var = sq / T - mean * mean;
        float sc = pos_gamma[m * DIM + c] * rsqrtf((float)(var + 1e-5));
        g_bnscale[m * DIM + c] = sc;
        g_bnshift[m * DIM + c] = pos_beta[m * DIM + c] - (float)mean * sc;
    }
    float maxd = __int_as_float(g_maxbits);
    float vol = (float)(g_sumdist / T) / (maxd + 1e-8f);
    g_volvec[c] = vol * gC_W[c] + gC_b[c];
}

// ---------------- fused attention via mma.sync fp16 (ldmatrix A, LDG B frags) ----------------
#define SH_OFF    0          // 128 x 100 u32 = 51200
#define SQ_OFF    51200      // 6144
#define SK_OFF    57344      // 6144
#define SB2_OFF   63488      // 2304
#define SSC_OFF   65792      // 3072
#define SWT_OFF   68864      // 3072
#define SXYZ_OFF  71936      // 1536
#define SIDX_OFF  73472      // 512
#define SAH_OFF   73984      // 6144 (BN-folded A)
#define SSH_OFF   80128      // 2304 (BN-folded S)
#define ATT_SMEM  82432

__global__ void __launch_bounds__(512, 1) attn_mma_kernel(
    const int* __restrict__ knn, const float* __restrict__ pos_b2)
{
    extern __shared__ char smem[];
    const int t = threadIdx.x;
    const int wid = t >> 5, lane = t & 31;
    const int wm = wid & 3, wn = wid >> 2;
    const int g = lane >> 2, la3 = lane & 3;
    const int nb = blockIdx.x * 8;

    uint32_t* s_h  = (uint32_t*)(smem + SH_OFF);
    float* s_q   = (float*)(smem + SQ_OFF);
    float* s_k0  = (float*)(smem + SK_OFF);
    float* s_b2  = (float*)(smem + SB2_OFF);
    float* s_sc  = (float*)(smem + SSC_OFF);
    float* s_w   = (float*)(smem + SWT_OFF);
    float* s_xyz = (float*)(smem + SXYZ_OFF);
    int*   s_idx = (int*)(smem + SIDX_OFF);
    float* s_ahat = (float*)(smem + SAH_OFF);
    float* s_Sh   = (float*)(smem + SSH_OFF);
    const uint32_t shb = (uint32_t)__cvta_generic_to_shared(smem + SH_OFF);

    // ---- stage shared inputs ----
    for (int u = t; u < 128; u += 512) s_idx[u] = knn[(nb + (u >> 4)) * NS + (u & 15)];
    for (int u = t; u < 8 * 48; u += 512) s_xyz[u] = g_knnxyz[(long)nb * 48 + u];
    for (int u = t; u < 3 * DIM; u += 512) s_b2[u] = pos_b2[u];
    for (int u = t; u < 8 * DIM; u += 512) {
        int n = u / DIM, c = u % DIM;
        long r0 = (long)knn[(nb + n) * NS] * 576;
        s_q[u]  = g_qkv[r0 + c];
        s_k0[u] = g_qkv[r0 + 192 + c];
    }
    __syncthreads();

    // ---- base scores: q0.k_j + q0.b2[0] + k0.b2[1], per (n,h,j) ----
    for (int task = t; task < 768; task += 512) {
        int n = task / 96, h = (task / 16) % 6, j = task & 15;
        const float4* qv = (const float4*)(s_q + n * DIM + 32 * h);
        const float4* kv0 = (const float4*)(s_k0 + n * DIM + 32 * h);
        const float4* b0 = (const float4*)(s_b2 + 32 * h);
        const float4* b1 = (const float4*)(s_b2 + DIM + 32 * h);
        const float4* kj = (const float4*)(g_qkv + (long)s_idx[n * 16 + j] * 576 + 192 + 32 * h);
        float dot = 0.f;
#pragma unroll
        for (int u = 0; u < 8; u++) {
            float4 q4 = qv[u], k4 = kj[u], b04 = b0[u], b14 = b1[u], kk0 = kv0[u];
            dot += q4.x * (k4.x + b04.x) + q4.y * (k4.y + b04.y)
                 + q4.z * (k4.z + b04.z) + q4.w * (k4.w + b04.w);
            dot += kk0.x * b14.x + kk0.y * b14.y + kk0.z * b14.z + kk0.w * b14.w;
        }
        s_sc[(n * 6 + h) * 16 + j] = dot;
    }

    const int hb0 = (48 * wn) >> 5;
    const int grow = t >> 2;
    const int gn2 = grow >> 4, gj2 = grow & 15;

    for (int m = 0; m < 3; m++) {
        float acc[2][6][4];
#pragma unroll
        for (int a1 = 0; a1 < 2; a1++)
#pragma unroll
            for (int a2 = 0; a2 < 6; a2++)
#pragma unroll
                for (int a3 = 0; a3 < 4; a3++) acc[a1][a2][a3] = 0.f;

        __syncthreads();
        // ---- stage BN-folded A and S for this mat ----
        for (int u = t; u < 8 * DIM; u += 512) {
            int cg = u % DIM;
            float a = g_A[((long)m * NPTS + nb + (u / DIM)) * DIM + cg];
            s_ahat[u] = a * g_bnscale[m * DIM + cg] + g_bnshift[m * DIM + cg];
        }
        for (int u = t; u < 3 * DIM; u += 512) {
            int cg = u % DIM;
            s_Sh[u] = g_S[(m * 3 + u / DIM) * DIM + cg] * g_bnscale[m * DIM + cg];
        }
        __syncthreads();
        // ---- generate h (fp16 pairs) from SMEM-staged operands ----
        {
            float xx = s_xyz[gn2 * 48 + gj2 * 3 + 0];
            float yy = s_xyz[gn2 * 48 + gj2 * 3 + 1];
            float zz = s_xyz[gn2 * 48 + gj2 * 3 + 2];
            const float* ah = s_ahat + gn2 * DIM;
#pragma unroll
            for (int i = 0; i < 24; i++) {
                int cu = (t & 3) + 4 * i;
                int cg = 2 * cu;
                float2 a2 = *(const float2*)&ah[cg];
                float2 S0 = *(const float2*)&s_Sh[cg];
                float2 S1 = *(const float2*)&s_Sh[DIM + cg];
                float2 S2 = *(const float2*)&s_Sh[2 * DIM + cg];
                float h0 = a2.x - (xx * S0.x + yy * S1.x + zz * S2.x);
                float h1 = a2.y - (xx * S0.y + yy * S1.y + zz * S2.y);
                s_h[grow * 100 + cu] = pack_h2(fmaxf(h0, 0.f), fmaxf(h1, 0.f));
            }
        }
        __syncthreads();

        // ---- mma: K=192 in 12 k16-steps; A via ldmatrix, B frags via coalesced LDG ----
#pragma unroll
        for (int ks = 0; ks < 12; ks++) {
            const uint4* bq = (const uint4*)g_W2f + (((m * 4 + wn) * 12 + ks) * 3) * 32;
            uint4 u0 = bq[lane];
            uint4 u1 = bq[32 + lane];
            uint4 u2 = bq[64 + lane];
            uint32_t afr[2][4];
#pragma unroll
            for (int mt = 0; mt < 2; mt++) {
                uint32_t addr = shb + 4 * ((32 * wm + 16 * mt + (lane & 15)) * 100
                                           + ks * 8 + (lane >> 4) * 4);
                ldm_x4(afr[mt], addr);
            }
            mma_f16(acc[0][0], afr[0], u0.x, u0.y);
            mma_f16(acc[1][0], afr[1], u0.x, u0.y);
            mma_f16(acc[0][1], afr[0], u0.z, u0.w);
            mma_f16(acc[1][1], afr[1], u0.z, u0.w);
            mma_f16(acc[0][2], afr[0], u1.x, u1.y);
            mma_f16(acc[1][2], afr[1], u1.x, u1.y);
            mma_f16(acc[0][3], afr[0], u1.z, u1.w);
            mma_f16(acc[1][3], afr[1], u1.z, u1.w);
            mma_f16(acc[0][4], afr[0], u2.x, u2.y);
            mma_f16(acc[1][4], afr[1], u2.x, u2.y);
            mma_f16(acc[0][5], afr[0], u2.z, u2.w);
            mma_f16(acc[1][5], afr[1], u2.z, u2.w);
        }

        // ---- epilogue for mat m ----
        if (m < 2) {
            const float* base = (m == 0) ? s_q : s_k0;
            float part[8];
#pragma unroll
            for (int u = 0; u < 8; u++) part[u] = 0.f;
#pragma unroll
            for (int mt = 0; mt < 2; mt++) {
                const float* bp = base + (2 * wm + mt) * DIM;
#pragma unroll
                for (int nt = 0; nt < 6; nt++) {
                    int c0 = 48 * wn + 8 * nt + 2 * la3;
                    int bkt = ((48 * wn + 8 * nt) >> 5) - hb0;
                    float q0v = bp[c0], q1v = bp[c0 + 1];
                    part[mt * 4 + 0 * 2 + bkt] += acc[mt][nt][0] * q0v + acc[mt][nt][1] * q1v;
                    part[mt * 4 + 1 * 2 + bkt] += acc[mt][nt][2] * q0v + acc[mt][nt][3] * q1v;
                }
            }
#pragma unroll
            for (int u = 0; u < 8; u++) {
                part[u] += __shfl_xor_sync(0xffffffffu, part[u], 1);
                part[u] += __shfl_xor_sync(0xffffffffu, part[u], 2);
            }
            if (la3 == 0) {
                int j0 = g;
#pragma unroll
                for (int mt = 0; mt < 2; mt++)
#pragma unroll
                    for (int rb = 0; rb < 2; rb++)
#pragma unroll
                        for (int bkt = 0; bkt < 2; bkt++) {
                            int h = hb0 + bkt;
                            atomicAdd(&s_sc[((2 * wm + mt) * 6 + h) * 16 + j0 + 8 * rb],
                                      part[mt * 4 + rb * 2 + bkt]);
                        }
            }
            if (m == 1) {
                __syncthreads();
                if (t < 48) {
                    const float scale = 0.17677669529663687f;  // 32^-0.5
                    float* sc = s_sc + t * 16;
                    float mx = -1e30f;
#pragma unroll
                    for (int j = 0; j < 16; j++) mx = fmaxf(mx, sc[j]);
                    float se = 0.f;
                    float ev[16];
#pragma unroll
                    for (int j = 0; j < 16; j++) { ev[j] = expf((sc[j] - mx) * scale); se += ev[j]; }
                    float inv = 1.f / se;
#pragma unroll
                    for (int j = 0; j < 16; j++) s_w[t * 16 + j] = ev[j] * inv;
                }
                __syncthreads();
            }
        } else {
#pragma unroll
            for (int mt = 0; mt < 2; mt++) {
                int node = 2 * wm + mt;
                int j0 = g;
                long v0b = (long)s_idx[node * 16 + j0] * 576 + 384;
                long v1b = (long)s_idx[node * 16 + j0 + 8] * 576 + 384;
#pragma unroll
                for (int nt = 0; nt < 6; nt++) {
                    int c0 = 48 * wn + 8 * nt + 2 * la3;
                    int h = c0 >> 5;
                    float w0 = s_w[(node * 6 + h) * 16 + j0];
                    float w1 = s_w[(node * 6 + h) * 16 + j0 + 8];
                    float b20 = s_b2[2 * DIM + c0], b21 = s_b2[2 * DIM + c0 + 1];
                    float o0 = w0 * (acc[mt][nt][0] + g_qkv[v0b + c0] + b20)
                             + w1 * (acc[mt][nt][2] + g_qkv[v1b + c0] + b20);
                    float o1 = w0 * (acc[mt][nt][1] + g_qkv[v0b + c0 + 1] + b21)
                             + w1 * (acc[mt][nt][3] + g_qkv[v1b + c0 + 1] + b21);
#pragma unroll
                    for (int o = 4; o < 32; o <<= 1) {
                        o0 += __shfl_xor_sync(0xffffffffu, o0, o);
                        o1 += __shfl_xor_sync(0xffffffffu, o1, o);
                    }
                    if (g == 0) {
                        *(uint32_t*)(g_atth + (long)(nb + node) * DIM + c0) = pack_h2(o0, o1);
                    }
                }
            }
        }
    }
}

// ---------------- host launcher ----------------
extern "C" void kernel_launch(void* const* d_in, const int* in_sizes, int n_in,
                              void* d_out, int out_size)
{
    const float* p      = (const float*)d_in[0];
    const float* x      = (const float*)d_in[1];
    const int*   knn    = (const int*)d_in[2];
    const float* W_qkv  = (const float*)d_in[3];
    const float* W_proj = (const float*)d_in[4];
    const float* b_proj = (const float*)d_in[5];
    const float* prop_W = (const float*)d_in[6];
    const float* prop_b = (const float*)d_in[7];
    const float* gA_W   = (const float*)d_in[8];
    const float* gA_b   = (const float*)d_in[9];
    const float* gB_W   = (const float*)d_in[10];
    const float* gB_b   = (const float*)d_in[11];
    const float* gC_W   = (const float*)d_in[12];
    const float* gC_b   = (const float*)d_in[13];
    const float* pos_W1 = (const float*)d_in[14];
    const float* pos_b1 = (const float*)d_in[15];
    const float* pos_gamma = (const float*)d_in[16];
    const float* pos_beta  = (const float*)d_in[17];
    const float* pos_W2 = (const float*)d_in[18];
    const float* pos_b2 = (const float*)d_in[19];
    const float* kn     = (const float*)d_in[20];
    const float* de_W1  = (const float*)d_in[21];
    const float* de_b1  = (const float*)d_in[22];
    const float* de_W2  = (const float*)d_in[23];
    const float* de_b2  = (const float*)d_in[24];
    const float* kp_W   = (const float*)d_in[25];
    const float* kp_b   = (const float*)d_in[26];
    const float* fus_W  = (const float*)d_in[27];
    const float* fus_b  = (const float*)d_in[28];
    float* out = (float*)d_out;

    float *xpw, *qkv, *volvec, *bfq;
    __half *xh, *prefh, *atth;
    cudaGetSymbolAddress((void**)&xpw, g_xpw);
    cudaGetSymbolAddress((void**)&qkv, g_qkv);
    cudaGetSymbolAddress((void**)&volvec, g_volvec);
    cudaGetSymbolAddress((void**)&bfq, g_bfq);
    cudaGetSymbolAddress((void**)&xh, g_xh);
    cudaGetSymbolAddress((void**)&prefh, g_prefh);
    cudaGetSymbolAddress((void**)&atth, g_atth);

    cudaFuncSetAttribute(attn_mma_kernel, cudaFuncAttributeMaxDynamicSharedMemorySize, ATT_SMEM);

    prep_kernel<<<512, 256>>>(prop_W, W_proj, pos_W1, x);
    pre_kernel<<<1, 64>>>(de_W2, de_b2, kp_W, kp_b);
    w2f_kernel<<<864, 256>>>(pos_W2);
    wfq_kernel<<<432, 256>>>(fus_W, W_qkv);
    bfq_kernel<<<3, 192>>>(fus_b, W_qkv);
    hgemm_kernel<<<dim3(3, 128), 256>>>(xh, OFF_PROP, nullptr, nullptr, xpw, 192);
    node1_kernel<<<NPTS, 192>>>(p, x, knn, prop_W, prop_b, gA_W, gA_b, gB_W, gB_b,
                                kn, de_W1, de_b1, de_W2, de_b2);
    agemm_kernel<<<dim3(9, 128), 256>>>(pos_b1);
    reduce_kernel<<<64, 256>>>();
    bnstats_kernel<<<dim3(NPTS / BNCHUNK, 3), 192>>>();
    finalize_kernel<<<1, 192>>>(pos_W1, pos_gamma, pos_beta, gC_W, gC_b);
    hgemm_kernel<<<dim3(9, 128), 256>>>(prefh, OFF_QKV, bfq, volvec, qkv, 576);
    attn_mma_kernel<<<NPTS / 8, 512, ATT_SMEM>>>(knn, pos_b2);
    hgemm_kernel<<<dim3(3, 128), 256>>>(atth, OFF_PROJ, b_proj, nullptr, out, 192);
}

// round 8
// speedup vs baseline: 3.8473x; 1.0441x over previous
#include <cuda_runtime.h>
#include <cuda_fp16.h>
#include <math.h>
#include <stdint.h>

#define NPTS 16384
#define DIM  192
#define NS   16
#define NH   6
#define HD   32
#define KSP  16
#define DQ   48

// ---------------- scratch (device globals; no allocs allowed) ----------------
__device__ float g_xpw[NPTS * DIM];
__device__ float g_qkv[NPTS * 576];
__device__ float g_A[3L * NPTS * DIM];
__device__ float g_knnxyz[NPTS * 48];
__device__ float g_m3[NPTS * 3];
__device__ float g_distsum[NPTS];
__device__ float g_distmax[NPTS];
__device__ double g_ch[3 * DIM * 5];
__device__ double g_Sm3[3];
__device__ double g_SM33[6];
__device__ double g_sumdist;
__device__ int    g_maxbits;
__device__ float g_S[9 * DIM];
__device__ float g_bnscale[3 * DIM];
__device__ float g_bnshift[3 * DIM];
__device__ float g_volvec[DIM];
__device__ float g_kpwproj[DQ];
__device__ float g_kpconst;
__device__ __half g_Wh[184320];            // dense weights as half, [n][k=192]
__device__ uint32_t g_W1t[48 * 576];       // pos_W1 as tf32 bits, [k][m*192+c]
__device__ float g_bfq[576];               // fus_b @ W_qkv
__device__ uint32_t g_W2f[221184];         // pos_W2 fp16 mma fragments
__device__ __half g_xh[NPTS * DIM];        // x as half
__device__ __half g_prefh[NPTS * DIM];     // prefus as half
__device__ __half g_atth[NPTS * DIM];      // attn out as half

#define OFF_PROP 0
#define OFF_QKV  36864
#define OFF_PROJ 147456

// mma.sync m16n8k16 f16 with f32 accum (baseline PTX)
__device__ __forceinline__ void mma_f16(float* c, const uint32_t* a, uint32_t b0, uint32_t b1) {
    asm volatile("mma.sync.aligned.m16n8k16.row.col.f32.f16.f16.f32 "
        "{%0,%1,%2,%3}, {%4,%5,%6,%7}, {%8,%9}, {%0,%1,%2,%3};"
        : "+f"(c[0]), "+f"(c[1]), "+f"(c[2]), "+f"(c[3])
        : "r"(a[0]), "r"(a[1]), "r"(a[2]), "r"(a[3]), "r"(b0), "r"(b1));
}
// mma.sync m16n8k8 tf32
__device__ __forceinline__ void mma_tf32(float* c, const uint32_t* a, uint32_t b0, uint32_t b1) {
    asm volatile("mma.sync.aligned.m16n8k8.row.col.f32.tf32.tf32.f32 "
        "{%0,%1,%2,%3}, {%4,%5,%6,%7}, {%8,%9}, {%0,%1,%2,%3};"
        : "+f"(c[0]), "+f"(c[1]), "+f"(c[2]), "+f"(c[3])
        : "r"(a[0]), "r"(a[1]), "r"(a[2]), "r"(a[3]), "r"(b0), "r"(b1));
}
__device__ __forceinline__ void ldm_x4(uint32_t* d, uint32_t a) {
    asm volatile("ldmatrix.sync.aligned.m8n8.x4.shared.b16 {%0,%1,%2,%3}, [%4];"
        : "=r"(d[0]), "=r"(d[1]), "=r"(d[2]), "=r"(d[3]) : "r"(a));
}
__device__ __forceinline__ uint32_t pack_h2(float a, float b) {
    __half2 h = __floats2half2_rn(a, b);
    return *(uint32_t*)&h;
}
__device__ __forceinline__ uint32_t f2tf32(float f) {
    uint32_t r;
    asm("cvt.rna.tf32.f32 %0, %1;" : "=r"(r) : "f"(f));
    return r;
}
__device__ __forceinline__ double dwarpsum(double v) {
#pragma unroll
    for (int o = 16; o > 0; o >>= 1) v += __shfl_xor_sync(0xffffffffu, v, o);
    return v;
}

// ---------------- merged prep: zeros + weight converts + x->half ----------------
__global__ void __launch_bounds__(256) prep_kernel(
    const float* __restrict__ prop_W, const float* __restrict__ W_proj,
    const float* __restrict__ pos_W1, const float* __restrict__ x)
{
    int gid = blockIdx.x * 256 + threadIdx.x;
    int stride = gridDim.x * 256;
    for (int i = gid; i < 3 * DIM * 5; i += stride) g_ch[i] = 0.0;
    if (gid < 3) g_Sm3[gid] = 0.0;
    if (gid < 6) g_SM33[gid] = 0.0;
    if (gid == 0) { g_sumdist = 0.0; g_maxbits = 0; }
    for (int i = gid; i < 192 * 192; i += stride) {
        int k = i / 192, n = i % 192;
        g_Wh[OFF_PROP + n * 192 + k] = __float2half(prop_W[i]);
        g_Wh[OFF_PROJ + n * 192 + k] = __float2half(W_proj[i]);
    }
    for (int i = gid; i < 48 * 576; i += stride) {
        int k = i / 576, n = i % 576;
        int m = n / 192, c = n % 192;
        g_W1t[i] = f2tf32(pos_W1[((long)m * 48 + k) * 192 + c]);
    }
    for (int i = gid; i < NPTS * DIM / 2; i += stride) {
        float2 v = ((const float2*)x)[i];
        ((uint32_t*)g_xh)[i] = pack_h2(v.x, v.y);
    }
}

// ---------------- tiny precompute: de_W2 @ kp_W ----------------
__global__ void pre_kernel(const float* __restrict__ de_W2, const float* __restrict__ de_b2,
                           const float* __restrict__ kp_W, const float* __restrict__ kp_b) {
    int t = threadIdx.x;
    if (t < DQ) {
        float s = 0.f;
        for (int c = 0; c < DIM; c++) s += de_W2[t * DIM + c] * kp_W[c];
        g_kpwproj[t] = s;
    }
    if (t == 63) {
        float s = 0.f;
        for (int c = 0; c < DIM; c++) s += de_b2[c] * kp_W[c];
        g_kpconst = s + kp_b[0];
    }
}

// ---------------- pos_W2 -> per-(mat,wn,lane) mma fragment buffer ----------------
__global__ void __launch_bounds__(256) w2f_kernel(const float* __restrict__ pos_W2) {
    int gid = blockIdx.x * 256 + threadIdx.x;
    if (gid >= 221184) return;
    int e = gid & 3;
    int r = gid >> 2;
    int lane = r & 31; r >>= 5;
    int qq = r % 3; r /= 3;
    int ks = r % 12; r /= 12;
    int wn = r & 3;
    int m = r >> 2;
    int q = qq * 4 + e;
    int nt = q >> 1, ib = q & 1;
    int g = lane >> 2, la3 = lane & 3;
    int nr = 48 * wn + 8 * nt + g;
    int o = ks * 8 + la3 + 4 * ib;
    g_W2f[gid] = pack_h2(pos_W2[((long)m * DIM + 2 * o) * DIM + nr],
                         pos_W2[((long)m * DIM + 2 * o + 1) * DIM + nr]);
}

// ---------------- Wfq = fus_W @ W_qkv : tiled smem GEMM, half output [n][k] ----------------
__global__ void __launch_bounds__(256) wfq_kernel(const float* __restrict__ fus_W,
                                                  const float* __restrict__ W_qkv) {
    __shared__ float As[16][65];
    __shared__ float Bs[16][65];
    int t = threadIdx.x;
    int row0 = blockIdx.y * 64;       // kin
    int col0 = blockIdx.x * 64;       // n
    int mb = (t / 16) * 4;
    int nb = (t % 16) * 4;
    int a_k = t % 16, a_m = t / 16;
    int b_n = t % 64, b_k = t / 64;
    float acc[4][4] = {};
    for (int k0 = 0; k0 < 192; k0 += 16) {
#pragma unroll
        for (int p = 0; p < 4; p++) {
            int m = a_m + p * 16;
            As[a_k][m] = fus_W[(row0 + m) * 192 + k0 + a_k];
        }
#pragma unroll
        for (int p = 0; p < 4; p++) {
            int kk = b_k + p * 4;
            Bs[kk][b_n] = W_qkv[(k0 + kk) * 576 + col0 + b_n];
        }
        __syncthreads();
#pragma unroll
        for (int kk = 0; kk < 16; kk++) {
            float a[4], b[4];
#pragma unroll
            for (int i = 0; i < 4; i++) a[i] = As[kk][mb + i];
#pragma unroll
            for (int j = 0; j < 4; j++) b[j] = Bs[kk][nb + j];
#pragma unroll
            for (int i = 0; i < 4; i++)
#pragma unroll
                for (int j = 0; j < 4; j++)
                    acc[i][j] += a[i] * b[j];
        }
        __syncthreads();
    }
#pragma unroll
    for (int i = 0; i < 4; i++)
#pragma unroll
        for (int j = 0; j < 4; j++)
            g_Wh[OFF_QKV + (col0 + nb + j) * 192 + row0 + mb + i] = __float2half(acc[i][j]);
}

__global__ void bfq_kernel(const float* __restrict__ fus_b, const float* __restrict__ W_qkv) {
    int n = blockIdx.x * 192 + threadIdx.x;
    if (n >= 576) return;
    float s = 0.f;
    for (int j = 0; j < 192; j++) s += fus_b[j] * W_qkv[j * 576 + n];
    g_bfq[n] = s;
}

// ---------------- fp16 tensor-core GEMM: C = (Ah + addvec?) @ Wh^T (+ bias?) ----------------
__global__ void __launch_bounds__(256) hgemm_kernel(
    const __half* __restrict__ Ah, int woff, const float* __restrict__ bias,
    const float* __restrict__ addvec, float* __restrict__ C, int Ncol)
{
    __shared__ uint32_t sA[128][36];
    __shared__ uint32_t sB[64][36];
    int t = threadIdx.x;
    int wid = t >> 5, lane = t & 31;
    int wm = wid & 3, wn = wid >> 2;
    int g = lane >> 2, la3 = lane & 3;
    int row0 = blockIdx.y * 128, col0 = blockIdx.x * 64;
    const uint32_t* Whu = (const uint32_t*)(g_Wh + woff);
    const uint32_t* Au = (const uint32_t*)Ah;
    uint32_t sAb = (uint32_t)__cvta_generic_to_shared(&sA[0][0]);
    uint32_t sBb = (uint32_t)__cvta_generic_to_shared(&sB[0][0]);
    float acc[2][4][4] = {};
    for (int kp = 0; kp < 3; kp++) {
        int k0 = kp * 64;
        for (int u = t; u < 4096; u += 256) {
            int r = u >> 5, cu = u & 31;
            uint32_t v = Au[(long)(row0 + r) * 96 + (k0 >> 1) + cu];
            if (addvec) {
                float2 f = __half22float2(*(__half2*)&v);
                f.x += addvec[k0 + 2 * cu];
                f.y += addvec[k0 + 2 * cu + 1];
                v = pack_h2(f.x, f.y);
            }
            sA[r][cu] = v;
        }
        for (int u = t; u < 2048; u += 256) {
            int r = u >> 5, cu = u & 31;
            sB[r][cu] = Whu[(col0 + r) * 96 + (k0 >> 1) + cu];
        }
        __syncthreads();
#pragma unroll
        for (int ks = 0; ks < 4; ks++) {
            uint32_t afr[2][4], bfr[2][4];
#pragma unroll
            for (int mt = 0; mt < 2; mt++) {
                uint32_t addr = sAb + 4 * ((32 * wm + 16 * mt + (lane & 15)) * 36
                                           + ks * 8 + (lane >> 4) * 4);
                ldm_x4(afr[mt], addr);
            }
#pragma unroll
            for (int p = 0; p < 2; p++) {
                uint32_t addr = sBb + 4 * ((32 * wn + 16 * p + (lane >> 4) * 8 + (lane & 7)) * 36
                                           + ks * 8 + ((lane >> 3) & 1) * 4);
                ldm_x4(bfr[p], addr);
            }
#pragma unroll
            for (int nt = 0; nt < 4; nt++) {
                int p = nt >> 1, i0 = (nt & 1) * 2;
                mma_f16(acc[0][nt], afr[0], bfr[p][i0], bfr[p][i0 + 1]);
                mma_f16(acc[1][nt], afr[1], bfr[p][i0], bfr[p][i0 + 1]);
            }
        }
        __syncthreads();
    }
#pragma unroll
    for (int mt = 0; mt < 2; mt++) {
#pragma unroll
        for (int nt = 0; nt < 4; nt++) {
            int col = col0 + 32 * wn + 8 * nt + 2 * la3;
            float b0v = bias ? bias[col] : 0.f;
            float b1v = bias ? bias[col + 1] : 0.f;
            int r = row0 + 32 * wm + 16 * mt + g;
            *(float2*)&C[(long)r * Ncol + col] =
                make_float2(acc[mt][nt][0] + b0v, acc[mt][nt][1] + b1v);
            *(float2*)&C[(long)(r + 8) * Ncol + col] =
                make_float2(acc[mt][nt][2] + b0v, acc[mt][nt][3] + b1v);
        }
    }
}

// ---------------- A = knnxyz @ pos_W1 + pos_b1 via tf32 mma (K=48) ----------------
__global__ void __launch_bounds__(256) agemm_kernel(const float* __restrict__ pos_b1) {
    __shared__ uint32_t sA[128 * 50];
    __shared__ uint32_t sB[48 * 72];
    int t = threadIdx.x;
    int wid = t >> 5, lane = t & 31;
    int wm = wid & 3, wn = wid >> 2;
    int g = lane >> 2, la3 = lane & 3;
    int row0 = blockIdx.y * 128, col0 = blockIdx.x * 64;
    int m_blk = col0 / 192, cbase = col0 - m_blk * 192;

    for (int u = t; u < 128 * 48; u += 256) {
        int r = u / 48, k = u % 48;
        sA[r * 50 + k] = f2tf32(g_knnxyz[(long)(row0 + r) * 48 + k]);
    }
    for (int u = t; u < 48 * 64; u += 256) {
        int k = u >> 6, n = u & 63;
        sB[k * 72 + n] = g_W1t[k * 576 + col0 + n];
    }
    __syncthreads();

    float acc[2][4][4] = {};
#pragma unroll
    for (int ks = 0; ks < 6; ks++) {
        int ca = ks * 8 + la3;
        uint32_t afr[2][4];
#pragma unroll
        for (int mt = 0; mt < 2; mt++) {
            int r = 32 * wm + 16 * mt + g;
            afr[mt][0] = sA[r * 50 + ca];
            afr[mt][1] = sA[(r + 8) * 50 + ca];
            afr[mt][2] = sA[r * 50 + ca + 4];
            afr[mt][3] = sA[(r + 8) * 50 + ca + 4];
        }
#pragma unroll
        for (int nt = 0; nt < 4; nt++) {
            int nc = 32 * wn + 8 * nt + g;
            uint32_t b0 = sB[ca * 72 + nc];
            uint32_t b1 = sB[(ca + 4) * 72 + nc];
            mma_tf32(acc[0][nt], afr[0], b0, b1);
            mma_tf32(acc[1][nt], afr[1], b0, b1);
        }
    }
#pragma unroll
    for (int mt = 0; mt < 2; mt++) {
#pragma unroll
        for (int nt = 0; nt < 4; nt++) {
            int colL = 32 * wn + 8 * nt + 2 * la3;
            float b0v = pos_b1[col0 + colL], b1v = pos_b1[col0 + colL + 1];
            int r = row0 + 32 * wm + 16 * mt + g;
            *(float2*)&g_A[((long)m_blk * NPTS + r) * DIM + cbase + colL] =
                make_float2(acc[mt][nt][0] + b0v, acc[mt][nt][1] + b1v);
            *(float2*)&g_A[((long)m_blk * NPTS + r + 8) * DIM + cbase + colL] =
                make_float2(acc[mt][nt][2] + b0v, acc[mt][nt][3] + b1v);
        }
    }
}

// ---------------- per-node stage 1 ----------------
__global__ void __launch_bounds__(192) node1_kernel(
    const float* __restrict__ p, const float* __restrict__ x, const int* __restrict__ knn,
    const float* __restrict__ prop_W, const float* __restrict__ prop_b,
    const float* __restrict__ gA_W, const float* __restrict__ gA_b,
    const float* __restrict__ gB_W, const float* __restrict__ gB_b,
    const float* __restrict__ kn, const float* __restrict__ de_W1,
    const float* __restrict__ de_b1, const float* __restrict__ de_W2,
    const float* __restrict__ de_b2)
{
    int n = blockIdx.x;
    int c = threadIdx.x;
    __shared__ float s_p[3];
    __shared__ int   s_idx[NS];
    __shared__ float s_xyz[NS * 3];
    __shared__ float s_pr[NS * 3];
    __shared__ float s_dist[NS];
    __shared__ float s_rep[9];
    __shared__ float s_maxd;
    __shared__ float s_kd[KSP];
    __shared__ float s_g[KSP * DQ];
    __shared__ float s_sc[KSP];
    __shared__ float s_w[DQ];

    if (c < 3) s_p[c] = p[n * 3 + c];
    if (c < NS) s_idx[c] = knn[n * NS + c];
    __syncthreads();

    if (c < NS) {
        int id = s_idx[c];
        float ax = p[id * 3 + 0], ay = p[id * 3 + 1], az = p[id * 3 + 2];
        s_xyz[c * 3 + 0] = ax; s_xyz[c * 3 + 1] = ay; s_xyz[c * 3 + 2] = az;
        float rx = ax - s_p[0], ry = ay - s_p[1], rz = az - s_p[2];
        s_pr[c * 3 + 0] = rx; s_pr[c * 3 + 1] = ry; s_pr[c * 3 + 2] = rz;
        s_dist[c] = sqrtf(rx * rx + ry * ry + rz * rz + 1e-12f);
    }
    if (c >= 32 && c < 32 + KSP) {
        int s = c - 32;
        float dx = s_p[0] - kn[s * 3 + 0];
        float dy = s_p[1] - kn[s * 3 + 1];
        float dz = s_p[2] - kn[s * 3 + 2];
        s_kd[s] = sqrtf(dx * dx + dy * dy + dz * dz + 1e-12f);
    }
    __syncthreads();

    if (c == 0) {
        float mx = 0, my = 0, mz = 0, qx = 0, qy = 0, qz = 0, md = 0, sd = 0;
        for (int j = 0; j < NS; j++) {
            mx += s_pr[j * 3]; my += s_pr[j * 3 + 1]; mz += s_pr[j * 3 + 2];
            qx += s_xyz[j * 3]; qy += s_xyz[j * 3 + 1]; qz += s_xyz[j * 3 + 2];
            md = fmaxf(md, s_dist[j]); sd += s_dist[j];
        }
        const float inv = 1.f / NS;
        s_rep[0] = mx * inv; s_rep[1] = my * inv; s_rep[2] = mz * inv;
        s_rep[3] = qx * inv; s_rep[4] = qy * inv; s_rep[5] = qz * inv;
        s_rep[6] = s_p[0]; s_rep[7] = s_p[1]; s_rep[8] = s_p[2];
        s_maxd = md;
        g_distsum[n] = sd; g_distmax[n] = md;
        g_m3[n * 3 + 0] = qx; g_m3[n * 3 + 1] = qy; g_m3[n * 3 + 2] = qz;
    }
    if (c < NS * 3) g_knnxyz[n * 48 + c] = s_xyz[c];
    for (int idx = c; idx < KSP * DQ; idx += 192) {
        int s = idx / DQ, k = idx % DQ;
        s_g[idx] = fmaxf(s_kd[s] * de_W1[k] + de_b1[k], 0.f);
    }
    __syncthreads();

    if (c < KSP) {
        float l = g_kpconst;
        for (int k = 0; k < DQ; k++) l += s_g[c * DQ + k] * g_kpwproj[k];
        s_sc[c] = l;
    }
    __syncthreads();
    if (c == 0) {
        float mx = -1e30f;
        for (int s = 0; s < KSP; s++) mx = fmaxf(mx, s_sc[s]);
        float se = 0.f;
        for (int s = 0; s < KSP; s++) { float e = expf(s_sc[s] - mx); s_sc[s] = e; se += e; }
        float inv = 1.f / se;
        for (int s = 0; s < KSP; s++) s_sc[s] *= inv;
    }
    __syncthreads();
    if (c < DQ) {
        float w = 0.f;
        for (int s = 0; s < KSP; s++) w += s_sc[s] * s_g[s * DQ + c];
        s_w[c] = w;
    }
    __syncthreads();

    float dist_feat = de_b2[c];
#pragma unroll
    for (int k = 0; k < DQ; k++) dist_feat += s_w[k] * de_W2[k * DIM + c];

    float geo = gA_b[c] + gB_b[c] + s_maxd * gB_W[c];
#pragma unroll
    for (int i = 0; i < 9; i++) geo += s_rep[i] * gA_W[i * DIM + c];

    float w0 = prop_W[192 * DIM + c], w1 = prop_W[193 * DIM + c], w2 = prop_W[194 * DIM + c];
    float pb = prop_b[c];
    float msg = 0.f;
#pragma unroll
    for (int s = 0; s < NS; s++) {
        float v = g_xpw[(long)s_idx[s] * DIM + c]
                + s_pr[s * 3] * w0 + s_pr[s * 3 + 1] * w1 + s_pr[s * 3 + 2] * w2 + pb;
        msg += fmaxf(v, 0.f);
    }
    msg *= (1.f / NS);
    g_prefh[(long)n * DIM + c] = __float2half(x[(long)n * DIM + c] + msg + geo + dist_feat);
}

// ---------------- global reductions (coalesced, warp shuffles) ----------------
__global__ void __launch_bounds__(256) reduce_kernel() {
    int tid = blockIdx.x * blockDim.x + threadIdx.x;
    int stride = gridDim.x * blockDim.x;
    double lsum = 0, l0 = 0, l1 = 0, l2 = 0;
    float lmax = 0.f;
    for (int n = tid; n < NPTS; n += stride) {
        lsum += (double)g_distsum[n];
        lmax = fmaxf(lmax, g_distmax[n]);
        l0 += (double)g_m3[n * 3 + 0];
        l1 += (double)g_m3[n * 3 + 1];
        l2 += (double)g_m3[n * 3 + 2];
    }
    double m0 = 0, m1 = 0, m2 = 0, m3v = 0, m4 = 0, m5 = 0;
    for (int idx = tid; idx < NPTS * NS; idx += stride) {
        float xx = g_knnxyz[idx * 3 + 0];
        float yy = g_knnxyz[idx * 3 + 1];
        float zz = g_knnxyz[idx * 3 + 2];
        m0 += (double)xx * xx; m1 += (double)xx * yy; m2 += (double)xx * zz;
        m3v += (double)yy * yy; m4 += (double)yy * zz; m5 += (double)zz * zz;
    }
    lsum = dwarpsum(lsum); l0 = dwarpsum(l0); l1 = dwarpsum(l1); l2 = dwarpsum(l2);
    m0 = dwarpsum(m0); m1 = dwarpsum(m1); m2 = dwarpsum(m2);
    m3v = dwarpsum(m3v); m4 = dwarpsum(m4); m5 = dwarpsum(m5);
#pragma unroll
    for (int o = 16; o > 0; o >>= 1) lmax = fmaxf(lmax, __shfl_xor_sync(0xffffffffu, lmax, o));
    if ((threadIdx.x & 31) == 0) {
        atomicAdd(&g_sumdist, lsum);
        atomicAdd(&g_Sm3[0], l0); atomicAdd(&g_Sm3[1], l1); atomicAdd(&g_Sm3[2], l2);
        atomicAdd(&g_SM33[0], m0); atomicAdd(&g_SM33[1], m1); atomicAdd(&g_SM33[2], m2);
        atomicAdd(&g_SM33[3], m3v); atomicAdd(&g_SM33[4], m4); atomicAdd(&g_SM33[5], m5);
        atomicMax(&g_maxbits, __float_as_int(lmax));
    }
}

// ---------------- BN per-channel statistics (float chunks, double atomics) ----------------
#define BNCHUNK 64
__global__ void __launch_bounds__(192) bnstats_kernel() {
    int m = blockIdx.y;
    int n0 = blockIdx.x * BNCHUNK;
    int c = threadIdx.x;
    float sa = 0, sa2 = 0, sx = 0, sy = 0, sz = 0;
    const float* Abase = g_A + (long)m * NPTS * DIM;
    for (int n = n0; n < n0 + BNCHUNK; n++) {
        float a = Abase[(long)n * DIM + c];
        float mx = g_m3[n * 3 + 0], my = g_m3[n * 3 + 1], mz = g_m3[n * 3 + 2];
        sa += a;
        sa2 += a * a;
        sx += a * mx; sy += a * my; sz += a * mz;
    }
    double* d = g_ch + ((long)m * DIM + c) * 5;
    atomicAdd(d + 0, (double)sa); atomicAdd(d + 1, (double)sa2);
    atomicAdd(d + 2, (double)sx); atomicAdd(d + 3, (double)sy); atomicAdd(d + 4, (double)sz);
}

// ---------------- finalize: S, BN scale/shift, vol vector ----------------
__global__ void __launch_bounds__(192) finalize_kernel(
    const float* __restrict__ pos_W1, const float* __restrict__ pos_gamma,
    const float* __restrict__ pos_beta, const float* __restrict__ gC_W,
    const float* __restrict__ gC_b)
{
    int c = threadIdx.x;
    float Sv[3][3];
#pragma unroll
    for (int m = 0; m < 3; m++)
#pragma unroll
        for (int k = 0; k < 3; k++) {
            float s = 0.f;
            for (int j = 0; j < NS; j++) s += pos_W1[(long)m * 48 * DIM + (3 * j + k) * DIM + c];
            Sv[m][k] = s;
            g_S[(m * 3 + k) * DIM + c] = s;
        }
    const double T = (double)NPTS * NS;
    double Q0 = g_SM33[0], Q1 = g_SM33[1], Q2 = g_SM33[2], Q3 = g_SM33[3], Q4 = g_SM33[4], Q5 = g_SM33[5];
    double P0 = g_Sm3[0], P1 = g_Sm3[1], P2 = g_Sm3[2];
#pragma unroll
    for (int m = 0; m < 3; m++) {
        const double* d = g_ch + ((long)m * DIM + c) * 5;
        double SA = d[0], SA2 = d[1], SMx = d[2], SMy = d[3], SMz = d[4];
        double Sx = Sv[m][0], Sy = Sv[m][1], Sz = Sv[m][2];
        double mean = (16.0 * SA - (Sx * P0 + Sy * P1 + Sz * P2)) / T;
        double sq = 16.0 * SA2 - 2.0 * (Sx * SMx + Sy * SMy + Sz * SMz)
                  + Sx * Sx * Q0 + Sy * Sy * Q3 + Sz * Sz * Q5
                  + 2.0 * (Sx * Sy * Q1 + Sx * Sz * Q2 + Sy * Sz * Q4);
        double var = sq / T - mean * mean;
        float sc = pos_gamma[m * DIM + c] * rsqrtf((float)(var + 1e-5));
        g_bnscale[m * DIM + c] = sc;
        g_bnshift[m * DIM + c] = pos_beta[m * DIM + c] - (float)mean * sc;
    }
    float maxd = __int_as_float(g_maxbits);
    float vol = (float)(g_sumdist / T) / (maxd + 1e-8f);
    g_volvec[c] = vol * gC_W[c] + gC_b[c];
}

// ---------------- fused attention via mma.sync fp16 ----------------
#define SH_OFF    0          // 128 x 100 u32 = 51200
#define SQ_OFF    51200      // 6144
#define SK_OFF    57344      // 6144
#define SB2_OFF   63488      // 2304
#define SSC_OFF   65792      // 3072
#define SWT_OFF   68864      // 3072
#define SXYZ_OFF  71936      // 1536
#define SIDX_OFF  73472      // 512
#define SAH_OFF   73984      // 3 x 8 x 192 f32 = 18432
#define SSH_OFF   92416      // 3 x 3 x 192 f32 = 6912
#define ATT_SMEM  99328

__global__ void __launch_bounds__(512, 1) attn_mma_kernel(
    const int* __restrict__ knn, const float* __restrict__ pos_b2)
{
    extern __shared__ char smem[];
    const int t = threadIdx.x;
    const int wid = t >> 5, lane = t & 31;
    const int wm = wid & 3, wn = wid >> 2;
    const int g = lane >> 2, la3 = lane & 3;
    const int nb = blockIdx.x * 8;

    uint32_t* s_h  = (uint32_t*)(smem + SH_OFF);
    float* s_q   = (float*)(smem + SQ_OFF);
    float* s_k0  = (float*)(smem + SK_OFF);
    float* s_b2  = (float*)(smem + SB2_OFF);
    float* s_sc  = (float*)(smem + SSC_OFF);
    float* s_w   = (float*)(smem + SWT_OFF);
    float* s_xyz = (float*)(smem + SXYZ_OFF);
    int*   s_idx = (int*)(smem + SIDX_OFF);
    float* s_ahat = (float*)(smem + SAH_OFF);
    float* s_Sh   = (float*)(smem + SSH_OFF);
    const uint32_t shb = (uint32_t)__cvta_generic_to_shared(smem + SH_OFF);

    // ---- stage shared inputs ----
    for (int u = t; u < 128; u += 512) s_idx[u] = knn[(nb + (u >> 4)) * NS + (u & 15)];
    for (int u = t; u < 8 * 48; u += 512) s_xyz[u] = g_knnxyz[(long)nb * 48 + u];
    for (int u = t; u < 3 * DIM; u += 512) s_b2[u] = pos_b2[u];
    for (int u = t; u < 8 * DIM; u += 512) {
        int n = u / DIM, c = u % DIM;
        long r0 = (long)knn[(nb + n) * NS] * 576;
        s_q[u]  = g_qkv[r0 + c];
        s_k0[u] = g_qkv[r0 + 192 + c];
    }
    // ---- stage BN-folded A (all 3 mats) and S (all 3 mats) ----
    for (int u = t; u < 3 * 8 * DIM; u += 512) {
        int m = u / (8 * DIM);
        int rem = u - m * 8 * DIM;
        int node = rem / DIM, cg = rem % DIM;
        float a = g_A[((long)m * NPTS + nb + node) * DIM + cg];
        s_ahat[u] = a * g_bnscale[m * DIM + cg] + g_bnshift[m * DIM + cg];
    }
    for (int u = t; u < 3 * 3 * DIM; u += 512) {
        int m = u / (3 * DIM);
        int rem = u - m * 3 * DIM;
        s_Sh[u] = g_S[(m * 3 + rem / DIM) * DIM + (rem % DIM)] * g_bnscale[m * DIM + rem % DIM];
    }
    __syncthreads();

    // ---- base scores: q0.k_j + q0.b2[0] + k0.b2[1], per (n,h,j) ----
    for (int task = t; task < 768; task += 512) {
        int n = task / 96, h = (task / 16) % 6, j = task & 15;
        const float4* qv = (const float4*)(s_q + n * DIM + 32 * h);
        const float4* kv0 = (const float4*)(s_k0 + n * DIM + 32 * h);
        const float4* b0 = (const float4*)(s_b2 + 32 * h);
        const float4* b1 = (const float4*)(s_b2 + DIM + 32 * h);
        const float4* kj = (const float4*)(g_qkv + (long)s_idx[n * 16 + j] * 576 + 192 + 32 * h);
        float dot = 0.f;
#pragma unroll
        for (int u = 0; u < 8; u++) {
            float4 q4 = qv[u], k4 = kj[u], b04 = b0[u], b14 = b1[u], kk0 = kv0[u];
            dot += q4.x * (k4.x + b04.x) + q4.y * (k4.y + b04.y)
                 + q4.z * (k4.z + b04.z) + q4.w * (k4.w + b04.w);
            dot += kk0.x * b14.x + kk0.y * b14.y + kk0.z * b14.z + kk0.w * b14.w;
        }
        s_sc[(n * 6 + h) * 16 + j] = dot;
    }

    const int hb0 = (48 * wn) >> 5;
    const int grow = t >> 2;
    const int gn2 = grow >> 4, gj2 = grow & 15;

    for (int m = 0; m < 3; m++) {
        float acc[2][6][4];
#pragma unroll
        for (int a1 = 0; a1 < 2; a1++)
#pragma unroll
            for (int a2 = 0; a2 < 6; a2++)
#pragma unroll
                for (int a3 = 0; a3 < 4; a3++) acc[a1][a2][a3] = 0.f;

        __syncthreads();   // prev mma reads of s_h done (and base scores for m=0)
        // ---- generate h (fp16 pairs) from pre-staged operands ----
        {
            float xx = s_xyz[gn2 * 48 + gj2 * 3 + 0];
            float yy = s_xyz[gn2 * 48 + gj2 * 3 + 1];
            float zz = s_xyz[gn2 * 48 + gj2 * 3 + 2];
            const float* ah = s_ahat + m * 8 * DIM + gn2 * DIM;
            const float* Sh = s_Sh + m * 3 * DIM;
#pragma unroll
            for (int i = 0; i < 24; i++) {
                int cu = (t & 3) + 4 * i;
                int cg = 2 * cu;
                float2 a2 = *(const float2*)&ah[cg];
                float2 S0 = *(const float2*)&Sh[cg];
                float2 S1 = *(const float2*)&Sh[DIM + cg];
                float2 S2 = *(const float2*)&Sh[2 * DIM + cg];
                float h0 = a2.x - (xx * S0.x + yy * S1.x + zz * S2.x);
                float h1 = a2.y - (xx * S0.y + yy * S1.y + zz * S2.y);
                s_h[grow * 100 + cu] = pack_h2(fmaxf(h0, 0.f), fmaxf(h1, 0.f));
            }
        }
        __syncthreads();

        // ---- mma: K=192 in 12 k16-steps; A via ldmatrix, B frags via coalesced LDG ----
#pragma unroll
        for (int ks = 0; ks < 12; ks++) {
            const uint4* bq = (const uint4*)g_W2f + (((m * 4 + wn) * 12 + ks) * 3) * 32;
            uint4 u0 = bq[lane];
            uint4 u1 = bq[32 + lane];
            uint4 u2 = bq[64 + lane];
            uint32_t afr[2][4];
#pragma unroll
            for (int mt = 0; mt < 2; mt++) {
                uint32_t addr = shb + 4 * ((32 * wm + 16 * mt + (lane & 15)) * 100
                                           + ks * 8 + (lane >> 4) * 4);
                ldm_x4(afr[mt], addr);
            }
            mma_f16(acc[0][0], afr[0], u0.x, u0.y);
            mma_f16(acc[1][0], afr[1], u0.x, u0.y);
            mma_f16(acc[0][1], afr[0], u0.z, u0.w);
            mma_f16(acc[1][1], afr[1], u0.z, u0.w);
            mma_f16(acc[0][2], afr[0], u1.x, u1.y);
            mma_f16(acc[1][2], afr[1], u1.x, u1.y);
            mma_f16(acc[0][3], afr[0], u1.z, u1.w);
            mma_f16(acc[1][3], afr[1], u1.z, u1.w);
            mma_f16(acc[0][4], afr[0], u2.x, u2.y);
            mma_f16(acc[1][4], afr[1], u2.x, u2.y);
            mma_f16(acc[0][5], afr[0], u2.z, u2.w);
            mma_f16(acc[1][5], afr[1], u2.z, u2.w);
        }

        // ---- epilogue for mat m ----
        if (m < 2) {
            const float* base = (m == 0) ? s_q : s_k0;
            float part[8];
#pragma unroll
            for (int u = 0; u < 8; u++) part[u] = 0.f;
#pragma unroll
            for (int mt = 0; mt < 2; mt++) {
                const float* bp = base + (2 * wm + mt) * DIM;
#pragma unroll
                for (int nt = 0; nt < 6; nt++) {
                    int c0 = 48 * wn + 8 * nt + 2 * la3;
                    int bkt = ((48 * wn + 8 * nt) >> 5) - hb0;
                    float q0v = bp[c0], q1v = bp[c0 + 1];
                    part[mt * 4 + 0 * 2 + bkt] += acc[mt][nt][0] * q0v + acc[mt][nt][1] * q1v;
                    part[mt * 4 + 1 * 2 + bkt] += acc[mt][nt][2] * q0v + acc[mt][nt][3] * q1v;
                }
            }
#pragma unroll
            for (int u = 0; u < 8; u++) {
                part[u] += __shfl_xor_sync(0xffffffffu, part[u], 1);
                part[u] += __shfl_xor_sync(0xffffffffu, part[u], 2);
            }
            if (la3 == 0) {
                int j0 = g;
#pragma unroll
                for (int mt = 0; mt < 2; mt++)
#pragma unroll
                    for (int rb = 0; rb < 2; rb++)
#pragma unroll
                        for (int bkt = 0; bkt < 2; bkt++) {
                            int h = hb0 + bkt;
                            atomicAdd(&s_sc[((2 * wm + mt) * 6 + h) * 16 + j0 + 8 * rb],
                                      part[mt * 4 + rb * 2 + bkt]);
                        }
            }
            if (m == 1) {
                __syncthreads();
                if (t < 48) {
                    const float scale = 0.17677669529663687f;  // 32^-0.5
                    float* sc = s_sc + t * 16;
                    float mx = -1e30f;
#pragma unroll
                    for (int j = 0; j < 16; j++) mx = fmaxf(mx, sc[j]);
                    float se = 0.f;
                    float ev[16];
#pragma unroll
                    for (int j = 0; j < 16; j++) { ev[j] = expf((sc[j] - mx) * scale); se += ev[j]; }
                    float inv = 1.f / se;
#pragma unroll
                    for (int j = 0; j < 16; j++) s_w[t * 16 + j] = ev[j] * inv;
                }
                __syncthreads();
            }
        } else {
#pragma unroll
            for (int mt = 0; mt < 2; mt++) {
                int node = 2 * wm + mt;
                int j0 = g;
                long v0b = (long)s_idx[node * 16 + j0] * 576 + 384;
                long v1b = (long)s_idx[node * 16 + j0 + 8] * 576 + 384;
#pragma unroll
                for (int nt = 0; nt < 6; nt++) {
                    int c0 = 48 * wn + 8 * nt + 2 * la3;
                    int h = c0 >> 5;
                    float w0 = s_w[(node * 6 + h) * 16 + j0];
                    float w1 = s_w[(node * 6 + h) * 16 + j0 + 8];
                    float b20 = s_b2[2 * DIM + c0], b21 = s_b2[2 * DIM + c0 + 1];
                    float o0 = w0 * (acc[mt][nt][0] + g_qkv[v0b + c0] + b20)
                             + w1 * (acc[mt][nt][2] + g_qkv[v1b + c0] + b20);
                    float o1 = w0 * (acc[mt][nt][1] + g_qkv[v0b + c0 + 1] + b21)
                             + w1 * (acc[mt][nt][3] + g_qkv[v1b + c0 + 1] + b21);
#pragma unroll
                    for (int o = 4; o < 32; o <<= 1) {
                        o0 += __shfl_xor_sync(0xffffffffu, o0, o);
                        o1 += __shfl_xor_sync(0xffffffffu, o1, o);
                    }
                    if (g == 0) {
                        *(uint32_t*)(g_atth + (long)(nb + node) * DIM + c0) = pack_h2(o0, o1);
                    }
                }
            }
        }
    }
}

// ---------------- host launcher ----------------
extern "C" void kernel_launch(void* const* d_in, const int* in_sizes, int n_in,
                              void* d_out, int out_size)
{
    const float* p      = (const float*)d_in[0];
    const float* x      = (const float*)d_in[1];
    const int*   knn    = (const int*)d_in[2];
    const float* W_qkv  = (const float*)d_in[3];
    const float* W_proj = (const float*)d_in[4];
    const float* b_proj = (const float*)d_in[5];
    const float* prop_W = (const float*)d_in[6];
    const float* prop_b = (const float*)d_in[7];
    const float* gA_W   = (const float*)d_in[8];
    const float* gA_b   = (const float*)d_in[9];
    const float* gB_W   = (const float*)d_in[10];
    const float* gB_b   = (const float*)d_in[11];
    const float* gC_W   = (const float*)d_in[12];
    const float* gC_b   = (const float*)d_in[13];
    const float* pos_W1 = (const float*)d_in[14];
    const float* pos_b1 = (const float*)d_in[15];
    const float* pos_gamma = (const float*)d_in[16];
    const float* pos_beta  = (const float*)d_in[17];
    const float* pos_W2 = (const float*)d_in[18];
    const float* pos_b2 = (const float*)d_in[19];
    const float* kn     = (const float*)d_in[20];
    const float* de_W1  = (const float*)d_in[21];
    const float* de_b1  = (const float*)d_in[22];
    const float* de_W2  = (const float*)d_in[23];
    const float* de_b2  = (const float*)d_in[24];
    const float* kp_W   = (const float*)d_in[25];
    const float* kp_b   = (const float*)d_in[26];
    const float* fus_W  = (const float*)d_in[27];
    const float* fus_b  = (const float*)d_in[28];
    float* out = (float*)d_out;

    float *xpw, *qkv, *volvec, *bfq;
    __half *xh, *prefh, *atth;
    cudaGetSymbolAddress((void**)&xpw, g_xpw);
    cudaGetSymbolAddress((void**)&qkv, g_qkv);
    cudaGetSymbolAddress((void**)&volvec, g_volvec);
    cudaGetSymbolAddress((void**)&bfq, g_bfq);
    cudaGetSymbolAddress((void**)&xh, g_xh);
    cudaGetSymbolAddress((void**)&prefh, g_prefh);
    cudaGetSymbolAddress((void**)&atth, g_atth);

    cudaFuncSetAttribute(attn_mma_kernel, cudaFuncAttributeMaxDynamicSharedMemorySize, ATT_SMEM);

    prep_kernel<<<512, 256>>>(prop_W, W_proj, pos_W1, x);
    pre_kernel<<<1, 64>>>(de_W2, de_b2, kp_W, kp_b);
    w2f_kernel<<<864, 256>>>(pos_W2);
    wfq_kernel<<<dim3(9, 3), 256>>>(fus_W, W_qkv);
    bfq_kernel<<<3, 192>>>(fus_b, W_qkv);
    hgemm_kernel<<<dim3(3, 128), 256>>>(xh, OFF_PROP, nullptr, nullptr, xpw, 192);
    node1_kernel<<<NPTS, 192>>>(p, x, knn, prop_W, prop_b, gA_W, gA_b, gB_W, gB_b,
                                kn, de_W1, de_b1, de_W2, de_b2);
    agemm_kernel<<<dim3(9, 128), 256>>>(pos_b1);
    reduce_kernel<<<128, 256>>>();
    bnstats_kernel<<<dim3(NPTS / BNCHUNK, 3), 192>>>();
    finalize_kernel<<<1, 192>>>(pos_W1, pos_gamma, pos_beta, gC_W, gC_b);
    hgemm_kernel<<<dim3(9, 128), 256>>>(prefh, OFF_QKV, bfq, volvec, qkv, 576);
    attn_mma_kernel<<<NPTS / 8, 512, ATT_SMEM>>>(knn, pos_b2);
    hgemm_kernel<<<dim3(3, 128), 256>>>(atth, OFF_PROJ, b_proj, nullptr, out, 192);
}